// round 1
// baseline (speedup 1.0000x reference)
#include <cuda_runtime.h>
#include <math.h>

// Problem constants
#define B_ 2
#define T_ 512
#define P_ 8
#define D_ 1024
#define NH 16
#define NKV 4
#define HD 64
#define NTOK 8192   // B*P*T

// Scratch (device globals: allocation-free rule)
__device__ float g_q[NTOK * 1024];
__device__ float g_k[NTOK * 256];
__device__ float g_v[NTOK * 256];
__device__ float g_o[NTOK * 1024];

// logical row r in (b,p,t) order  ->  storage row in (b,t,p) order
__device__ __forceinline__ int remap_bpt(int r) {
    int b = r >> 12;          // P_*T_ = 4096
    int p = (r >> 9) & 7;
    int t = r & 511;
    return (b << 12) + (t << 3) + p;
}

// ---------------------------------------------------------------------------
// SGEMM: C[M x N] = A[M x 1024] * Bw[1024 x N]
// 128x128 block tile, BK=16, 256 threads, 8x8 per-thread microtile.
// REMAP_A: gather A rows through (b,t,p) transpose (hidden_states input)
// REMAP_C: scatter C rows through (b,t,p) transpose (final output)
// ---------------------------------------------------------------------------
template<int REMAP_A, int REMAP_C>
__global__ void __launch_bounds__(256) sgemm_k(const float* __restrict__ A,
                                               const float* __restrict__ Bw,
                                               float* __restrict__ C, int N) {
    __shared__ float As[16][128];
    __shared__ float Bs[16][128];
    const int K = 1024;
    int tid = threadIdx.x;
    int tx = tid & 15, ty = tid >> 4;
    int bm = blockIdx.y, bn = blockIdx.x;

    int ar = tid >> 2;            // 0..63
    int ak = (tid & 3) << 2;      // 0,4,8,12
    int arow0 = bm * 128 + ar;
    int arow1 = arow0 + 64;
    if (REMAP_A) { arow0 = remap_bpt(arow0); arow1 = remap_bpt(arow1); }
    const float* Ap0 = A + arow0 * K + ak;
    const float* Ap1 = A + arow1 * K + ak;

    int bk = tid >> 5;            // 0..7
    int bc = (tid & 31) << 2;     // 0..124
    const float* Bp = Bw + bk * N + bn * 128 + bc;

    float acc[8][8];
    #pragma unroll
    for (int i = 0; i < 8; i++)
        #pragma unroll
        for (int j = 0; j < 8; j++) acc[i][j] = 0.f;

    for (int k0 = 0; k0 < K; k0 += 16) {
        float4 a0 = *(const float4*)(Ap0 + k0);
        float4 a1 = *(const float4*)(Ap1 + k0);
        float4 b0 = *(const float4*)(Bp + k0 * N);
        float4 b1 = *(const float4*)(Bp + (k0 + 8) * N);
        __syncthreads();
        As[ak + 0][ar] = a0.x; As[ak + 1][ar] = a0.y;
        As[ak + 2][ar] = a0.z; As[ak + 3][ar] = a0.w;
        As[ak + 0][ar + 64] = a1.x; As[ak + 1][ar + 64] = a1.y;
        As[ak + 2][ar + 64] = a1.z; As[ak + 3][ar + 64] = a1.w;
        *(float4*)&Bs[bk][bc]     = b0;
        *(float4*)&Bs[bk + 8][bc] = b1;
        __syncthreads();
        #pragma unroll
        for (int kk = 0; kk < 16; kk++) {
            float rm[8], rn[8];
            *(float4*)&rm[0] = *(float4*)&As[kk][ty * 8];
            *(float4*)&rm[4] = *(float4*)&As[kk][ty * 8 + 4];
            *(float4*)&rn[0] = *(float4*)&Bs[kk][tx * 8];
            *(float4*)&rn[4] = *(float4*)&Bs[kk][tx * 8 + 4];
            #pragma unroll
            for (int i = 0; i < 8; i++)
                #pragma unroll
                for (int j = 0; j < 8; j++)
                    acc[i][j] = fmaf(rm[i], rn[j], acc[i][j]);
        }
    }

    #pragma unroll
    for (int i = 0; i < 8; i++) {
        int row = bm * 128 + ty * 8 + i;
        if (REMAP_C) row = remap_bpt(row);
        float* Cp = C + row * N + bn * 128 + tx * 8;
        *(float4*)Cp       = make_float4(acc[i][0], acc[i][1], acc[i][2], acc[i][3]);
        *(float4*)(Cp + 4) = make_float4(acc[i][4], acc[i][5], acc[i][6], acc[i][7]);
    }
}

// ---------------------------------------------------------------------------
// RoPE in place on g_q (16 heads) and g_k (4 heads).
// One thread per (token, head, i<32) rotation pair.
// ---------------------------------------------------------------------------
__global__ void rope_k() {
    int idx = blockIdx.x * blockDim.x + threadIdx.x;
    const int QP = NTOK * NH * 32;   // 4194304
    const int KP = NTOK * NKV * 32;  // 1048576
    if (idx >= QP + KP) return;
    float* base;
    int i, tok;
    if (idx < QP) {
        i = idx & 31;
        int r = idx >> 5;
        int h = r & 15;
        tok = r >> 4;
        base = g_q + tok * 1024 + h * 64;
    } else {
        int j = idx - QP;
        i = j & 31;
        int r = j >> 5;
        int h = r & 3;
        tok = r >> 2;
        base = g_k + tok * 256 + h * 64;
    }
    int t = tok & 511;  // tok = (b*P+p)*T + t
    // inv_freq = 10000^{-i/32} = exp(-i * ln(10000)/32), accurate path
    float invf = expf(-(float)i * 0.28782313662425574f);
    float ang = (float)t * invf;
    float s, c;
    sincosf(ang, &s, &c);
    float x1 = base[i], x2 = base[i + 32];
    base[i]      = x1 * c - x2 * s;
    base[i + 32] = x1 * s + x2 * c;
}

// ---------------------------------------------------------------------------
// Flash attention. Block = one (b,p,h) x 64-row q tile. 256 threads.
// Thread (row = tid/4, col = tid%4): owns q-row `row`, output dims [16c,16c+16),
// and scores for j = 4*jj + col (jj in [0,16)). smem row stride 68 (bank pad).
// P tile reuses the K buffer after phase A.
// ---------------------------------------------------------------------------
#define SROW 68
__global__ void __launch_bounds__(256) attn_k() {
    extern __shared__ float sm[];
    float* Qs  = sm;                // 64 x SROW
    float* KPs = sm + 64 * SROW;    // K tile, then P tile
    float* Vs  = sm + 2 * 64 * SROW;

    int tid = threadIdx.x;
    int row = tid >> 2;
    int col = tid & 3;

    int bph = blockIdx.y;
    int h   = bph & 15;
    int bp  = bph >> 4;
    int hkv = h >> 2;               // repeat factor 4
    int qt0 = blockIdx.x << 6;

    const float* qbase = g_q + (bp * 512) * 1024 + h * 64;
    const float* kbase = g_k + (bp * 512) * 256 + hkv * 64;
    const float* vbase = g_v + (bp * 512) * 256 + hkv * 64;

    // Q tile: 64 rows x 64 cols
    for (int idx = tid; idx < 1024; idx += 256) {
        int r  = idx >> 4;
        int c4 = (idx & 15) << 2;
        *(float4*)&Qs[r * SROW + c4] = *(const float4*)(qbase + (qt0 + r) * 1024 + c4);
    }

    float s[16], o[16];
    #pragma unroll
    for (int i = 0; i < 16; i++) o[i] = 0.f;
    float m = -INFINITY, l = 0.f;
    const float sc = 0.125f;  // 1/sqrt(64)

    for (int kt0 = 0; kt0 < 512; kt0 += 64) {
        __syncthreads();  // previous phase C done reading KPs/Vs (also covers Q load)
        for (int idx = tid; idx < 1024; idx += 256) {
            int r  = idx >> 4;
            int c4 = (idx & 15) << 2;
            *(float4*)&KPs[r * SROW + c4] = *(const float4*)(kbase + (kt0 + r) * 256 + c4);
            *(float4*)&Vs[r * SROW + c4]  = *(const float4*)(vbase + (kt0 + r) * 256 + c4);
        }
        __syncthreads();

        // Phase A: s[jj] = q[row] . k[4*jj+col]
        #pragma unroll
        for (int jj = 0; jj < 16; jj++) s[jj] = 0.f;
        #pragma unroll
        for (int d4 = 0; d4 < 64; d4 += 4) {
            float4 q4 = *(float4*)&Qs[row * SROW + d4];
            #pragma unroll
            for (int jj = 0; jj < 16; jj++) {
                float4 k4 = *(float4*)&KPs[(4 * jj + col) * SROW + d4];
                s[jj] = fmaf(q4.x, k4.x, s[jj]);
                s[jj] = fmaf(q4.y, k4.y, s[jj]);
                s[jj] = fmaf(q4.z, k4.z, s[jj]);
                s[jj] = fmaf(q4.w, k4.w, s[jj]);
            }
        }

        // Phase B: online softmax update
        float tmax = s[0];
        #pragma unroll
        for (int jj = 1; jj < 16; jj++) tmax = fmaxf(tmax, s[jj]);
        tmax = fmaxf(tmax, __shfl_xor_sync(0xffffffffu, tmax, 1));
        tmax = fmaxf(tmax, __shfl_xor_sync(0xffffffffu, tmax, 2));
        float mnew  = fmaxf(m, sc * tmax);
        float alpha = __expf(m - mnew);

        __syncthreads();  // all warps done reading KPs as K before P overwrite
        float psum = 0.f;
        #pragma unroll
        for (int jj = 0; jj < 16; jj++) {
            float p = __expf(fmaf(sc, s[jj], -mnew));
            KPs[row * SROW + 4 * jj + col] = p;
            psum += p;
        }
        psum += __shfl_xor_sync(0xffffffffu, psum, 1);
        psum += __shfl_xor_sync(0xffffffffu, psum, 2);
        l = l * alpha + psum;
        m = mnew;
        #pragma unroll
        for (int i = 0; i < 16; i++) o[i] *= alpha;
        __syncthreads();

        // Phase C: o += P @ V
        #pragma unroll 8
        for (int j = 0; j < 64; j++) {
            float p = KPs[row * SROW + j];
            const float* vp = &Vs[j * SROW + col * 16];
            float4 v0 = *(const float4*)(vp);
            float4 v1 = *(const float4*)(vp + 4);
            float4 v2 = *(const float4*)(vp + 8);
            float4 v3 = *(const float4*)(vp + 12);
            o[0]  = fmaf(p, v0.x, o[0]);  o[1]  = fmaf(p, v0.y, o[1]);
            o[2]  = fmaf(p, v0.z, o[2]);  o[3]  = fmaf(p, v0.w, o[3]);
            o[4]  = fmaf(p, v1.x, o[4]);  o[5]  = fmaf(p, v1.y, o[5]);
            o[6]  = fmaf(p, v1.z, o[6]);  o[7]  = fmaf(p, v1.w, o[7]);
            o[8]  = fmaf(p, v2.x, o[8]);  o[9]  = fmaf(p, v2.y, o[9]);
            o[10] = fmaf(p, v2.z, o[10]); o[11] = fmaf(p, v2.w, o[11]);
            o[12] = fmaf(p, v3.x, o[12]); o[13] = fmaf(p, v3.y, o[13]);
            o[14] = fmaf(p, v3.z, o[14]); o[15] = fmaf(p, v3.w, o[15]);
        }
    }

    float inv = 1.f / l;
    float* op = g_o + (bp * 512 + qt0 + row) * 1024 + h * 64 + col * 16;
    *(float4*)(op)      = make_float4(o[0]*inv,  o[1]*inv,  o[2]*inv,  o[3]*inv);
    *(float4*)(op + 4)  = make_float4(o[4]*inv,  o[5]*inv,  o[6]*inv,  o[7]*inv);
    *(float4*)(op + 8)  = make_float4(o[8]*inv,  o[9]*inv,  o[10]*inv, o[11]*inv);
    *(float4*)(op + 12) = make_float4(o[12]*inv, o[13]*inv, o[14]*inv, o[15]*inv);
}

// ---------------------------------------------------------------------------
extern "C" void kernel_launch(void* const* d_in, const int* in_sizes, int n_in,
                              void* d_out, int out_size) {
    (void)in_sizes; (void)n_in; (void)out_size;
    const float* hidden = (const float*)d_in[0];
    const float* Wq = (const float*)d_in[1];
    const float* Wk = (const float*)d_in[2];
    const float* Wv = (const float*)d_in[3];
    const float* Wo = (const float*)d_in[4];
    float* out = (float*)d_out;

    float *pq, *pk, *pv, *po;
    cudaGetSymbolAddress((void**)&pq, g_q);
    cudaGetSymbolAddress((void**)&pk, g_k);
    cudaGetSymbolAddress((void**)&pv, g_v);
    cudaGetSymbolAddress((void**)&po, g_o);

    // QKV projections (A rows gathered through the (b,t,p)->(b,p,t) transpose)
    sgemm_k<1, 0><<<dim3(8, 64), 256>>>(hidden, Wq, pq, 1024);
    sgemm_k<1, 0><<<dim3(2, 64), 256>>>(hidden, Wk, pk, 256);
    sgemm_k<1, 0><<<dim3(2, 64), 256>>>(hidden, Wv, pv, 256);

    // RoPE on q and k in place
    rope_k<<<(NTOK * NH * 32 + NTOK * NKV * 32) / 256, 256>>>();

    // Flash attention: 8 q-tiles x 256 (b,p,h) instances
    const int attn_smem = 3 * 64 * SROW * 4;  // 52224 B
    cudaFuncSetAttribute(attn_k, cudaFuncAttributeMaxDynamicSharedMemorySize, attn_smem);
    attn_k<<<dim3(8, 256), 256, attn_smem>>>();

    // Output projection, scattering rows back to (b,t,p) order
    sgemm_k<0, 1><<<dim3(8, 64), 256>>>(po, Wo, out, 1024);
}

// round 2
// speedup vs baseline: 1.0002x; 1.0002x over previous
#include <cuda_runtime.h>
#include <math.h>

// Problem constants
#define B_ 2
#define T_ 512
#define P_ 8
#define D_ 1024
#define NH 16
#define NKV 4
#define HD 64
#define NTOK 8192   // B*P*T

// Scratch (device globals: allocation-free rule)
__device__ float g_q[NTOK * 1024];
__device__ float g_k[NTOK * 256];
__device__ float g_v[NTOK * 256];
__device__ float g_o[NTOK * 1024];

// logical row r in (b,p,t) order  ->  storage row in (b,t,p) order
__device__ __forceinline__ int remap_bpt(int r) {
    int b = r >> 12;          // P_*T_ = 4096
    int p = (r >> 9) & 7;
    int t = r & 511;
    return (b << 12) + (t << 3) + p;
}

// ---------------------------------------------------------------------------
// SGEMM: C[M x N] = A[M x 1024] * Bw[1024 x N]
// 128x128 block tile, BK=16, 256 threads, 8x8 per-thread microtile.
// REMAP_A: gather A rows through (b,t,p) transpose (hidden_states input)
// REMAP_C: scatter C rows through (b,t,p) transpose (final output)
// ---------------------------------------------------------------------------
template<int REMAP_A, int REMAP_C>
__global__ void __launch_bounds__(256) sgemm_k(const float* __restrict__ A,
                                               const float* __restrict__ Bw,
                                               float* __restrict__ C, int N) {
    __shared__ float As[16][128];
    __shared__ float Bs[16][128];
    const int K = 1024;
    int tid = threadIdx.x;
    int tx = tid & 15, ty = tid >> 4;
    int bm = blockIdx.y, bn = blockIdx.x;

    int ar = tid >> 2;            // 0..63
    int ak = (tid & 3) << 2;      // 0,4,8,12
    int arow0 = bm * 128 + ar;
    int arow1 = arow0 + 64;
    if (REMAP_A) { arow0 = remap_bpt(arow0); arow1 = remap_bpt(arow1); }
    const float* Ap0 = A + arow0 * K + ak;
    const float* Ap1 = A + arow1 * K + ak;

    int bk = tid >> 5;            // 0..7
    int bc = (tid & 31) << 2;     // 0..124
    const float* Bp = Bw + bk * N + bn * 128 + bc;

    float acc[8][8];
    #pragma unroll
    for (int i = 0; i < 8; i++)
        #pragma unroll
        for (int j = 0; j < 8; j++) acc[i][j] = 0.f;

    for (int k0 = 0; k0 < K; k0 += 16) {
        float4 a0 = *(const float4*)(Ap0 + k0);
        float4 a1 = *(const float4*)(Ap1 + k0);
        float4 b0 = *(const float4*)(Bp + k0 * N);
        float4 b1 = *(const float4*)(Bp + (k0 + 8) * N);
        __syncthreads();
        As[ak + 0][ar] = a0.x; As[ak + 1][ar] = a0.y;
        As[ak + 2][ar] = a0.z; As[ak + 3][ar] = a0.w;
        As[ak + 0][ar + 64] = a1.x; As[ak + 1][ar + 64] = a1.y;
        As[ak + 2][ar + 64] = a1.z; As[ak + 3][ar + 64] = a1.w;
        *(float4*)&Bs[bk][bc]     = b0;
        *(float4*)&Bs[bk + 8][bc] = b1;
        __syncthreads();
        #pragma unroll
        for (int kk = 0; kk < 16; kk++) {
            float rm[8], rn[8];
            *(float4*)&rm[0] = *(float4*)&As[kk][ty * 8];
            *(float4*)&rm[4] = *(float4*)&As[kk][ty * 8 + 4];
            *(float4*)&rn[0] = *(float4*)&Bs[kk][tx * 8];
            *(float4*)&rn[4] = *(float4*)&Bs[kk][tx * 8 + 4];
            #pragma unroll
            for (int i = 0; i < 8; i++)
                #pragma unroll
                for (int j = 0; j < 8; j++)
                    acc[i][j] = fmaf(rm[i], rn[j], acc[i][j]);
        }
    }

    #pragma unroll
    for (int i = 0; i < 8; i++) {
        int row = bm * 128 + ty * 8 + i;
        if (REMAP_C) row = remap_bpt(row);
        float* Cp = C + row * N + bn * 128 + tx * 8;
        *(float4*)Cp       = make_float4(acc[i][0], acc[i][1], acc[i][2], acc[i][3]);
        *(float4*)(Cp + 4) = make_float4(acc[i][4], acc[i][5], acc[i][6], acc[i][7]);
    }
}

// ---------------------------------------------------------------------------
// RoPE in place on g_q (16 heads) and g_k (4 heads).
// One thread per (token, head, i<32) rotation pair.
// ---------------------------------------------------------------------------
__global__ void rope_k() {
    int idx = blockIdx.x * blockDim.x + threadIdx.x;
    const int QP = NTOK * NH * 32;   // 4194304
    const int KP = NTOK * NKV * 32;  // 1048576
    if (idx >= QP + KP) return;
    float* base;
    int i, tok;
    if (idx < QP) {
        i = idx & 31;
        int r = idx >> 5;
        int h = r & 15;
        tok = r >> 4;
        base = g_q + tok * 1024 + h * 64;
    } else {
        int j = idx - QP;
        i = j & 31;
        int r = j >> 5;
        int h = r & 3;
        tok = r >> 2;
        base = g_k + tok * 256 + h * 64;
    }
    int t = tok & 511;  // tok = (b*P+p)*T + t
    // inv_freq = 10000^{-i/32} = exp(-i * ln(10000)/32), accurate path
    float invf = expf(-(float)i * 0.28782313662425574f);
    float ang = (float)t * invf;
    float s, c;
    sincosf(ang, &s, &c);
    float x1 = base[i], x2 = base[i + 32];
    base[i]      = x1 * c - x2 * s;
    base[i + 32] = x1 * s + x2 * c;
}

// ---------------------------------------------------------------------------
// Flash attention. Block = one (b,p,h) x 64-row q tile. 256 threads.
// Thread (row = tid/4, col = tid%4): owns q-row `row`, output dims [16c,16c+16),
// and scores for j = 4*jj + col (jj in [0,16)). smem row stride 68 (bank pad).
// P tile reuses the K buffer after phase A.
// ---------------------------------------------------------------------------
#define SROW 68
__global__ void __launch_bounds__(256) attn_k() {
    extern __shared__ float sm[];
    float* Qs  = sm;                // 64 x SROW
    float* KPs = sm + 64 * SROW;    // K tile, then P tile
    float* Vs  = sm + 2 * 64 * SROW;

    int tid = threadIdx.x;
    int row = tid >> 2;
    int col = tid & 3;

    int bph = blockIdx.y;
    int h   = bph & 15;
    int bp  = bph >> 4;
    int hkv = h >> 2;               // repeat factor 4
    int qt0 = blockIdx.x << 6;

    const float* qbase = g_q + (bp * 512) * 1024 + h * 64;
    const float* kbase = g_k + (bp * 512) * 256 + hkv * 64;
    const float* vbase = g_v + (bp * 512) * 256 + hkv * 64;

    // Q tile: 64 rows x 64 cols
    for (int idx = tid; idx < 1024; idx += 256) {
        int r  = idx >> 4;
        int c4 = (idx & 15) << 2;
        *(float4*)&Qs[r * SROW + c4] = *(const float4*)(qbase + (qt0 + r) * 1024 + c4);
    }

    float s[16], o[16];
    #pragma unroll
    for (int i = 0; i < 16; i++) o[i] = 0.f;
    float m = -INFINITY, l = 0.f;
    const float sc = 0.125f;  // 1/sqrt(64)

    for (int kt0 = 0; kt0 < 512; kt0 += 64) {
        __syncthreads();  // previous phase C done reading KPs/Vs (also covers Q load)
        for (int idx = tid; idx < 1024; idx += 256) {
            int r  = idx >> 4;
            int c4 = (idx & 15) << 2;
            *(float4*)&KPs[r * SROW + c4] = *(const float4*)(kbase + (kt0 + r) * 256 + c4);
            *(float4*)&Vs[r * SROW + c4]  = *(const float4*)(vbase + (kt0 + r) * 256 + c4);
        }
        __syncthreads();

        // Phase A: s[jj] = q[row] . k[4*jj+col]
        #pragma unroll
        for (int jj = 0; jj < 16; jj++) s[jj] = 0.f;
        #pragma unroll
        for (int d4 = 0; d4 < 64; d4 += 4) {
            float4 q4 = *(float4*)&Qs[row * SROW + d4];
            #pragma unroll
            for (int jj = 0; jj < 16; jj++) {
                float4 k4 = *(float4*)&KPs[(4 * jj + col) * SROW + d4];
                s[jj] = fmaf(q4.x, k4.x, s[jj]);
                s[jj] = fmaf(q4.y, k4.y, s[jj]);
                s[jj] = fmaf(q4.z, k4.z, s[jj]);
                s[jj] = fmaf(q4.w, k4.w, s[jj]);
            }
        }

        // Phase B: online softmax update
        float tmax = s[0];
        #pragma unroll
        for (int jj = 1; jj < 16; jj++) tmax = fmaxf(tmax, s[jj]);
        tmax = fmaxf(tmax, __shfl_xor_sync(0xffffffffu, tmax, 1));
        tmax = fmaxf(tmax, __shfl_xor_sync(0xffffffffu, tmax, 2));
        float mnew  = fmaxf(m, sc * tmax);
        float alpha = __expf(m - mnew);

        __syncthreads();  // all warps done reading KPs as K before P overwrite
        float psum = 0.f;
        #pragma unroll
        for (int jj = 0; jj < 16; jj++) {
            float p = __expf(fmaf(sc, s[jj], -mnew));
            KPs[row * SROW + 4 * jj + col] = p;
            psum += p;
        }
        psum += __shfl_xor_sync(0xffffffffu, psum, 1);
        psum += __shfl_xor_sync(0xffffffffu, psum, 2);
        l = l * alpha + psum;
        m = mnew;
        #pragma unroll
        for (int i = 0; i < 16; i++) o[i] *= alpha;
        __syncthreads();

        // Phase C: o += P @ V
        #pragma unroll 8
        for (int j = 0; j < 64; j++) {
            float p = KPs[row * SROW + j];
            const float* vp = &Vs[j * SROW + col * 16];
            float4 v0 = *(const float4*)(vp);
            float4 v1 = *(const float4*)(vp + 4);
            float4 v2 = *(const float4*)(vp + 8);
            float4 v3 = *(const float4*)(vp + 12);
            o[0]  = fmaf(p, v0.x, o[0]);  o[1]  = fmaf(p, v0.y, o[1]);
            o[2]  = fmaf(p, v0.z, o[2]);  o[3]  = fmaf(p, v0.w, o[3]);
            o[4]  = fmaf(p, v1.x, o[4]);  o[5]  = fmaf(p, v1.y, o[5]);
            o[6]  = fmaf(p, v1.z, o[6]);  o[7]  = fmaf(p, v1.w, o[7]);
            o[8]  = fmaf(p, v2.x, o[8]);  o[9]  = fmaf(p, v2.y, o[9]);
            o[10] = fmaf(p, v2.z, o[10]); o[11] = fmaf(p, v2.w, o[11]);
            o[12] = fmaf(p, v3.x, o[12]); o[13] = fmaf(p, v3.y, o[13]);
            o[14] = fmaf(p, v3.z, o[14]); o[15] = fmaf(p, v3.w, o[15]);
        }
    }

    float inv = 1.f / l;
    float* op = g_o + (bp * 512 + qt0 + row) * 1024 + h * 64 + col * 16;
    *(float4*)(op)      = make_float4(o[0]*inv,  o[1]*inv,  o[2]*inv,  o[3]*inv);
    *(float4*)(op + 4)  = make_float4(o[4]*inv,  o[5]*inv,  o[6]*inv,  o[7]*inv);
    *(float4*)(op + 8)  = make_float4(o[8]*inv,  o[9]*inv,  o[10]*inv, o[11]*inv);
    *(float4*)(op + 12) = make_float4(o[12]*inv, o[13]*inv, o[14]*inv, o[15]*inv);
}

// ---------------------------------------------------------------------------
extern "C" void kernel_launch(void* const* d_in, const int* in_sizes, int n_in,
                              void* d_out, int out_size) {
    (void)in_sizes; (void)n_in; (void)out_size;
    const float* hidden = (const float*)d_in[0];
    const float* Wq = (const float*)d_in[1];
    const float* Wk = (const float*)d_in[2];
    const float* Wv = (const float*)d_in[3];
    const float* Wo = (const float*)d_in[4];
    float* out = (float*)d_out;

    float *pq, *pk, *pv, *po;
    cudaGetSymbolAddress((void**)&pq, g_q);
    cudaGetSymbolAddress((void**)&pk, g_k);
    cudaGetSymbolAddress((void**)&pv, g_v);
    cudaGetSymbolAddress((void**)&po, g_o);

    // QKV projections (A rows gathered through the (b,t,p)->(b,p,t) transpose)
    sgemm_k<1, 0><<<dim3(8, 64), 256>>>(hidden, Wq, pq, 1024);
    sgemm_k<1, 0><<<dim3(2, 64), 256>>>(hidden, Wk, pk, 256);
    sgemm_k<1, 0><<<dim3(2, 64), 256>>>(hidden, Wv, pv, 256);

    // RoPE on q and k in place
    rope_k<<<(NTOK * NH * 32 + NTOK * NKV * 32) / 256, 256>>>();

    // Flash attention: 8 q-tiles x 256 (b,p,h) instances
    const int attn_smem = 3 * 64 * SROW * 4;  // 52224 B
    cudaFuncSetAttribute(attn_k, cudaFuncAttributeMaxDynamicSharedMemorySize, attn_smem);
    attn_k<<<dim3(8, 256), 256, attn_smem>>>();

    // Output projection, scattering rows back to (b,t,p) order
    sgemm_k<0, 1><<<dim3(8, 64), 256>>>(po, Wo, out, 1024);
}

// round 4
// speedup vs baseline: 1.3014x; 1.3012x over previous
#include <cuda_runtime.h>
#include <cuda_bf16.h>
#include <cstdint>
#include <math.h>

#define NTOK 8192

__device__ float g_q[NTOK * 1024];
__device__ float g_k[NTOK * 256];
__device__ float g_v[NTOK * 256];
__device__ float g_o[NTOK * 1024];
__device__ float g_wt[1024 * 1024];

__device__ __forceinline__ int remap_bpt(int r) {
    int b = r >> 12, p = (r >> 9) & 7, t = r & 511;
    return (b << 12) + (t << 3) + p;
}

__device__ __forceinline__ uint32_t smem_u32(const void* p) {
    uint32_t a;
    asm("{ .reg .u64 t; cvta.to.shared.u64 t, %1; cvt.u32.u64 %0, t; }" : "=r"(a) : "l"(p));
    return a;
}

#define LDSM4(r0, r1, r2, r3, a) \
    asm volatile("ldmatrix.sync.aligned.m8n8.x4.shared.b16 {%0,%1,%2,%3}, [%4];" \
        : "=r"(r0), "=r"(r1), "=r"(r2), "=r"(r3) : "r"(a))

#define MMA16816(c, a0, a1, a2, a3, b0, b1) \
    asm volatile("mma.sync.aligned.m16n8k16.row.col.f32.bf16.bf16.f32 " \
        "{%0,%1,%2,%3},{%4,%5,%6,%7},{%8,%9},{%0,%1,%2,%3};" \
        : "+f"((c)[0]), "+f"((c)[1]), "+f"((c)[2]), "+f"((c)[3]) \
        : "r"(a0), "r"(a1), "r"(a2), "r"(a3), "r"(b0), "r"(b1))

__device__ __forceinline__ uint32_t pk_bf2(float x, float y) {
    __nv_bfloat162 h = __floats2bfloat162_rn(x, y);
    return *(uint32_t*)&h;
}

// ---------------- weight transpose: in[1024 x N] -> out[N x 1024] ----------------
__global__ void transpose_k(const float* __restrict__ in, float* __restrict__ out, int N) {
    __shared__ float t[32][33];
    int n0 = blockIdx.x * 32, k0 = blockIdx.y * 32, x = threadIdx.x;
    for (int j = threadIdx.y; j < 32; j += 8)
        t[j][x] = in[(size_t)(k0 + j) * N + n0 + x];
    __syncthreads();
    for (int j = threadIdx.y; j < 32; j += 8)
        out[(size_t)(n0 + j) * 1024 + k0 + x] = t[x][j];
}

// ---------------------------------------------------------------------------
// bf16 3-term-split GEMM via mma.sync (legacy HMMA path; tcgen05 not emittable
// through this harness' compute_103 PTX target).
// C[M x Ntot] = A[M x 1024] @ W, W pre-transposed as Bt[Ntot x 1024] (K-major).
// Tile 128x128, BK=32, 8 warps (2m x 4n), warp tile 64x32, m16n8k16 frags.
// acc += Ah*Bh + Ah*Bl + Al*Bh   (AlBl dropped: ~2^-18 relative -> rel_err ~4e-6)
// ---------------------------------------------------------------------------
#define ASTR 40   // bf16 stride per row (80 B) -> conflict-free ldmatrix
template<int RA, int RC>
__global__ void __launch_bounds__(256) bfgemm_k(const float* __restrict__ A,
                                                const float* __restrict__ Bt,
                                                float* __restrict__ C, int Ntot) {
    __shared__ __align__(16) __nv_bfloat16 Ah[128][ASTR], Al[128][ASTR];
    __shared__ __align__(16) __nv_bfloat16 Bh[128][ASTR], Bl[128][ASTR];

    int tid = threadIdx.x, wid = tid >> 5, lane = tid & 31;
    int bm = blockIdx.y, bn = blockIdx.x;
    int wm = (wid >> 2) * 64;    // warp m origin (2 warps in m)
    int wn = (wid & 3) * 32;     // warp n origin (4 warps in n)

    float acc[4][4][4];
    #pragma unroll
    for (int i = 0; i < 4; i++)
        #pragma unroll
        for (int j = 0; j < 4; j++)
            #pragma unroll
            for (int q = 0; q < 4; q++) acc[i][j][q] = 0.f;

    // Precompute global row indices for the conversion loop (4 passes)
    int cr[4], ca[4];
    #pragma unroll
    for (int p = 0; p < 4; p++) {
        int id = tid + p * 256;
        cr[p] = id >> 3;                 // tile row 0..127
        int am = bm * 128 + cr[p];
        if (RA) am = remap_bpt(am);
        ca[p] = am;
    }
    int kq = (tid & 7) * 4;              // k offset within BK (0,4,..,28)

    for (int k0 = 0; k0 < 1024; k0 += 32) {
        __syncthreads();
        #pragma unroll
        for (int p = 0; p < 4; p++) {
            int r = cr[p];
            float4 av = *(const float4*)(A + (size_t)ca[p] * 1024 + k0 + kq);
            float4 bv = *(const float4*)(Bt + (size_t)(bn * 128 + r) * 1024 + k0 + kq);

            float ahx = __bfloat162float(__float2bfloat16_rn(av.x));
            float ahy = __bfloat162float(__float2bfloat16_rn(av.y));
            float ahz = __bfloat162float(__float2bfloat16_rn(av.z));
            float ahw = __bfloat162float(__float2bfloat16_rn(av.w));
            float bhx = __bfloat162float(__float2bfloat16_rn(bv.x));
            float bhy = __bfloat162float(__float2bfloat16_rn(bv.y));
            float bhz = __bfloat162float(__float2bfloat16_rn(bv.z));
            float bhw = __bfloat162float(__float2bfloat16_rn(bv.w));

            *(uint2*)&Ah[r][kq] = make_uint2(pk_bf2(ahx, ahy), pk_bf2(ahz, ahw));
            *(uint2*)&Al[r][kq] = make_uint2(pk_bf2(av.x - ahx, av.y - ahy),
                                             pk_bf2(av.z - ahz, av.w - ahw));
            *(uint2*)&Bh[r][kq] = make_uint2(pk_bf2(bhx, bhy), pk_bf2(bhz, bhw));
            *(uint2*)&Bl[r][kq] = make_uint2(pk_bf2(bv.x - bhx, bv.y - bhy),
                                             pk_bf2(bv.z - bhz, bv.w - bhw));
        }
        __syncthreads();

        #pragma unroll
        for (int ks = 0; ks < 2; ks++) {
            int koff = ks * 16 + ((lane >> 4) << 3);
            int arow = wm + (lane & 15);

            uint32_t ah[4][4], al[4][4];
            #pragma unroll
            for (int mf = 0; mf < 4; mf++) {
                uint32_t addr_h = smem_u32(&Ah[arow + mf * 16][koff]);
                uint32_t addr_l = smem_u32(&Al[arow + mf * 16][koff]);
                LDSM4(ah[mf][0], ah[mf][1], ah[mf][2], ah[mf][3], addr_h);
                LDSM4(al[mf][0], al[mf][1], al[mf][2], al[mf][3], addr_l);
            }

            // B: x4 covers two n-frags (16 rows) per load
            uint32_t bh[4][2], bl[4][2];
            #pragma unroll
            for (int jp = 0; jp < 4; jp += 2) {
                int brow = wn + jp * 8 + (lane & 15);
                uint32_t r0, r1, r2, r3;
                LDSM4(r0, r1, r2, r3, smem_u32(&Bh[brow][koff]));
                bh[jp][0] = r0; bh[jp + 1][0] = r1; bh[jp][1] = r2; bh[jp + 1][1] = r3;
                LDSM4(r0, r1, r2, r3, smem_u32(&Bl[brow][koff]));
                bl[jp][0] = r0; bl[jp + 1][0] = r1; bl[jp][1] = r2; bl[jp + 1][1] = r3;
            }

            #pragma unroll
            for (int mf = 0; mf < 4; mf++)
                #pragma unroll
                for (int nf = 0; nf < 4; nf++) {
                    MMA16816(acc[mf][nf], ah[mf][0], ah[mf][1], ah[mf][2], ah[mf][3],
                             bh[nf][0], bh[nf][1]);
                    MMA16816(acc[mf][nf], ah[mf][0], ah[mf][1], ah[mf][2], ah[mf][3],
                             bl[nf][0], bl[nf][1]);
                    MMA16816(acc[mf][nf], al[mf][0], al[mf][1], al[mf][2], al[mf][3],
                             bh[nf][0], bh[nf][1]);
                }
        }
    }

    // Epilogue: c0,c1 -> (row, col..col+1); c2,c3 -> (row+8, ...)
    #pragma unroll
    for (int mf = 0; mf < 4; mf++) {
        int r0 = bm * 128 + wm + mf * 16 + (lane >> 2);
        int r1 = r0 + 8;
        if (RC) { r0 = remap_bpt(r0); r1 = remap_bpt(r1); }
        #pragma unroll
        for (int nf = 0; nf < 4; nf++) {
            int col = bn * 128 + wn + nf * 8 + (lane & 3) * 2;
            *(float2*)(C + (size_t)r0 * Ntot + col) = make_float2(acc[mf][nf][0], acc[mf][nf][1]);
            *(float2*)(C + (size_t)r1 * Ntot + col) = make_float2(acc[mf][nf][2], acc[mf][nf][3]);
        }
    }
}

// ---------------- RoPE ----------------
__global__ void rope_k() {
    int idx = blockIdx.x * blockDim.x + threadIdx.x;
    const int QP = NTOK * 16 * 32, KP = NTOK * 4 * 32;
    if (idx >= QP + KP) return;
    float* base;
    int i, tok;
    if (idx < QP) {
        i = idx & 31;
        int r = idx >> 5;
        tok = r >> 4;
        base = g_q + (size_t)tok * 1024 + (r & 15) * 64;
    } else {
        int j = idx - QP;
        i = j & 31;
        int r = j >> 5;
        tok = r >> 2;
        base = g_k + (size_t)tok * 256 + (r & 3) * 64;
    }
    int t = tok & 511;
    float invf = expf(-(float)i * 0.28782313662425574f);
    float ang = (float)t * invf, s, c;
    sincosf(ang, &s, &c);
    float x1 = base[i], x2 = base[i + 32];
    base[i]      = x1 * c - x2 * s;
    base[i + 32] = x1 * s + x2 * c;
}

// ---------------- Flash attention (unchanged, known-good from R1) ----------------
#define SROW 68
__global__ void __launch_bounds__(256) attn_k() {
    extern __shared__ float sm[];
    float* Qs  = sm;
    float* KPs = sm + 64 * SROW;
    float* Vs  = sm + 2 * 64 * SROW;

    int tid = threadIdx.x, row = tid >> 2, col = tid & 3;
    int bph = blockIdx.y, h = bph & 15, bp = bph >> 4, hkv = h >> 2;
    int qt0 = blockIdx.x << 6;

    const float* qbase = g_q + (size_t)(bp * 512) * 1024 + h * 64;
    const float* kbase = g_k + (size_t)(bp * 512) * 256 + hkv * 64;
    const float* vbase = g_v + (size_t)(bp * 512) * 256 + hkv * 64;

    for (int idx = tid; idx < 1024; idx += 256) {
        int r = idx >> 4, c4 = (idx & 15) << 2;
        *(float4*)&Qs[r * SROW + c4] = *(const float4*)(qbase + (size_t)(qt0 + r) * 1024 + c4);
    }

    float s[16], o[16];
    #pragma unroll
    for (int i = 0; i < 16; i++) o[i] = 0.f;
    float m = -INFINITY, l = 0.f;
    const float sc = 0.125f;

    for (int kt0 = 0; kt0 < 512; kt0 += 64) {
        __syncthreads();
        for (int idx = tid; idx < 1024; idx += 256) {
            int r = idx >> 4, c4 = (idx & 15) << 2;
            *(float4*)&KPs[r * SROW + c4] = *(const float4*)(kbase + (size_t)(kt0 + r) * 256 + c4);
            *(float4*)&Vs[r * SROW + c4]  = *(const float4*)(vbase + (size_t)(kt0 + r) * 256 + c4);
        }
        __syncthreads();

        #pragma unroll
        for (int jj = 0; jj < 16; jj++) s[jj] = 0.f;
        #pragma unroll
        for (int d4 = 0; d4 < 64; d4 += 4) {
            float4 q4 = *(float4*)&Qs[row * SROW + d4];
            #pragma unroll
            for (int jj = 0; jj < 16; jj++) {
                float4 k4 = *(float4*)&KPs[(4 * jj + col) * SROW + d4];
                s[jj] = fmaf(q4.x, k4.x, s[jj]);
                s[jj] = fmaf(q4.y, k4.y, s[jj]);
                s[jj] = fmaf(q4.z, k4.z, s[jj]);
                s[jj] = fmaf(q4.w, k4.w, s[jj]);
            }
        }

        float tmax = s[0];
        #pragma unroll
        for (int jj = 1; jj < 16; jj++) tmax = fmaxf(tmax, s[jj]);
        tmax = fmaxf(tmax, __shfl_xor_sync(0xffffffffu, tmax, 1));
        tmax = fmaxf(tmax, __shfl_xor_sync(0xffffffffu, tmax, 2));
        float mnew  = fmaxf(m, sc * tmax);
        float alpha = __expf(m - mnew);

        __syncthreads();
        float psum = 0.f;
        #pragma unroll
        for (int jj = 0; jj < 16; jj++) {
            float p = __expf(fmaf(sc, s[jj], -mnew));
            KPs[row * SROW + 4 * jj + col] = p;
            psum += p;
        }
        psum += __shfl_xor_sync(0xffffffffu, psum, 1);
        psum += __shfl_xor_sync(0xffffffffu, psum, 2);
        l = l * alpha + psum;
        m = mnew;
        #pragma unroll
        for (int i = 0; i < 16; i++) o[i] *= alpha;
        __syncthreads();

        #pragma unroll 8
        for (int j = 0; j < 64; j++) {
            float p = KPs[row * SROW + j];
            const float* vp = &Vs[j * SROW + col * 16];
            float4 v0 = *(const float4*)(vp);
            float4 v1 = *(const float4*)(vp + 4);
            float4 v2 = *(const float4*)(vp + 8);
            float4 v3 = *(const float4*)(vp + 12);
            o[0]  = fmaf(p, v0.x, o[0]);  o[1]  = fmaf(p, v0.y, o[1]);
            o[2]  = fmaf(p, v0.z, o[2]);  o[3]  = fmaf(p, v0.w, o[3]);
            o[4]  = fmaf(p, v1.x, o[4]);  o[5]  = fmaf(p, v1.y, o[5]);
            o[6]  = fmaf(p, v1.z, o[6]);  o[7]  = fmaf(p, v1.w, o[7]);
            o[8]  = fmaf(p, v2.x, o[8]);  o[9]  = fmaf(p, v2.y, o[9]);
            o[10] = fmaf(p, v2.z, o[10]); o[11] = fmaf(p, v2.w, o[11]);
            o[12] = fmaf(p, v3.x, o[12]); o[13] = fmaf(p, v3.y, o[13]);
            o[14] = fmaf(p, v3.z, o[14]); o[15] = fmaf(p, v3.w, o[15]);
        }
    }

    float inv = 1.f / l;
    float* op = g_o + (size_t)(bp * 512 + qt0 + row) * 1024 + h * 64 + col * 16;
    *(float4*)(op)      = make_float4(o[0]*inv,  o[1]*inv,  o[2]*inv,  o[3]*inv);
    *(float4*)(op + 4)  = make_float4(o[4]*inv,  o[5]*inv,  o[6]*inv,  o[7]*inv);
    *(float4*)(op + 8)  = make_float4(o[8]*inv,  o[9]*inv,  o[10]*inv, o[11]*inv);
    *(float4*)(op + 12) = make_float4(o[12]*inv, o[13]*inv, o[14]*inv, o[15]*inv);
}

// ---------------------------------------------------------------------------
extern "C" void kernel_launch(void* const* d_in, const int* in_sizes, int n_in,
                              void* d_out, int out_size) {
    (void)in_sizes; (void)n_in; (void)out_size;
    const float* hidden = (const float*)d_in[0];
    const float* Wq = (const float*)d_in[1];
    const float* Wk = (const float*)d_in[2];
    const float* Wv = (const float*)d_in[3];
    const float* Wo = (const float*)d_in[4];
    float* out = (float*)d_out;

    float *pq, *pk, *pv, *po, *pwt;
    cudaGetSymbolAddress((void**)&pq, g_q);
    cudaGetSymbolAddress((void**)&pk, g_k);
    cudaGetSymbolAddress((void**)&pv, g_v);
    cudaGetSymbolAddress((void**)&po, g_o);
    cudaGetSymbolAddress((void**)&pwt, g_wt);

    const int attn_smem = 3 * 64 * SROW * 4;  // 52224 B
    cudaFuncSetAttribute(attn_k, cudaFuncAttributeMaxDynamicSharedMemorySize, attn_smem);

    // Q projection
    transpose_k<<<dim3(32, 32), dim3(32, 8)>>>(Wq, pwt, 1024);
    bfgemm_k<1, 0><<<dim3(8, 64), 256>>>(hidden, pwt, pq, 1024);
    // K projection
    transpose_k<<<dim3(8, 32), dim3(32, 8)>>>(Wk, pwt, 256);
    bfgemm_k<1, 0><<<dim3(2, 64), 256>>>(hidden, pwt, pk, 256);
    // V projection
    transpose_k<<<dim3(8, 32), dim3(32, 8)>>>(Wv, pwt, 256);
    bfgemm_k<1, 0><<<dim3(2, 64), 256>>>(hidden, pwt, pv, 256);

    rope_k<<<(NTOK * 16 * 32 + NTOK * 4 * 32) / 256, 256>>>();

    attn_k<<<dim3(8, 256), 256, attn_smem>>>();

    // Output projection
    transpose_k<<<dim3(32, 32), dim3(32, 8)>>>(Wo, pwt, 1024);
    bfgemm_k<0, 1><<<dim3(8, 64), 256>>>(po, pwt, out, 1024);
}

// round 5
// speedup vs baseline: 3.0541x; 2.3468x over previous
#include <cuda_runtime.h>
#include <cuda_bf16.h>
#include <cstdint>
#include <math.h>

#define NTOK 8192

__device__ float g_q[NTOK * 1024];
__device__ float g_k[NTOK * 256];
__device__ float g_v[NTOK * 256];
__device__ float g_o[NTOK * 1024];
__device__ float g_wt[1024 * 1024];

__device__ __forceinline__ int remap_bpt(int r) {
    int b = r >> 12, p = (r >> 9) & 7, t = r & 511;
    return (b << 12) + (t << 3) + p;
}

__device__ __forceinline__ uint32_t smem_u32(const void* p) {
    uint32_t a;
    asm("{ .reg .u64 t; cvta.to.shared.u64 t, %1; cvt.u32.u64 %0, t; }" : "=r"(a) : "l"(p));
    return a;
}

#define LDSM4(r0, r1, r2, r3, a) \
    asm volatile("ldmatrix.sync.aligned.m8n8.x4.shared.b16 {%0,%1,%2,%3}, [%4];" \
        : "=r"(r0), "=r"(r1), "=r"(r2), "=r"(r3) : "r"(a))

#define MMA16816(c, a0, a1, a2, a3, b0, b1) \
    asm volatile("mma.sync.aligned.m16n8k16.row.col.f32.bf16.bf16.f32 " \
        "{%0,%1,%2,%3},{%4,%5,%6,%7},{%8,%9},{%0,%1,%2,%3};" \
        : "+f"((c)[0]), "+f"((c)[1]), "+f"((c)[2]), "+f"((c)[3]) \
        : "r"(a0), "r"(a1), "r"(a2), "r"(a3), "r"(b0), "r"(b1))

__device__ __forceinline__ uint32_t pk_bf2(float x, float y) {
    __nv_bfloat162 h = __floats2bfloat162_rn(x, y);
    return *(uint32_t*)&h;
}

// split float4 into bf16 hi (uint2) + bf16 lo residual (uint2)
__device__ __forceinline__ void split_store4(float4 v, void* ph, void* pl) {
    float hx = __bfloat162float(__float2bfloat16_rn(v.x));
    float hy = __bfloat162float(__float2bfloat16_rn(v.y));
    float hz = __bfloat162float(__float2bfloat16_rn(v.z));
    float hw = __bfloat162float(__float2bfloat16_rn(v.w));
    *(uint2*)ph = make_uint2(pk_bf2(hx, hy), pk_bf2(hz, hw));
    *(uint2*)pl = make_uint2(pk_bf2(v.x - hx, v.y - hy), pk_bf2(v.z - hz, v.w - hw));
}

// ---------------- weight transpose: in[1024 x N] -> out[N x 1024] ----------------
__global__ void transpose_k(const float* __restrict__ in, float* __restrict__ out, int N) {
    __shared__ float t[32][33];
    int n0 = blockIdx.x * 32, k0 = blockIdx.y * 32, x = threadIdx.x;
    for (int j = threadIdx.y; j < 32; j += 8)
        t[j][x] = in[(size_t)(k0 + j) * N + n0 + x];
    __syncthreads();
    for (int j = threadIdx.y; j < 32; j += 8)
        out[(size_t)(n0 + j) * 1024 + k0 + x] = t[x][j];
}

// ---------------------------------------------------------------------------
// bf16 3-term-split GEMM via mma.sync (unchanged from R4, validated).
// ---------------------------------------------------------------------------
#define ASTR 40
template<int RA, int RC>
__global__ void __launch_bounds__(256) bfgemm_k(const float* __restrict__ A,
                                                const float* __restrict__ Bt,
                                                float* __restrict__ C, int Ntot) {
    __shared__ __align__(16) __nv_bfloat16 Ah[128][ASTR], Al[128][ASTR];
    __shared__ __align__(16) __nv_bfloat16 Bh[128][ASTR], Bl[128][ASTR];

    int tid = threadIdx.x, wid = tid >> 5, lane = tid & 31;
    int bm = blockIdx.y, bn = blockIdx.x;
    int wm = (wid >> 2) * 64, wn = (wid & 3) * 32;

    float acc[4][4][4];
    #pragma unroll
    for (int i = 0; i < 4; i++)
        #pragma unroll
        for (int j = 0; j < 4; j++)
            #pragma unroll
            for (int q = 0; q < 4; q++) acc[i][j][q] = 0.f;

    int cr[4], ca[4];
    #pragma unroll
    for (int p = 0; p < 4; p++) {
        int id = tid + p * 256;
        cr[p] = id >> 3;
        int am = bm * 128 + cr[p];
        if (RA) am = remap_bpt(am);
        ca[p] = am;
    }
    int kq = (tid & 7) * 4;

    for (int k0 = 0; k0 < 1024; k0 += 32) {
        __syncthreads();
        #pragma unroll
        for (int p = 0; p < 4; p++) {
            int r = cr[p];
            float4 av = *(const float4*)(A + (size_t)ca[p] * 1024 + k0 + kq);
            float4 bv = *(const float4*)(Bt + (size_t)(bn * 128 + r) * 1024 + k0 + kq);
            split_store4(av, &Ah[r][kq], &Al[r][kq]);
            split_store4(bv, &Bh[r][kq], &Bl[r][kq]);
        }
        __syncthreads();

        #pragma unroll
        for (int ks = 0; ks < 2; ks++) {
            int koff = ks * 16 + ((lane >> 4) << 3);
            int arow = wm + (lane & 15);

            uint32_t ah[4][4], al[4][4];
            #pragma unroll
            for (int mf = 0; mf < 4; mf++) {
                LDSM4(ah[mf][0], ah[mf][1], ah[mf][2], ah[mf][3], smem_u32(&Ah[arow + mf * 16][koff]));
                LDSM4(al[mf][0], al[mf][1], al[mf][2], al[mf][3], smem_u32(&Al[arow + mf * 16][koff]));
            }
            uint32_t bh[4][2], bl[4][2];
            #pragma unroll
            for (int jp = 0; jp < 4; jp += 2) {
                int brow = wn + jp * 8 + (lane & 15);
                uint32_t r0, r1, r2, r3;
                LDSM4(r0, r1, r2, r3, smem_u32(&Bh[brow][koff]));
                bh[jp][0] = r0; bh[jp + 1][0] = r1; bh[jp][1] = r2; bh[jp + 1][1] = r3;
                LDSM4(r0, r1, r2, r3, smem_u32(&Bl[brow][koff]));
                bl[jp][0] = r0; bl[jp + 1][0] = r1; bl[jp][1] = r2; bl[jp + 1][1] = r3;
            }
            #pragma unroll
            for (int mf = 0; mf < 4; mf++)
                #pragma unroll
                for (int nf = 0; nf < 4; nf++) {
                    MMA16816(acc[mf][nf], ah[mf][0], ah[mf][1], ah[mf][2], ah[mf][3], bh[nf][0], bh[nf][1]);
                    MMA16816(acc[mf][nf], ah[mf][0], ah[mf][1], ah[mf][2], ah[mf][3], bl[nf][0], bl[nf][1]);
                    MMA16816(acc[mf][nf], al[mf][0], al[mf][1], al[mf][2], al[mf][3], bh[nf][0], bh[nf][1]);
                }
        }
    }

    #pragma unroll
    for (int mf = 0; mf < 4; mf++) {
        int r0 = bm * 128 + wm + mf * 16 + (lane >> 2);
        int r1 = r0 + 8;
        if (RC) { r0 = remap_bpt(r0); r1 = remap_bpt(r1); }
        #pragma unroll
        for (int nf = 0; nf < 4; nf++) {
            int col = bn * 128 + wn + nf * 8 + (lane & 3) * 2;
            *(float2*)(C + (size_t)r0 * Ntot + col) = make_float2(acc[mf][nf][0], acc[mf][nf][1]);
            *(float2*)(C + (size_t)r1 * Ntot + col) = make_float2(acc[mf][nf][2], acc[mf][nf][3]);
        }
    }
}

// ---------------- RoPE ----------------
__global__ void rope_k() {
    int idx = blockIdx.x * blockDim.x + threadIdx.x;
    const int QP = NTOK * 16 * 32, KP = NTOK * 4 * 32;
    if (idx >= QP + KP) return;
    float* base;
    int i, tok;
    if (idx < QP) {
        i = idx & 31;
        int r = idx >> 5;
        tok = r >> 4;
        base = g_q + (size_t)tok * 1024 + (r & 15) * 64;
    } else {
        int j = idx - QP;
        i = j & 31;
        int r = j >> 5;
        tok = r >> 2;
        base = g_k + (size_t)tok * 256 + (r & 3) * 64;
    }
    int t = tok & 511;
    float invf = expf(-(float)i * 0.28782313662425574f);
    float ang = (float)t * invf, s, c;
    sincosf(ang, &s, &c);
    float x1 = base[i], x2 = base[i + 32];
    base[i]      = x1 * c - x2 * s;
    base[i + 32] = x1 * s + x2 * c;
}

// ---------------------------------------------------------------------------
// Flash attention via mma.sync, 3-term split on both GEMMs.
// Block: 128 q rows x one (b,p,h). 8 warps, warp = 16 q rows x full k/d width.
// Q frags preloaded to registers (smem reused for K/V). V transposed in smem
// so PV B-frags use the bfgemm-validated non-trans ldmatrix pattern.
// ---------------------------------------------------------------------------
#define KSTR 72
__global__ void __launch_bounds__(256) attn_mma_k() {
    __shared__ __align__(16) __nv_bfloat16 SM[4 * 64 * KSTR];  // 36864 B
    __nv_bfloat16* Qhi = SM;                    // 128 x KSTR (regions 0-1)
    __nv_bfloat16* Qlo = SM + 2 * 64 * KSTR;    // 128 x KSTR (regions 2-3)
    __nv_bfloat16* Khi = SM;                    // 64 x KSTR
    __nv_bfloat16* Klo = SM + 64 * KSTR;
    __nv_bfloat16* Vth = SM + 2 * 64 * KSTR;    // transposed V [d][k]
    __nv_bfloat16* Vtl = SM + 3 * 64 * KSTR;

    int tid = threadIdx.x, wid = tid >> 5, lane = tid & 31;
    int bph = blockIdx.y, h = bph & 15, bp = bph >> 4, hkv = h >> 2;
    int qt0 = blockIdx.x << 7;

    const float* qbase = g_q + (size_t)(bp * 512 + qt0) * 1024 + h * 64;
    const float* kbase = g_k + (size_t)(bp * 512) * 256 + hkv * 64;
    const float* vbase = g_v + (size_t)(bp * 512) * 256 + hkv * 64;

    // ---- Load Q (pre-scaled by 1/8) as hi/lo bf16 ----
    for (int idx = tid; idx < 2048; idx += 256) {
        int r = idx >> 4, d4 = (idx & 15) << 2;
        float4 v = *(const float4*)(qbase + (size_t)r * 1024 + d4);
        v.x *= 0.125f; v.y *= 0.125f; v.z *= 0.125f; v.w *= 0.125f;
        split_store4(v, &Qhi[r * KSTR + d4], &Qlo[r * KSTR + d4]);
    }
    __syncthreads();

    // ---- Preload Q fragments (warp = rows [wid*16, wid*16+16)) ----
    uint32_t qh[4][4], ql[4][4];
    {
        int row = wid * 16 + (lane & 15);
        #pragma unroll
        for (int ks = 0; ks < 4; ks++) {
            int koff = ks * 16 + ((lane >> 4) << 3);
            LDSM4(qh[ks][0], qh[ks][1], qh[ks][2], qh[ks][3], smem_u32(&Qhi[row * KSTR + koff]));
            LDSM4(ql[ks][0], ql[ks][1], ql[ks][2], ql[ks][3], smem_u32(&Qlo[row * KSTR + koff]));
        }
    }
    __syncthreads();  // done with Q smem; reuse for K/V

    float o[8][4];
    #pragma unroll
    for (int nf = 0; nf < 8; nf++)
        #pragma unroll
        for (int c = 0; c < 4; c++) o[nf][c] = 0.f;
    float m0 = -INFINITY, m1 = -INFINITY, l0 = 0.f, l1 = 0.f;

    for (int kt = 0; kt < 512; kt += 64) {
        // ---- Load K tile (hi/lo) + V tile transposed (hi/lo) ----
        for (int idx = tid; idx < 1024; idx += 256) {
            int r = idx >> 4, d4 = (idx & 15) << 2;
            float4 kv = *(const float4*)(kbase + (size_t)(kt + r) * 256 + d4);
            split_store4(kv, &Khi[r * KSTR + d4], &Klo[r * KSTR + d4]);
            float4 vv = *(const float4*)(vbase + (size_t)(kt + r) * 256 + d4);
            float f[4] = {vv.x, vv.y, vv.z, vv.w};
            #pragma unroll
            for (int j = 0; j < 4; j++) {
                float hi = __bfloat162float(__float2bfloat16_rn(f[j]));
                Vth[(d4 + j) * KSTR + r] = __float2bfloat16_rn(hi);
                Vtl[(d4 + j) * KSTR + r] = __float2bfloat16_rn(f[j] - hi);
            }
        }
        __syncthreads();

        // ---- S = Q K^T (scaled), 3-term split ----
        float s[8][4];
        #pragma unroll
        for (int nf = 0; nf < 8; nf++)
            #pragma unroll
            for (int c = 0; c < 4; c++) s[nf][c] = 0.f;

        #pragma unroll
        for (int ks = 0; ks < 4; ks++) {
            int koff = ks * 16 + ((lane >> 4) << 3);
            #pragma unroll
            for (int jp = 0; jp < 8; jp += 2) {
                int brow = jp * 8 + (lane & 15);
                uint32_t r0, r1, r2, r3, t0, t1, t2, t3;
                LDSM4(r0, r1, r2, r3, smem_u32(&Khi[brow * KSTR + koff]));
                LDSM4(t0, t1, t2, t3, smem_u32(&Klo[brow * KSTR + koff]));
                MMA16816(s[jp],     qh[ks][0], qh[ks][1], qh[ks][2], qh[ks][3], r0, r2);
                MMA16816(s[jp],     qh[ks][0], qh[ks][1], qh[ks][2], qh[ks][3], t0, t2);
                MMA16816(s[jp],     ql[ks][0], ql[ks][1], ql[ks][2], ql[ks][3], r0, r2);
                MMA16816(s[jp + 1], qh[ks][0], qh[ks][1], qh[ks][2], qh[ks][3], r1, r3);
                MMA16816(s[jp + 1], qh[ks][0], qh[ks][1], qh[ks][2], qh[ks][3], t1, t3);
                MMA16816(s[jp + 1], ql[ks][0], ql[ks][1], ql[ks][2], ql[ks][3], r1, r3);
            }
        }

        // ---- Online softmax (rows r = lane>>2 and r+8) ----
        float rmax0 = -INFINITY, rmax1 = -INFINITY;
        #pragma unroll
        for (int nf = 0; nf < 8; nf++) {
            rmax0 = fmaxf(rmax0, fmaxf(s[nf][0], s[nf][1]));
            rmax1 = fmaxf(rmax1, fmaxf(s[nf][2], s[nf][3]));
        }
        rmax0 = fmaxf(rmax0, __shfl_xor_sync(0xffffffffu, rmax0, 1));
        rmax0 = fmaxf(rmax0, __shfl_xor_sync(0xffffffffu, rmax0, 2));
        rmax1 = fmaxf(rmax1, __shfl_xor_sync(0xffffffffu, rmax1, 1));
        rmax1 = fmaxf(rmax1, __shfl_xor_sync(0xffffffffu, rmax1, 2));
        float mn0 = fmaxf(m0, rmax0), mn1 = fmaxf(m1, rmax1);
        float al0 = __expf(m0 - mn0), al1 = __expf(m1 - mn1);
        float ps0 = 0.f, ps1 = 0.f;
        #pragma unroll
        for (int nf = 0; nf < 8; nf++) {
            s[nf][0] = __expf(s[nf][0] - mn0); ps0 += s[nf][0];
            s[nf][1] = __expf(s[nf][1] - mn0); ps0 += s[nf][1];
            s[nf][2] = __expf(s[nf][2] - mn1); ps1 += s[nf][2];
            s[nf][3] = __expf(s[nf][3] - mn1); ps1 += s[nf][3];
        }
        l0 = l0 * al0 + ps0; l1 = l1 * al1 + ps1;
        m0 = mn0; m1 = mn1;
        #pragma unroll
        for (int nf = 0; nf < 8; nf++) {
            o[nf][0] *= al0; o[nf][1] *= al0;
            o[nf][2] *= al1; o[nf][3] *= al1;
        }

        // ---- O += P V (P repacked from S frags in registers, hi/lo split) ----
        #pragma unroll
        for (int ks = 0; ks < 4; ks++) {
            float* pa = s[2 * ks];
            float* pb = s[2 * ks + 1];
            float ha0 = __bfloat162float(__float2bfloat16_rn(pa[0]));
            float ha1 = __bfloat162float(__float2bfloat16_rn(pa[1]));
            float ha2 = __bfloat162float(__float2bfloat16_rn(pa[2]));
            float ha3 = __bfloat162float(__float2bfloat16_rn(pa[3]));
            float hb0 = __bfloat162float(__float2bfloat16_rn(pb[0]));
            float hb1 = __bfloat162float(__float2bfloat16_rn(pb[1]));
            float hb2 = __bfloat162float(__float2bfloat16_rn(pb[2]));
            float hb3 = __bfloat162float(__float2bfloat16_rn(pb[3]));
            uint32_t ah0 = pk_bf2(ha0, ha1), ah1 = pk_bf2(ha2, ha3);
            uint32_t ah2 = pk_bf2(hb0, hb1), ah3 = pk_bf2(hb2, hb3);
            uint32_t al0_ = pk_bf2(pa[0] - ha0, pa[1] - ha1);
            uint32_t al1_ = pk_bf2(pa[2] - ha2, pa[3] - ha3);
            uint32_t al2_ = pk_bf2(pb[0] - hb0, pb[1] - hb1);
            uint32_t al3_ = pk_bf2(pb[2] - hb2, pb[3] - hb3);

            int koff = ks * 16 + ((lane >> 4) << 3);
            #pragma unroll
            for (int jp = 0; jp < 8; jp += 2) {
                int brow = jp * 8 + (lane & 15);
                uint32_t r0, r1, r2, r3, t0, t1, t2, t3;
                LDSM4(r0, r1, r2, r3, smem_u32(&Vth[brow * KSTR + koff]));
                LDSM4(t0, t1, t2, t3, smem_u32(&Vtl[brow * KSTR + koff]));
                MMA16816(o[jp],     ah0, ah1, ah2, ah3, r0, r2);
                MMA16816(o[jp],     ah0, ah1, ah2, ah3, t0, t2);
                MMA16816(o[jp],     al0_, al1_, al2_, al3_, r0, r2);
                MMA16816(o[jp + 1], ah0, ah1, ah2, ah3, r1, r3);
                MMA16816(o[jp + 1], ah0, ah1, ah2, ah3, t1, t3);
                MMA16816(o[jp + 1], al0_, al1_, al2_, al3_, r1, r3);
            }
        }
        __syncthreads();  // before next tile overwrites K/V
    }

    // ---- Finalize: normalize and write ----
    l0 += __shfl_xor_sync(0xffffffffu, l0, 1);
    l0 += __shfl_xor_sync(0xffffffffu, l0, 2);
    l1 += __shfl_xor_sync(0xffffffffu, l1, 1);
    l1 += __shfl_xor_sync(0xffffffffu, l1, 2);
    float inv0 = 1.f / l0, inv1 = 1.f / l1;

    int row = bp * 512 + qt0 + wid * 16 + (lane >> 2);
    float* ob0 = g_o + (size_t)row * 1024 + h * 64 + (lane & 3) * 2;
    float* ob1 = ob0 + 8 * 1024;
    #pragma unroll
    for (int nf = 0; nf < 8; nf++) {
        *(float2*)(ob0 + nf * 8) = make_float2(o[nf][0] * inv0, o[nf][1] * inv0);
        *(float2*)(ob1 + nf * 8) = make_float2(o[nf][2] * inv1, o[nf][3] * inv1);
    }
}

// ---------------------------------------------------------------------------
extern "C" void kernel_launch(void* const* d_in, const int* in_sizes, int n_in,
                              void* d_out, int out_size) {
    (void)in_sizes; (void)n_in; (void)out_size;
    const float* hidden = (const float*)d_in[0];
    const float* Wq = (const float*)d_in[1];
    const float* Wk = (const float*)d_in[2];
    const float* Wv = (const float*)d_in[3];
    const float* Wo = (const float*)d_in[4];
    float* out = (float*)d_out;

    float *pq, *pk, *pv, *po, *pwt;
    cudaGetSymbolAddress((void**)&pq, g_q);
    cudaGetSymbolAddress((void**)&pk, g_k);
    cudaGetSymbolAddress((void**)&pv, g_v);
    cudaGetSymbolAddress((void**)&po, g_o);
    cudaGetSymbolAddress((void**)&pwt, g_wt);

    // Q projection
    transpose_k<<<dim3(32, 32), dim3(32, 8)>>>(Wq, pwt, 1024);
    bfgemm_k<1, 0><<<dim3(8, 64), 256>>>(hidden, pwt, pq, 1024);
    // K projection
    transpose_k<<<dim3(8, 32), dim3(32, 8)>>>(Wk, pwt, 256);
    bfgemm_k<1, 0><<<dim3(2, 64), 256>>>(hidden, pwt, pk, 256);
    // V projection
    transpose_k<<<dim3(8, 32), dim3(32, 8)>>>(Wv, pwt, 256);
    bfgemm_k<1, 0><<<dim3(2, 64), 256>>>(hidden, pwt, pv, 256);

    rope_k<<<(NTOK * 16 * 32 + NTOK * 4 * 32) / 256, 256>>>();

    // Flash attention: 4 q-tiles of 128 x 256 (b,p,h)
    attn_mma_k<<<dim3(4, 256), 256>>>();

    // Output projection
    transpose_k<<<dim3(32, 32), dim3(32, 8)>>>(Wo, pwt, 1024);
    bfgemm_k<0, 1><<<dim3(8, 64), 256>>>(po, pwt, out, 1024);
}

// round 7
// speedup vs baseline: 3.3850x; 1.1083x over previous
#include <cuda_runtime.h>
#include <cuda_bf16.h>
#include <cstdint>
#include <math.h>

#define NTOK 8192

// fp32 intermediates
__device__ float g_q[NTOK * 1024];
__device__ float g_k[NTOK * 256];
__device__ float g_v[NTOK * 256];
__device__ float g_o[NTOK * 1024];
// bf16 hi/lo preconverted operands
__device__ __nv_bfloat16 g_ah[NTOK * 1024], g_al[NTOK * 1024];
__device__ __nv_bfloat16 g_qh[NTOK * 1024], g_ql[NTOK * 1024];
__device__ __nv_bfloat16 g_kh[NTOK * 256],  g_kl[NTOK * 256];
__device__ __nv_bfloat16 g_vth[NTOK * 256], g_vtl[NTOK * 256];
__device__ __nv_bfloat16 g_wth[1024 * 1024], g_wtl[1024 * 1024];

__device__ __forceinline__ int remap_bpt(int r) {
    int b = r >> 12, p = (r >> 9) & 7, t = r & 511;
    return (b << 12) + (t << 3) + p;
}
__device__ __forceinline__ uint32_t smem_u32(const void* p) {
    uint32_t a;
    asm("{ .reg .u64 t; cvta.to.shared.u64 t, %1; cvt.u32.u64 %0, t; }" : "=r"(a) : "l"(p));
    return a;
}
#define LDSM4(r0, r1, r2, r3, a) \
    asm volatile("ldmatrix.sync.aligned.m8n8.x4.shared.b16 {%0,%1,%2,%3}, [%4];" \
        : "=r"(r0), "=r"(r1), "=r"(r2), "=r"(r3) : "r"(a))
#define MMA16816(c, a0, a1, a2, a3, b0, b1) \
    asm volatile("mma.sync.aligned.m16n8k16.row.col.f32.bf16.bf16.f32 " \
        "{%0,%1,%2,%3},{%4,%5,%6,%7},{%8,%9},{%0,%1,%2,%3};" \
        : "+f"((c)[0]), "+f"((c)[1]), "+f"((c)[2]), "+f"((c)[3]) \
        : "r"(a0), "r"(a1), "r"(a2), "r"(a3), "r"(b0), "r"(b1))
#define CP16(dst, src) \
    asm volatile("cp.async.cg.shared.global [%0], [%1], 16;" :: "r"(dst), "l"(src))
#define CP_COMMIT() asm volatile("cp.async.commit_group;" ::: "memory")
#define CP_WAIT1()  asm volatile("cp.async.wait_group 1;" ::: "memory")
#define CP_WAIT0()  asm volatile("cp.async.wait_group 0;" ::: "memory")

__device__ __forceinline__ uint32_t pk_bf2(float x, float y) {
    __nv_bfloat162 h = __floats2bfloat162_rn(x, y);
    return *(uint32_t*)&h;
}
__device__ __forceinline__ void split_store4(float4 v, void* ph, void* pl) {
    float hx = __bfloat162float(__float2bfloat16_rn(v.x));
    float hy = __bfloat162float(__float2bfloat16_rn(v.y));
    float hz = __bfloat162float(__float2bfloat16_rn(v.z));
    float hw = __bfloat162float(__float2bfloat16_rn(v.w));
    *(uint2*)ph = make_uint2(pk_bf2(hx, hy), pk_bf2(hz, hw));
    *(uint2*)pl = make_uint2(pk_bf2(v.x - hx, v.y - hy), pk_bf2(v.z - hz, v.w - hw));
}

// ---------------- prep: A conversion (optionally remap-gather) ----------------
template<int REMAP>
__global__ void __launch_bounds__(256) convA_k(const float* __restrict__ src) {
    int idx = blockIdx.x * 256 + threadIdx.x;     // one float4 each
    int row = idx >> 8, c4 = (idx & 255) * 4;
    int srow = REMAP ? remap_bpt(row) : row;
    float4 v = *(const float4*)(src + (size_t)srow * 1024 + c4);
    split_store4(v, &g_ah[(size_t)row * 1024 + c4], &g_al[(size_t)row * 1024 + c4]);
}

// ---------------- prep: weight transpose + split: in[1024 x N] -> [N x 1024] ----------------
__global__ void transsplit_k(const float* __restrict__ in, int N) {
    __shared__ float t[32][33];
    int n0 = blockIdx.x * 32, k0 = blockIdx.y * 32, x = threadIdx.x;
    for (int j = threadIdx.y; j < 32; j += 8)
        t[j][x] = in[(size_t)(k0 + j) * N + n0 + x];
    __syncthreads();
    for (int j = threadIdx.y; j < 32; j += 8) {
        float v = t[x][j];
        float hi = __bfloat162float(__float2bfloat16_rn(v));
        size_t o = (size_t)(n0 + j) * 1024 + k0 + x;
        g_wth[o] = __float2bfloat16_rn(hi);
        g_wtl[o] = __float2bfloat16_rn(v - hi);
    }
}

// ---------------- prep: rope + scale + split for Q and K ----------------
__global__ void ropesplit_k() {
    int idx = blockIdx.x * blockDim.x + threadIdx.x;
    const int QP = NTOK * 16 * 32, KP = NTOK * 4 * 32;
    if (idx >= QP + KP) return;
    const float* base;
    __nv_bfloat16 *oh, *ol;
    int i, tok;
    float scale;
    if (idx < QP) {
        i = idx & 31;
        int r = idx >> 5;
        tok = r >> 4;
        size_t off = (size_t)tok * 1024 + (r & 15) * 64;
        base = g_q + off; oh = g_qh + off; ol = g_ql + off;
        scale = 0.125f;
    } else {
        int j = idx - QP;
        i = j & 31;
        int r = j >> 5;
        tok = r >> 2;
        size_t off = (size_t)tok * 256 + (r & 3) * 64;
        base = g_k + off; oh = g_kh + off; ol = g_kl + off;
        scale = 1.0f;
    }
    int t = tok & 511;
    float invf = expf(-(float)i * 0.28782313662425574f);
    float ang = (float)t * invf, s, c;
    sincosf(ang, &s, &c);
    float x1 = base[i], x2 = base[i + 32];
    float y1 = (x1 * c - x2 * s) * scale;
    float y2 = (x1 * s + x2 * c) * scale;
    float h1 = __bfloat162float(__float2bfloat16_rn(y1));
    float h2 = __bfloat162float(__float2bfloat16_rn(y2));
    oh[i]      = __float2bfloat16_rn(h1);
    ol[i]      = __float2bfloat16_rn(y1 - h1);
    oh[i + 32] = __float2bfloat16_rn(h2);
    ol[i + 32] = __float2bfloat16_rn(y2 - h2);
}

// ---------------- prep: V transpose+split per (bp,hkv): [512 k][64 d] -> [64 d][512 k] ----------------
__global__ void convV_k() {
    __shared__ float t[32][33];
    int g = blockIdx.z;                  // bp*4 + hkv, 0..63
    int bp = g >> 2, hkv = g & 3;
    int k0 = blockIdx.x * 32, d0 = blockIdx.y * 32, x = threadIdx.x;
    for (int j = threadIdx.y; j < 32; j += 8)
        t[j][x] = g_v[(size_t)(bp * 512 + k0 + j) * 256 + hkv * 64 + d0 + x];
    __syncthreads();
    for (int j = threadIdx.y; j < 32; j += 8) {
        float v = t[x][j];
        float hi = __bfloat162float(__float2bfloat16_rn(v));
        size_t o = (size_t)g * 32768 + (size_t)(d0 + j) * 512 + k0 + x;
        g_vth[o] = __float2bfloat16_rn(hi);
        g_vtl[o] = __float2bfloat16_rn(v - hi);
    }
}

// ---------------------------------------------------------------------------
// Pure-bf16 3-term GEMM with 2-stage cp.async pipeline.
// ---------------------------------------------------------------------------
#define ASTR 40
template<int RC>
__global__ void __launch_bounds__(256) bfgemm2_k(const __nv_bfloat16* __restrict__ Agh,
                                                 const __nv_bfloat16* __restrict__ Agl,
                                                 const __nv_bfloat16* __restrict__ Bgh,
                                                 const __nv_bfloat16* __restrict__ Bgl,
                                                 float* __restrict__ C, int Ntot) {
    extern __shared__ __nv_bfloat16 SM[];
    const int STG = 4 * 128 * ASTR;

    int tid = threadIdx.x, wid = tid >> 5, lane = tid & 31;
    int bm = blockIdx.y, bn = blockIdx.x;
    int wm = (wid >> 2) * 64, wn = (wid & 3) * 32;

    float acc[4][4][4];
    #pragma unroll
    for (int i = 0; i < 4; i++)
        #pragma unroll
        for (int j = 0; j < 4; j++)
            #pragma unroll
            for (int q = 0; q < 4; q++) acc[i][j][q] = 0.f;

    auto issue = [&](int it, int s) {
        __nv_bfloat16* stg = SM + s * STG;
        int k0 = it * 32;
        #pragma unroll
        for (int i = 0; i < 8; i++) {
            int arr = i >> 1;
            int cc = (i & 1) * 256 + tid;
            int r = cc >> 2, kc = (cc & 3) * 8;
            uint32_t dst = smem_u32(stg + arr * 128 * ASTR + r * ASTR + kc);
            const __nv_bfloat16* src;
            if (arr == 0)      src = Agh + (size_t)(bm * 128 + r) * 1024 + k0 + kc;
            else if (arr == 1) src = Agl + (size_t)(bm * 128 + r) * 1024 + k0 + kc;
            else if (arr == 2) src = Bgh + (size_t)(bn * 128 + r) * 1024 + k0 + kc;
            else               src = Bgl + (size_t)(bn * 128 + r) * 1024 + k0 + kc;
            CP16(dst, src);
        }
    };

    issue(0, 0);
    CP_COMMIT();

    for (int it = 0; it < 32; it++) {
        if (it + 1 < 32) { issue(it + 1, (it + 1) & 1); CP_COMMIT(); CP_WAIT1(); }
        else             { CP_WAIT0(); }
        __syncthreads();

        __nv_bfloat16* stg = SM + (it & 1) * STG;
        __nv_bfloat16* sAh = stg;
        __nv_bfloat16* sAl = stg + 128 * ASTR;
        __nv_bfloat16* sBh = stg + 2 * 128 * ASTR;
        __nv_bfloat16* sBl = stg + 3 * 128 * ASTR;

        #pragma unroll
        for (int ks = 0; ks < 2; ks++) {
            int koff = ks * 16 + ((lane >> 4) << 3);
            int arow = wm + (lane & 15);
            uint32_t ah[4][4], al[4][4];
            #pragma unroll
            for (int mf = 0; mf < 4; mf++) {
                LDSM4(ah[mf][0], ah[mf][1], ah[mf][2], ah[mf][3], smem_u32(&sAh[(arow + mf * 16) * ASTR + koff]));
                LDSM4(al[mf][0], al[mf][1], al[mf][2], al[mf][3], smem_u32(&sAl[(arow + mf * 16) * ASTR + koff]));
            }
            uint32_t bh[4][2], bl[4][2];
            #pragma unroll
            for (int jp = 0; jp < 4; jp += 2) {
                int brow = wn + jp * 8 + (lane & 15);
                uint32_t r0, r1, r2, r3;
                LDSM4(r0, r1, r2, r3, smem_u32(&sBh[brow * ASTR + koff]));
                bh[jp][0] = r0; bh[jp + 1][0] = r1; bh[jp][1] = r2; bh[jp + 1][1] = r3;
                LDSM4(r0, r1, r2, r3, smem_u32(&sBl[brow * ASTR + koff]));
                bl[jp][0] = r0; bl[jp + 1][0] = r1; bl[jp][1] = r2; bl[jp + 1][1] = r3;
            }
            #pragma unroll
            for (int mf = 0; mf < 4; mf++)
                #pragma unroll
                for (int nf = 0; nf < 4; nf++) {
                    MMA16816(acc[mf][nf], ah[mf][0], ah[mf][1], ah[mf][2], ah[mf][3], bh[nf][0], bh[nf][1]);
                    MMA16816(acc[mf][nf], ah[mf][0], ah[mf][1], ah[mf][2], ah[mf][3], bl[nf][0], bl[nf][1]);
                    MMA16816(acc[mf][nf], al[mf][0], al[mf][1], al[mf][2], al[mf][3], bh[nf][0], bh[nf][1]);
                }
        }
        __syncthreads();
    }

    #pragma unroll
    for (int mf = 0; mf < 4; mf++) {
        int r0 = bm * 128 + wm + mf * 16 + (lane >> 2);
        int r1 = r0 + 8;
        if (RC) { r0 = remap_bpt(r0); r1 = remap_bpt(r1); }
        #pragma unroll
        for (int nf = 0; nf < 4; nf++) {
            int col = bn * 128 + wn + nf * 8 + (lane & 3) * 2;
            *(float2*)(C + (size_t)r0 * Ntot + col) = make_float2(acc[mf][nf][0], acc[mf][nf][1]);
            *(float2*)(C + (size_t)r1 * Ntot + col) = make_float2(acc[mf][nf][2], acc[mf][nf][3]);
        }
    }
}

// ---------------------------------------------------------------------------
// Flash attention, pure bf16, 2-stage cp.async pipeline.
// ---------------------------------------------------------------------------
#define KSTR 72
__global__ void __launch_bounds__(256) attn2_k() {
    extern __shared__ __nv_bfloat16 ASM[];
    const int STG = 4 * 64 * KSTR;

    int tid = threadIdx.x, wid = tid >> 5, lane = tid & 31;
    int bph = blockIdx.y, h = bph & 15, bp = bph >> 4, hkv = h >> 2;
    int qt0 = blockIdx.x << 7;
    int qrow0 = bp * 512 + qt0;
    size_t vbase = (size_t)(bp * 4 + hkv) * 32768;

    // ---- Q tile into smem, then frags to registers ----
    {
        #pragma unroll
        for (int i = 0; i < 8; i++) {
            int half = i >> 2;
            int cc = (i & 3) * 256 + tid;
            int r = cc >> 3, kc = (cc & 7) * 8;
            uint32_t dst = smem_u32(ASM + half * 128 * KSTR + r * KSTR + kc);
            const __nv_bfloat16* src = (half ? g_ql : g_qh) + (size_t)(qrow0 + r) * 1024 + h * 64 + kc;
            CP16(dst, src);
        }
        CP_COMMIT(); CP_WAIT0();
        __syncthreads();
    }
    uint32_t qh[4][4], ql[4][4];
    {
        __nv_bfloat16* Qhi = ASM;
        __nv_bfloat16* Qlo = ASM + 128 * KSTR;
        int row = wid * 16 + (lane & 15);
        #pragma unroll
        for (int ks = 0; ks < 4; ks++) {
            int koff = ks * 16 + ((lane >> 4) << 3);
            LDSM4(qh[ks][0], qh[ks][1], qh[ks][2], qh[ks][3], smem_u32(&Qhi[row * KSTR + koff]));
            LDSM4(ql[ks][0], ql[ks][1], ql[ks][2], ql[ks][3], smem_u32(&Qlo[row * KSTR + koff]));
        }
    }
    __syncthreads();

    auto issue = [&](int it, int s) {
        __nv_bfloat16* stg = ASM + s * STG;
        int kt = it * 64;
        #pragma unroll
        for (int i = 0; i < 8; i++) {
            int arr = i >> 1;
            int cc = (i & 1) * 256 + tid;
            int r = cc >> 3, kc = (cc & 7) * 8;
            uint32_t dst = smem_u32(stg + arr * 64 * KSTR + r * KSTR + kc);
            const __nv_bfloat16* src;
            if (arr == 0)      src = g_kh + (size_t)(bp * 512 + kt + r) * 256 + hkv * 64 + kc;
            else if (arr == 1) src = g_kl + (size_t)(bp * 512 + kt + r) * 256 + hkv * 64 + kc;
            else if (arr == 2) src = g_vth + vbase + (size_t)r * 512 + kt + kc;
            else               src = g_vtl + vbase + (size_t)r * 512 + kt + kc;
            CP16(dst, src);
        }
    };

    float o[8][4];
    #pragma unroll
    for (int nf = 0; nf < 8; nf++)
        #pragma unroll
        for (int c = 0; c < 4; c++) o[nf][c] = 0.f;
    float m0 = -INFINITY, m1 = -INFINITY, l0 = 0.f, l1 = 0.f;

    issue(0, 0);
    CP_COMMIT();

    for (int it = 0; it < 8; it++) {
        if (it + 1 < 8) { issue(it + 1, (it + 1) & 1); CP_COMMIT(); CP_WAIT1(); }
        else            { CP_WAIT0(); }
        __syncthreads();

        __nv_bfloat16* stg = ASM + (it & 1) * STG;
        __nv_bfloat16* Khi = stg;
        __nv_bfloat16* Klo = stg + 64 * KSTR;
        __nv_bfloat16* Vth = stg + 2 * 64 * KSTR;
        __nv_bfloat16* Vtl = stg + 3 * 64 * KSTR;

        float s[8][4];
        #pragma unroll
        for (int nf = 0; nf < 8; nf++)
            #pragma unroll
            for (int c = 0; c < 4; c++) s[nf][c] = 0.f;

        #pragma unroll
        for (int ks = 0; ks < 4; ks++) {
            int koff = ks * 16 + ((lane >> 4) << 3);
            #pragma unroll
            for (int jp = 0; jp < 8; jp += 2) {
                int brow = jp * 8 + (lane & 15);
                uint32_t r0, r1, r2, r3, t0, t1, t2, t3;
                LDSM4(r0, r1, r2, r3, smem_u32(&Khi[brow * KSTR + koff]));
                LDSM4(t0, t1, t2, t3, smem_u32(&Klo[brow * KSTR + koff]));
                MMA16816(s[jp],     qh[ks][0], qh[ks][1], qh[ks][2], qh[ks][3], r0, r2);
                MMA16816(s[jp],     qh[ks][0], qh[ks][1], qh[ks][2], qh[ks][3], t0, t2);
                MMA16816(s[jp],     ql[ks][0], ql[ks][1], ql[ks][2], ql[ks][3], r0, r2);
                MMA16816(s[jp + 1], qh[ks][0], qh[ks][1], qh[ks][2], qh[ks][3], r1, r3);
                MMA16816(s[jp + 1], qh[ks][0], qh[ks][1], qh[ks][2], qh[ks][3], t1, t3);
                MMA16816(s[jp + 1], ql[ks][0], ql[ks][1], ql[ks][2], ql[ks][3], r1, r3);
            }
        }

        float rmax0 = -INFINITY, rmax1 = -INFINITY;
        #pragma unroll
        for (int nf = 0; nf < 8; nf++) {
            rmax0 = fmaxf(rmax0, fmaxf(s[nf][0], s[nf][1]));
            rmax1 = fmaxf(rmax1, fmaxf(s[nf][2], s[nf][3]));
        }
        rmax0 = fmaxf(rmax0, __shfl_xor_sync(0xffffffffu, rmax0, 1));
        rmax0 = fmaxf(rmax0, __shfl_xor_sync(0xffffffffu, rmax0, 2));
        rmax1 = fmaxf(rmax1, __shfl_xor_sync(0xffffffffu, rmax1, 1));
        rmax1 = fmaxf(rmax1, __shfl_xor_sync(0xffffffffu, rmax1, 2));
        float mn0 = fmaxf(m0, rmax0), mn1 = fmaxf(m1, rmax1);
        float al0 = __expf(m0 - mn0), al1 = __expf(m1 - mn1);
        float ps0 = 0.f, ps1 = 0.f;
        #pragma unroll
        for (int nf = 0; nf < 8; nf++) {
            s[nf][0] = __expf(s[nf][0] - mn0); ps0 += s[nf][0];
            s[nf][1] = __expf(s[nf][1] - mn0); ps0 += s[nf][1];
            s[nf][2] = __expf(s[nf][2] - mn1); ps1 += s[nf][2];
            s[nf][3] = __expf(s[nf][3] - mn1); ps1 += s[nf][3];
        }
        l0 = l0 * al0 + ps0; l1 = l1 * al1 + ps1;
        m0 = mn0; m1 = mn1;
        #pragma unroll
        for (int nf = 0; nf < 8; nf++) {
            o[nf][0] *= al0; o[nf][1] *= al0;
            o[nf][2] *= al1; o[nf][3] *= al1;
        }

        #pragma unroll
        for (int ks = 0; ks < 4; ks++) {
            float* pa = s[2 * ks];
            float* pb = s[2 * ks + 1];
            float ha0 = __bfloat162float(__float2bfloat16_rn(pa[0]));
            float ha1 = __bfloat162float(__float2bfloat16_rn(pa[1]));
            float ha2 = __bfloat162float(__float2bfloat16_rn(pa[2]));
            float ha3 = __bfloat162float(__float2bfloat16_rn(pa[3]));
            float hb0 = __bfloat162float(__float2bfloat16_rn(pb[0]));
            float hb1 = __bfloat162float(__float2bfloat16_rn(pb[1]));
            float hb2 = __bfloat162float(__float2bfloat16_rn(pb[2]));
            float hb3 = __bfloat162float(__float2bfloat16_rn(pb[3]));
            uint32_t ah0 = pk_bf2(ha0, ha1), ah1 = pk_bf2(ha2, ha3);
            uint32_t ah2 = pk_bf2(hb0, hb1), ah3 = pk_bf2(hb2, hb3);
            uint32_t pl0 = pk_bf2(pa[0] - ha0, pa[1] - ha1);
            uint32_t pl1 = pk_bf2(pa[2] - ha2, pa[3] - ha3);
            uint32_t pl2 = pk_bf2(pb[0] - hb0, pb[1] - hb1);
            uint32_t pl3 = pk_bf2(pb[2] - hb2, pb[3] - hb3);

            int koff = ks * 16 + ((lane >> 4) << 3);
            #pragma unroll
            for (int jp = 0; jp < 8; jp += 2) {
                int brow = jp * 8 + (lane & 15);
                uint32_t r0, r1, r2, r3, t0, t1, t2, t3;
                LDSM4(r0, r1, r2, r3, smem_u32(&Vth[brow * KSTR + koff]));
                LDSM4(t0, t1, t2, t3, smem_u32(&Vtl[brow * KSTR + koff]));
                MMA16816(o[jp],     ah0, ah1, ah2, ah3, r0, r2);
                MMA16816(o[jp],     ah0, ah1, ah2, ah3, t0, t2);
                MMA16816(o[jp],     pl0, pl1, pl2, pl3, r0, r2);
                MMA16816(o[jp + 1], ah0, ah1, ah2, ah3, r1, r3);
                MMA16816(o[jp + 1], ah0, ah1, ah2, ah3, t1, t3);
                MMA16816(o[jp + 1], pl0, pl1, pl2, pl3, r1, r3);
            }
        }
        __syncthreads();
    }

    l0 += __shfl_xor_sync(0xffffffffu, l0, 1);
    l0 += __shfl_xor_sync(0xffffffffu, l0, 2);
    l1 += __shfl_xor_sync(0xffffffffu, l1, 1);
    l1 += __shfl_xor_sync(0xffffffffu, l1, 2);
    float inv0 = 1.f / l0, inv1 = 1.f / l1;

    int row = qrow0 + wid * 16 + (lane >> 2);
    float* ob0 = g_o + (size_t)row * 1024 + h * 64 + (lane & 3) * 2;
    float* ob1 = ob0 + 8 * 1024;
    #pragma unroll
    for (int nf = 0; nf < 8; nf++) {
        *(float2*)(ob0 + nf * 8) = make_float2(o[nf][0] * inv0, o[nf][1] * inv0);
        *(float2*)(ob1 + nf * 8) = make_float2(o[nf][2] * inv1, o[nf][3] * inv1);
    }
}

// ---------------------------------------------------------------------------
extern "C" void kernel_launch(void* const* d_in, const int* in_sizes, int n_in,
                              void* d_out, int out_size) {
    (void)in_sizes; (void)n_in; (void)out_size;
    const float* hidden = (const float*)d_in[0];
    const float* Wq = (const float*)d_in[1];
    const float* Wk = (const float*)d_in[2];
    const float* Wv = (const float*)d_in[3];
    const float* Wo = (const float*)d_in[4];
    float* out = (float*)d_out;

    float *pq, *pk, *pv, *po;
    __nv_bfloat16 *pah, *pal, *pwh, *pwl;
    cudaGetSymbolAddress((void**)&pq, g_q);
    cudaGetSymbolAddress((void**)&pk, g_k);
    cudaGetSymbolAddress((void**)&pv, g_v);
    cudaGetSymbolAddress((void**)&po, g_o);
    cudaGetSymbolAddress((void**)&pah, g_ah);
    cudaGetSymbolAddress((void**)&pal, g_al);
    cudaGetSymbolAddress((void**)&pwh, g_wth);
    cudaGetSymbolAddress((void**)&pwl, g_wtl);

    const int gsm = 2 * 4 * 128 * ASTR * 2;   // 81920 B
    const int asm_ = 2 * 4 * 64 * KSTR * 2;   // 73728 B
    cudaFuncSetAttribute(bfgemm2_k<0>, cudaFuncAttributeMaxDynamicSharedMemorySize, gsm);
    cudaFuncSetAttribute(bfgemm2_k<1>, cudaFuncAttributeMaxDynamicSharedMemorySize, gsm);
    cudaFuncSetAttribute(attn2_k, cudaFuncAttributeMaxDynamicSharedMemorySize, asm_);

    // Preconvert A (hidden, remap-gathered) once for all QKV projections
    convA_k<1><<<8192, 256>>>(hidden);

    // Q projection
    transsplit_k<<<dim3(32, 32), dim3(32, 8)>>>(Wq, 1024);
    bfgemm2_k<0><<<dim3(8, 64), 256, gsm>>>(pah, pal, pwh, pwl, pq, 1024);
    // K projection
    transsplit_k<<<dim3(8, 32), dim3(32, 8)>>>(Wk, 256);
    bfgemm2_k<0><<<dim3(2, 64), 256, gsm>>>(pah, pal, pwh, pwl, pk, 256);
    // V projection
    transsplit_k<<<dim3(8, 32), dim3(32, 8)>>>(Wv, 256);
    bfgemm2_k<0><<<dim3(2, 64), 256, gsm>>>(pah, pal, pwh, pwl, pv, 256);

    // RoPE + scale + bf16 split for Q/K; V transpose + split (z = 64 groups — R6 bugfix)
    ropesplit_k<<<(NTOK * 16 * 32 + NTOK * 4 * 32) / 256, 256>>>();
    convV_k<<<dim3(16, 2, 64), dim3(32, 8)>>>();

    // Attention
    attn2_k<<<dim3(4, 256), 256, asm_>>>();

    // Output projection (convert attention output, then GEMM with remap scatter)
    convA_k<0><<<8192, 256>>>(po);
    transsplit_k<<<dim3(32, 32), dim3(32, 8)>>>(Wo, 1024);
    bfgemm2_k<1><<<dim3(8, 64), 256, gsm>>>(pah, pal, pwh, pwl, out, 1024);
}

// round 8
// speedup vs baseline: 3.5143x; 1.0382x over previous
#include <cuda_runtime.h>
#include <cuda_bf16.h>
#include <cstdint>
#include <math.h>

#define NTOK 8192

// fp32 intermediates
__device__ float g_q[NTOK * 1024];
__device__ float g_k[NTOK * 256];
__device__ float g_v[NTOK * 256];
__device__ float g_o[NTOK * 1024];
// bf16 hi/lo preconverted operands
__device__ __nv_bfloat16 g_ah[NTOK * 1024], g_al[NTOK * 1024];
__device__ __nv_bfloat16 g_qh[NTOK * 1024], g_ql[NTOK * 1024];
__device__ __nv_bfloat16 g_kh[NTOK * 256],  g_kl[NTOK * 256];
__device__ __nv_bfloat16 g_vth[NTOK * 256], g_vtl[NTOK * 256];
__device__ __nv_bfloat16 g_wth[1536 * 1024], g_wtl[1536 * 1024];  // QKV concat (or Wo)

__device__ __forceinline__ int remap_bpt(int r) {
    int b = r >> 12, p = (r >> 9) & 7, t = r & 511;
    return (b << 12) + (t << 3) + p;
}
__device__ __forceinline__ uint32_t smem_u32(const void* p) {
    uint32_t a;
    asm("{ .reg .u64 t; cvta.to.shared.u64 t, %1; cvt.u32.u64 %0, t; }" : "=r"(a) : "l"(p));
    return a;
}
#define LDSM4(r0, r1, r2, r3, a) \
    asm volatile("ldmatrix.sync.aligned.m8n8.x4.shared.b16 {%0,%1,%2,%3}, [%4];" \
        : "=r"(r0), "=r"(r1), "=r"(r2), "=r"(r3) : "r"(a))
#define MMA16816(c, a0, a1, a2, a3, b0, b1) \
    asm volatile("mma.sync.aligned.m16n8k16.row.col.f32.bf16.bf16.f32 " \
        "{%0,%1,%2,%3},{%4,%5,%6,%7},{%8,%9},{%0,%1,%2,%3};" \
        : "+f"((c)[0]), "+f"((c)[1]), "+f"((c)[2]), "+f"((c)[3]) \
        : "r"(a0), "r"(a1), "r"(a2), "r"(a3), "r"(b0), "r"(b1))
#define CP16(dst, src) \
    asm volatile("cp.async.cg.shared.global [%0], [%1], 16;" :: "r"(dst), "l"(src))
#define CP_COMMIT() asm volatile("cp.async.commit_group;" ::: "memory")
#define CP_WAIT0()  asm volatile("cp.async.wait_group 0;" ::: "memory")

__device__ __forceinline__ uint32_t pk_bf2(float x, float y) {
    __nv_bfloat162 h = __floats2bfloat162_rn(x, y);
    return *(uint32_t*)&h;
}
__device__ __forceinline__ void split_store4(float4 v, void* ph, void* pl) {
    float hx = __bfloat162float(__float2bfloat16_rn(v.x));
    float hy = __bfloat162float(__float2bfloat16_rn(v.y));
    float hz = __bfloat162float(__float2bfloat16_rn(v.z));
    float hw = __bfloat162float(__float2bfloat16_rn(v.w));
    *(uint2*)ph = make_uint2(pk_bf2(hx, hy), pk_bf2(hz, hw));
    *(uint2*)pl = make_uint2(pk_bf2(v.x - hx, v.y - hy), pk_bf2(v.z - hz, v.w - hw));
}

// ---------------- prep: A conversion (optionally remap-gather) ----------------
template<int REMAP>
__global__ void __launch_bounds__(256) convA_k(const float* __restrict__ src) {
    int idx = blockIdx.x * 256 + threadIdx.x;
    int row = idx >> 8, c4 = (idx & 255) * 4;
    int srow = REMAP ? remap_bpt(row) : row;
    float4 v = *(const float4*)(src + (size_t)srow * 1024 + c4);
    split_store4(v, &g_ah[(size_t)row * 1024 + c4], &g_al[(size_t)row * 1024 + c4]);
}

// ---------------- prep: fused QKV weight transpose + split ----------------
// Wq -> rows [0,1024), Wk -> [1024,1280), Wv -> [1280,1536) of g_wth/g_wtl
__global__ void transsplit3_k(const float* __restrict__ Wq,
                              const float* __restrict__ Wk,
                              const float* __restrict__ Wv) {
    __shared__ float t[32][33];
    int z = blockIdx.z;
    const float* in = (z == 0) ? Wq : (z == 1) ? Wk : Wv;
    int N = (z == 0) ? 1024 : 256;
    int rowoff = (z == 0) ? 0 : (z == 1) ? 1024 : 1280;
    int n0 = blockIdx.x * 32;
    if (n0 >= N) return;
    int k0 = blockIdx.y * 32, x = threadIdx.x;
    for (int j = threadIdx.y; j < 32; j += 8)
        t[j][x] = in[(size_t)(k0 + j) * N + n0 + x];
    __syncthreads();
    for (int j = threadIdx.y; j < 32; j += 8) {
        float v = t[x][j];
        float hi = __bfloat162float(__float2bfloat16_rn(v));
        size_t o = (size_t)(rowoff + n0 + j) * 1024 + k0 + x;
        g_wth[o] = __float2bfloat16_rn(hi);
        g_wtl[o] = __float2bfloat16_rn(v - hi);
    }
}

// single-weight variant (Wo), rows [0,1024)
__global__ void transsplit_k(const float* __restrict__ in) {
    __shared__ float t[32][33];
    int n0 = blockIdx.x * 32, k0 = blockIdx.y * 32, x = threadIdx.x;
    for (int j = threadIdx.y; j < 32; j += 8)
        t[j][x] = in[(size_t)(k0 + j) * 1024 + n0 + x];
    __syncthreads();
    for (int j = threadIdx.y; j < 32; j += 8) {
        float v = t[x][j];
        float hi = __bfloat162float(__float2bfloat16_rn(v));
        size_t o = (size_t)(n0 + j) * 1024 + k0 + x;
        g_wth[o] = __float2bfloat16_rn(hi);
        g_wtl[o] = __float2bfloat16_rn(v - hi);
    }
}

// ---------------- prep: rope + scale + split (Q scale includes log2e) ----------------
__global__ void ropesplit_k() {
    int idx = blockIdx.x * blockDim.x + threadIdx.x;
    const int QP = NTOK * 16 * 32, KP = NTOK * 4 * 32;
    if (idx >= QP + KP) return;
    const float* base;
    __nv_bfloat16 *oh, *ol;
    int i, tok;
    float scale;
    if (idx < QP) {
        i = idx & 31;
        int r = idx >> 5;
        tok = r >> 4;
        size_t off = (size_t)tok * 1024 + (r & 15) * 64;
        base = g_q + off; oh = g_qh + off; ol = g_ql + off;
        scale = 0.125f * 1.4426950408889634f;   // fold log2(e): softmax in exp2 domain
    } else {
        int j = idx - QP;
        i = j & 31;
        int r = j >> 5;
        tok = r >> 2;
        size_t off = (size_t)tok * 256 + (r & 3) * 64;
        base = g_k + off; oh = g_kh + off; ol = g_kl + off;
        scale = 1.0f;
    }
    int t = tok & 511;
    float invf = expf(-(float)i * 0.28782313662425574f);
    float ang = (float)t * invf, s, c;
    sincosf(ang, &s, &c);
    float x1 = base[i], x2 = base[i + 32];
    float y1 = (x1 * c - x2 * s) * scale;
    float y2 = (x1 * s + x2 * c) * scale;
    float h1 = __bfloat162float(__float2bfloat16_rn(y1));
    float h2 = __bfloat162float(__float2bfloat16_rn(y2));
    oh[i]      = __float2bfloat16_rn(h1);
    ol[i]      = __float2bfloat16_rn(y1 - h1);
    oh[i + 32] = __float2bfloat16_rn(h2);
    ol[i + 32] = __float2bfloat16_rn(y2 - h2);
}

// ---------------- prep: V transpose+split per (bp,hkv) ----------------
__global__ void convV_k() {
    __shared__ float t[32][33];
    int g = blockIdx.z;                  // bp*4 + hkv, 0..63
    int bp = g >> 2, hkv = g & 3;
    int k0 = blockIdx.x * 32, d0 = blockIdx.y * 32, x = threadIdx.x;
    for (int j = threadIdx.y; j < 32; j += 8)
        t[j][x] = g_v[(size_t)(bp * 512 + k0 + j) * 256 + hkv * 64 + d0 + x];
    __syncthreads();
    for (int j = threadIdx.y; j < 32; j += 8) {
        float v = t[x][j];
        float hi = __bfloat162float(__float2bfloat16_rn(v));
        size_t o = (size_t)g * 32768 + (size_t)(d0 + j) * 512 + k0 + x;
        g_vth[o] = __float2bfloat16_rn(hi);
        g_vtl[o] = __float2bfloat16_rn(v - hi);
    }
}

// ---------------------------------------------------------------------------
// GEMM compute core (shared by QKV-fused and O kernels).
// One __syncthreads per k-iter: wait0 -> sync -> issue(next) -> compute.
// ---------------------------------------------------------------------------
#define ASTR 40

struct GemmCore {
    __nv_bfloat16* SM;
    int tid, wid, lane, wm, wn;
    float acc[4][4][4];

    __device__ __forceinline__ void init(__nv_bfloat16* sm, int t) {
        SM = sm; tid = t; wid = t >> 5; lane = t & 31;
        wm = (wid >> 2) * 64; wn = (wid & 3) * 32;
        #pragma unroll
        for (int i = 0; i < 4; i++)
            #pragma unroll
            for (int j = 0; j < 4; j++)
                #pragma unroll
                for (int q = 0; q < 4; q++) acc[i][j][q] = 0.f;
    }
    __device__ __forceinline__ void issue(const __nv_bfloat16* Agh, const __nv_bfloat16* Agl,
                                          const __nv_bfloat16* Bgh, const __nv_bfloat16* Bgl,
                                          int am0, int bn0, int k0, int s) {
        __nv_bfloat16* stg = SM + s * (4 * 128 * ASTR);
        #pragma unroll
        for (int i = 0; i < 8; i++) {
            int arr = i >> 1;
            int cc = (i & 1) * 256 + tid;
            int r = cc >> 2, kc = (cc & 3) * 8;
            uint32_t dst = smem_u32(stg + arr * 128 * ASTR + r * ASTR + kc);
            const __nv_bfloat16* src;
            if (arr == 0)      src = Agh + (size_t)(am0 + r) * 1024 + k0 + kc;
            else if (arr == 1) src = Agl + (size_t)(am0 + r) * 1024 + k0 + kc;
            else if (arr == 2) src = Bgh + (size_t)(bn0 + r) * 1024 + k0 + kc;
            else               src = Bgl + (size_t)(bn0 + r) * 1024 + k0 + kc;
            CP16(dst, src);
        }
    }
    __device__ __forceinline__ void compute(int s) {
        __nv_bfloat16* stg = SM + s * (4 * 128 * ASTR);
        __nv_bfloat16* sAh = stg;
        __nv_bfloat16* sAl = stg + 128 * ASTR;
        __nv_bfloat16* sBh = stg + 2 * 128 * ASTR;
        __nv_bfloat16* sBl = stg + 3 * 128 * ASTR;
        #pragma unroll
        for (int ks = 0; ks < 2; ks++) {
            int koff = ks * 16 + ((lane >> 4) << 3);
            int arow = wm + (lane & 15);
            uint32_t ah[4][4], al[4][4];
            #pragma unroll
            for (int mf = 0; mf < 4; mf++) {
                LDSM4(ah[mf][0], ah[mf][1], ah[mf][2], ah[mf][3], smem_u32(&sAh[(arow + mf * 16) * ASTR + koff]));
                LDSM4(al[mf][0], al[mf][1], al[mf][2], al[mf][3], smem_u32(&sAl[(arow + mf * 16) * ASTR + koff]));
            }
            uint32_t bh[4][2], bl[4][2];
            #pragma unroll
            for (int jp = 0; jp < 4; jp += 2) {
                int brow = wn + jp * 8 + (lane & 15);
                uint32_t r0, r1, r2, r3;
                LDSM4(r0, r1, r2, r3, smem_u32(&sBh[brow * ASTR + koff]));
                bh[jp][0] = r0; bh[jp + 1][0] = r1; bh[jp][1] = r2; bh[jp + 1][1] = r3;
                LDSM4(r0, r1, r2, r3, smem_u32(&sBl[brow * ASTR + koff]));
                bl[jp][0] = r0; bl[jp + 1][0] = r1; bl[jp][1] = r2; bl[jp + 1][1] = r3;
            }
            #pragma unroll
            for (int mf = 0; mf < 4; mf++)
                #pragma unroll
                for (int nf = 0; nf < 4; nf++) {
                    MMA16816(acc[mf][nf], ah[mf][0], ah[mf][1], ah[mf][2], ah[mf][3], bh[nf][0], bh[nf][1]);
                    MMA16816(acc[mf][nf], ah[mf][0], ah[mf][1], ah[mf][2], ah[mf][3], bl[nf][0], bl[nf][1]);
                    MMA16816(acc[mf][nf], al[mf][0], al[mf][1], al[mf][2], al[mf][3], bh[nf][0], bh[nf][1]);
                }
        }
    }
};

// Fused QKV projection: A = g_ah/g_al (pre-remapped), B rows 0..1535 of g_wth/g_wtl.
// bn<8 -> Q cols, bn in {8,9} -> K, {10,11} -> V.
__global__ void __launch_bounds__(256) bfgemmQKV_k() {
    extern __shared__ __nv_bfloat16 SM[];
    GemmCore g;
    g.init(SM, threadIdx.x);
    int bm = blockIdx.y, bn = blockIdx.x;
    int am0 = bm * 128, bn0 = bn * 128;

    g.issue(g_ah, g_al, g_wth, g_wtl, am0, bn0, 0, 0);
    CP_COMMIT();
    for (int it = 0; it < 32; it++) {
        CP_WAIT0();
        __syncthreads();
        if (it + 1 < 32) { g.issue(g_ah, g_al, g_wth, g_wtl, am0, bn0, (it + 1) * 32, (it + 1) & 1); CP_COMMIT(); }
        g.compute(it & 1);
    }

    float* C; int Ntot, colb;
    if (bn < 8)       { C = g_q; Ntot = 1024; colb = bn * 128; }
    else if (bn < 10) { C = g_k; Ntot = 256;  colb = (bn - 8) * 128; }
    else              { C = g_v; Ntot = 256;  colb = (bn - 10) * 128; }
    #pragma unroll
    for (int mf = 0; mf < 4; mf++) {
        int r0 = am0 + g.wm + mf * 16 + (g.lane >> 2);
        int r1 = r0 + 8;
        #pragma unroll
        for (int nf = 0; nf < 4; nf++) {
            int col = colb + g.wn + nf * 8 + (g.lane & 3) * 2;
            *(float2*)(C + (size_t)r0 * Ntot + col) = make_float2(g.acc[mf][nf][0], g.acc[mf][nf][1]);
            *(float2*)(C + (size_t)r1 * Ntot + col) = make_float2(g.acc[mf][nf][2], g.acc[mf][nf][3]);
        }
    }
}

// Output projection: A = g_ah/g_al (converted attention output), C scattered via remap.
__global__ void __launch_bounds__(256) bfgemmO_k(float* __restrict__ C) {
    extern __shared__ __nv_bfloat16 SM[];
    GemmCore g;
    g.init(SM, threadIdx.x);
    int bm = blockIdx.y, bn = blockIdx.x;
    int am0 = bm * 128, bn0 = bn * 128;

    g.issue(g_ah, g_al, g_wth, g_wtl, am0, bn0, 0, 0);
    CP_COMMIT();
    for (int it = 0; it < 32; it++) {
        CP_WAIT0();
        __syncthreads();
        if (it + 1 < 32) { g.issue(g_ah, g_al, g_wth, g_wtl, am0, bn0, (it + 1) * 32, (it + 1) & 1); CP_COMMIT(); }
        g.compute(it & 1);
    }
    #pragma unroll
    for (int mf = 0; mf < 4; mf++) {
        int r0 = remap_bpt(am0 + g.wm + mf * 16 + (g.lane >> 2));
        int r1 = remap_bpt(am0 + g.wm + mf * 16 + (g.lane >> 2) + 8);
        #pragma unroll
        for (int nf = 0; nf < 4; nf++) {
            int col = bn0 + g.wn + nf * 8 + (g.lane & 3) * 2;
            *(float2*)(C + (size_t)r0 * 1024 + col) = make_float2(g.acc[mf][nf][0], g.acc[mf][nf][1]);
            *(float2*)(C + (size_t)r1 * 1024 + col) = make_float2(g.acc[mf][nf][2], g.acc[mf][nf][3]);
        }
    }
}

// ---------------------------------------------------------------------------
// Flash attention, pure bf16, 2-stage cp.async, ONE sync per iter, exp2 softmax.
// ---------------------------------------------------------------------------
#define KSTR 72
__global__ void __launch_bounds__(256) attn2_k() {
    extern __shared__ __nv_bfloat16 ASM[];
    const int STG = 4 * 64 * KSTR;

    int tid = threadIdx.x, wid = tid >> 5, lane = tid & 31;
    int bph = blockIdx.y, h = bph & 15, bp = bph >> 4, hkv = h >> 2;
    int qt0 = blockIdx.x << 7;
    int qrow0 = bp * 512 + qt0;
    size_t vbase = (size_t)(bp * 4 + hkv) * 32768;

    // ---- Q tile into smem (stage0 region), then frags to registers ----
    {
        #pragma unroll
        for (int i = 0; i < 8; i++) {
            int half = i >> 2;
            int cc = (i & 3) * 256 + tid;
            int r = cc >> 3, kc = (cc & 7) * 8;
            uint32_t dst = smem_u32(ASM + half * 128 * KSTR + r * KSTR + kc);
            const __nv_bfloat16* src = (half ? g_ql : g_qh) + (size_t)(qrow0 + r) * 1024 + h * 64 + kc;
            CP16(dst, src);
        }
        CP_COMMIT(); CP_WAIT0();
        __syncthreads();
    }
    uint32_t qh[4][4], ql[4][4];
    {
        __nv_bfloat16* Qhi = ASM;
        __nv_bfloat16* Qlo = ASM + 128 * KSTR;
        int row = wid * 16 + (lane & 15);
        #pragma unroll
        for (int ks = 0; ks < 4; ks++) {
            int koff = ks * 16 + ((lane >> 4) << 3);
            LDSM4(qh[ks][0], qh[ks][1], qh[ks][2], qh[ks][3], smem_u32(&Qhi[row * KSTR + koff]));
            LDSM4(ql[ks][0], ql[ks][1], ql[ks][2], ql[ks][3], smem_u32(&Qlo[row * KSTR + koff]));
        }
    }
    __syncthreads();

    auto issue = [&](int it, int s) {
        __nv_bfloat16* stg = ASM + s * STG;
        int kt = it * 64;
        #pragma unroll
        for (int i = 0; i < 8; i++) {
            int arr = i >> 1;
            int cc = (i & 1) * 256 + tid;
            int r = cc >> 3, kc = (cc & 7) * 8;
            uint32_t dst = smem_u32(stg + arr * 64 * KSTR + r * KSTR + kc);
            const __nv_bfloat16* src;
            if (arr == 0)      src = g_kh + (size_t)(bp * 512 + kt + r) * 256 + hkv * 64 + kc;
            else if (arr == 1) src = g_kl + (size_t)(bp * 512 + kt + r) * 256 + hkv * 64 + kc;
            else if (arr == 2) src = g_vth + vbase + (size_t)r * 512 + kt + kc;
            else               src = g_vtl + vbase + (size_t)r * 512 + kt + kc;
            CP16(dst, src);
        }
    };

    float o[8][4];
    #pragma unroll
    for (int nf = 0; nf < 8; nf++)
        #pragma unroll
        for (int c = 0; c < 4; c++) o[nf][c] = 0.f;
    float m0 = -INFINITY, m1 = -INFINITY, l0 = 0.f, l1 = 0.f;

    issue(0, 0);
    CP_COMMIT();

    for (int it = 0; it < 8; it++) {
        CP_WAIT0();
        __syncthreads();
        if (it + 1 < 8) { issue(it + 1, (it + 1) & 1); CP_COMMIT(); }

        __nv_bfloat16* stg = ASM + (it & 1) * STG;
        __nv_bfloat16* Khi = stg;
        __nv_bfloat16* Klo = stg + 64 * KSTR;
        __nv_bfloat16* Vth = stg + 2 * 64 * KSTR;
        __nv_bfloat16* Vtl = stg + 3 * 64 * KSTR;

        float s[8][4];
        #pragma unroll
        for (int nf = 0; nf < 8; nf++)
            #pragma unroll
            for (int c = 0; c < 4; c++) s[nf][c] = 0.f;

        #pragma unroll
        for (int ks = 0; ks < 4; ks++) {
            int koff = ks * 16 + ((lane >> 4) << 3);
            #pragma unroll
            for (int jp = 0; jp < 8; jp += 2) {
                int brow = jp * 8 + (lane & 15);
                uint32_t r0, r1, r2, r3, t0, t1, t2, t3;
                LDSM4(r0, r1, r2, r3, smem_u32(&Khi[brow * KSTR + koff]));
                LDSM4(t0, t1, t2, t3, smem_u32(&Klo[brow * KSTR + koff]));
                MMA16816(s[jp],     qh[ks][0], qh[ks][1], qh[ks][2], qh[ks][3], r0, r2);
                MMA16816(s[jp],     qh[ks][0], qh[ks][1], qh[ks][2], qh[ks][3], t0, t2);
                MMA16816(s[jp],     ql[ks][0], ql[ks][1], ql[ks][2], ql[ks][3], r0, r2);
                MMA16816(s[jp + 1], qh[ks][0], qh[ks][1], qh[ks][2], qh[ks][3], r1, r3);
                MMA16816(s[jp + 1], qh[ks][0], qh[ks][1], qh[ks][2], qh[ks][3], t1, t3);
                MMA16816(s[jp + 1], ql[ks][0], ql[ks][1], ql[ks][2], ql[ks][3], r1, r3);
            }
        }

        // softmax in exp2 domain (log2e folded into Q prescale)
        float rmax0 = -INFINITY, rmax1 = -INFINITY;
        #pragma unroll
        for (int nf = 0; nf < 8; nf++) {
            rmax0 = fmaxf(rmax0, fmaxf(s[nf][0], s[nf][1]));
            rmax1 = fmaxf(rmax1, fmaxf(s[nf][2], s[nf][3]));
        }
        rmax0 = fmaxf(rmax0, __shfl_xor_sync(0xffffffffu, rmax0, 1));
        rmax0 = fmaxf(rmax0, __shfl_xor_sync(0xffffffffu, rmax0, 2));
        rmax1 = fmaxf(rmax1, __shfl_xor_sync(0xffffffffu, rmax1, 1));
        rmax1 = fmaxf(rmax1, __shfl_xor_sync(0xffffffffu, rmax1, 2));
        float mn0 = fmaxf(m0, rmax0), mn1 = fmaxf(m1, rmax1);
        float al0 = exp2f(m0 - mn0), al1 = exp2f(m1 - mn1);
        float ps0 = 0.f, ps1 = 0.f;
        #pragma unroll
        for (int nf = 0; nf < 8; nf++) {
            s[nf][0] = exp2f(s[nf][0] - mn0); ps0 += s[nf][0];
            s[nf][1] = exp2f(s[nf][1] - mn0); ps0 += s[nf][1];
            s[nf][2] = exp2f(s[nf][2] - mn1); ps1 += s[nf][2];
            s[nf][3] = exp2f(s[nf][3] - mn1); ps1 += s[nf][3];
        }
        l0 = l0 * al0 + ps0; l1 = l1 * al1 + ps1;
        m0 = mn0; m1 = mn1;
        #pragma unroll
        for (int nf = 0; nf < 8; nf++) {
            o[nf][0] *= al0; o[nf][1] *= al0;
            o[nf][2] *= al1; o[nf][3] *= al1;
        }

        #pragma unroll
        for (int ks = 0; ks < 4; ks++) {
            float* pa = s[2 * ks];
            float* pb = s[2 * ks + 1];
            float ha0 = __bfloat162float(__float2bfloat16_rn(pa[0]));
            float ha1 = __bfloat162float(__float2bfloat16_rn(pa[1]));
            float ha2 = __bfloat162float(__float2bfloat16_rn(pa[2]));
            float ha3 = __bfloat162float(__float2bfloat16_rn(pa[3]));
            float hb0 = __bfloat162float(__float2bfloat16_rn(pb[0]));
            float hb1 = __bfloat162float(__float2bfloat16_rn(pb[1]));
            float hb2 = __bfloat162float(__float2bfloat16_rn(pb[2]));
            float hb3 = __bfloat162float(__float2bfloat16_rn(pb[3]));
            uint32_t ah0 = pk_bf2(ha0, ha1), ah1 = pk_bf2(ha2, ha3);
            uint32_t ah2 = pk_bf2(hb0, hb1), ah3 = pk_bf2(hb2, hb3);
            uint32_t pl0 = pk_bf2(pa[0] - ha0, pa[1] - ha1);
            uint32_t pl1 = pk_bf2(pa[2] - ha2, pa[3] - ha3);
            uint32_t pl2 = pk_bf2(pb[0] - hb0, pb[1] - hb1);
            uint32_t pl3 = pk_bf2(pb[2] - hb2, pb[3] - hb3);

            int koff = ks * 16 + ((lane >> 4) << 3);
            #pragma unroll
            for (int jp = 0; jp < 8; jp += 2) {
                int brow = jp * 8 + (lane & 15);
                uint32_t r0, r1, r2, r3, t0, t1, t2, t3;
                LDSM4(r0, r1, r2, r3, smem_u32(&Vth[brow * KSTR + koff]));
                LDSM4(t0, t1, t2, t3, smem_u32(&Vtl[brow * KSTR + koff]));
                MMA16816(o[jp],     ah0, ah1, ah2, ah3, r0, r2);
                MMA16816(o[jp],     ah0, ah1, ah2, ah3, t0, t2);
                MMA16816(o[jp],     pl0, pl1, pl2, pl3, r0, r2);
                MMA16816(o[jp + 1], ah0, ah1, ah2, ah3, r1, r3);
                MMA16816(o[jp + 1], ah0, ah1, ah2, ah3, t1, t3);
                MMA16816(o[jp + 1], pl0, pl1, pl2, pl3, r1, r3);
            }
        }
        __syncthreads();   // protect stage (it&1) from issue(it+2) next iter
    }

    l0 += __shfl_xor_sync(0xffffffffu, l0, 1);
    l0 += __shfl_xor_sync(0xffffffffu, l0, 2);
    l1 += __shfl_xor_sync(0xffffffffu, l1, 1);
    l1 += __shfl_xor_sync(0xffffffffu, l1, 2);
    float inv0 = 1.f / l0, inv1 = 1.f / l1;

    int row = qrow0 + wid * 16 + (lane >> 2);
    float* ob0 = g_o + (size_t)row * 1024 + h * 64 + (lane & 3) * 2;
    float* ob1 = ob0 + 8 * 1024;
    #pragma unroll
    for (int nf = 0; nf < 8; nf++) {
        *(float2*)(ob0 + nf * 8) = make_float2(o[nf][0] * inv0, o[nf][1] * inv0);
        *(float2*)(ob1 + nf * 8) = make_float2(o[nf][2] * inv1, o[nf][3] * inv1);
    }
}

// ---------------------------------------------------------------------------
extern "C" void kernel_launch(void* const* d_in, const int* in_sizes, int n_in,
                              void* d_out, int out_size) {
    (void)in_sizes; (void)n_in; (void)out_size;
    const float* hidden = (const float*)d_in[0];
    const float* Wq = (const float*)d_in[1];
    const float* Wk = (const float*)d_in[2];
    const float* Wv = (const float*)d_in[3];
    const float* Wo = (const float*)d_in[4];
    float* out = (float*)d_out;

    float* po;
    cudaGetSymbolAddress((void**)&po, g_o);

    const int gsm = 2 * 4 * 128 * ASTR * 2;   // 81920 B
    const int asm_ = 2 * 4 * 64 * KSTR * 2;   // 73728 B
    cudaFuncSetAttribute(bfgemmQKV_k, cudaFuncAttributeMaxDynamicSharedMemorySize, gsm);
    cudaFuncSetAttribute(bfgemmO_k, cudaFuncAttributeMaxDynamicSharedMemorySize, gsm);
    cudaFuncSetAttribute(attn2_k, cudaFuncAttributeMaxDynamicSharedMemorySize, asm_);

    // 0: convert hidden (remap-gathered) to bf16 hi/lo
    convA_k<1><<<8192, 256>>>(hidden);
    // 1: all three weights transposed+split in one launch
    transsplit3_k<<<dim3(32, 32, 3), dim3(32, 8)>>>(Wq, Wk, Wv);
    // 2: fused QKV projection
    bfgemmQKV_k<<<dim3(12, 64), 256, gsm>>>();
    // 3: rope (+log2e Q prescale) + split
    ropesplit_k<<<(NTOK * 16 * 32 + NTOK * 4 * 32) / 256, 256>>>();
    // 4: V transpose + split
    convV_k<<<dim3(16, 2, 64), dim3(32, 8)>>>();
    // 5: attention  <- ncu -s 5 -c 1 captures THIS
    attn2_k<<<dim3(4, 256), 256, asm_>>>();
    // 6-8: output projection
    convA_k<0><<<8192, 256>>>(po);
    transsplit_k<<<dim3(32, 32), dim3(32, 8)>>>(Wo);
    bfgemmO_k<<<dim3(8, 64), 256, gsm>>>(out);
}

// round 9
// speedup vs baseline: 3.6947x; 1.0513x over previous
#include <cuda_runtime.h>
#include <cuda_bf16.h>
#include <cstdint>
#include <math.h>

#define NTOK 8192

// fp32 intermediates
__device__ float g_q[NTOK * 1024];
__device__ float g_k[NTOK * 256];
__device__ float g_v[NTOK * 256];
__device__ float g_o[NTOK * 1024];
// bf16 hi/lo preconverted operands
__device__ __nv_bfloat16 g_ah[NTOK * 1024], g_al[NTOK * 1024];
__device__ __nv_bfloat16 g_qh[NTOK * 1024], g_ql[NTOK * 1024];
__device__ __nv_bfloat16 g_kh[NTOK * 256],  g_kl[NTOK * 256];
__device__ __nv_bfloat16 g_vth[NTOK * 256], g_vtl[NTOK * 256];
__device__ __nv_bfloat16 g_wth[1536 * 1024], g_wtl[1536 * 1024];

__device__ __forceinline__ int remap_bpt(int r) {
    int b = r >> 12, p = (r >> 9) & 7, t = r & 511;
    return (b << 12) + (t << 3) + p;
}
__device__ __forceinline__ uint32_t smem_u32(const void* p) {
    uint32_t a;
    asm("{ .reg .u64 t; cvta.to.shared.u64 t, %1; cvt.u32.u64 %0, t; }" : "=r"(a) : "l"(p));
    return a;
}
#define LDSM4(r0, r1, r2, r3, a) \
    asm volatile("ldmatrix.sync.aligned.m8n8.x4.shared.b16 {%0,%1,%2,%3}, [%4];" \
        : "=r"(r0), "=r"(r1), "=r"(r2), "=r"(r3) : "r"(a))
#define MMA16816(c, a0, a1, a2, a3, b0, b1) \
    asm volatile("mma.sync.aligned.m16n8k16.row.col.f32.bf16.bf16.f32 " \
        "{%0,%1,%2,%3},{%4,%5,%6,%7},{%8,%9},{%0,%1,%2,%3};" \
        : "+f"((c)[0]), "+f"((c)[1]), "+f"((c)[2]), "+f"((c)[3]) \
        : "r"(a0), "r"(a1), "r"(a2), "r"(a3), "r"(b0), "r"(b1))
#define CP16(dst, src) \
    asm volatile("cp.async.cg.shared.global [%0], [%1], 16;" :: "r"(dst), "l"(src))
#define CP_COMMIT() asm volatile("cp.async.commit_group;" ::: "memory")
#define CP_WAIT0()  asm volatile("cp.async.wait_group 0;" ::: "memory")

__device__ __forceinline__ uint32_t pk_bf2(float x, float y) {
    __nv_bfloat162 h = __floats2bfloat162_rn(x, y);
    return *(uint32_t*)&h;
}
__device__ __forceinline__ void split_store4(float4 v, void* ph, void* pl) {
    float hx = __bfloat162float(__float2bfloat16_rn(v.x));
    float hy = __bfloat162float(__float2bfloat16_rn(v.y));
    float hz = __bfloat162float(__float2bfloat16_rn(v.z));
    float hw = __bfloat162float(__float2bfloat16_rn(v.w));
    *(uint2*)ph = make_uint2(pk_bf2(hx, hy), pk_bf2(hz, hw));
    *(uint2*)pl = make_uint2(pk_bf2(v.x - hx, v.y - hy), pk_bf2(v.z - hz, v.w - hw));
}

// ---------------- shared prep bodies ----------------
template<int REMAP>
__device__ __forceinline__ void convA_body(const float* __restrict__ src, int blk, int tid) {
    int idx = blk * 256 + tid;
    int row = idx >> 8, c4 = (idx & 255) * 4;
    int srow = REMAP ? remap_bpt(row) : row;
    float4 v = *(const float4*)(src + (size_t)srow * 1024 + c4);
    split_store4(v, &g_ah[(size_t)row * 1024 + c4], &g_al[(size_t)row * 1024 + c4]);
}

__device__ __forceinline__ void transsplit_body(const float* __restrict__ in, int N,
                                                int rowoff, int bx, int by, int tid) {
    __shared__ float t[32][33];
    int n0 = bx * 32;
    if (n0 >= N) return;
    int k0 = by * 32, x = tid & 31, y = tid >> 5;
    for (int j = y; j < 32; j += 8)
        t[j][x] = in[(size_t)(k0 + j) * N + n0 + x];
    __syncthreads();
    for (int j = y; j < 32; j += 8) {
        float v = t[x][j];
        float hi = __bfloat162float(__float2bfloat16_rn(v));
        size_t o = (size_t)(rowoff + n0 + j) * 1024 + k0 + x;
        g_wth[o] = __float2bfloat16_rn(hi);
        g_wtl[o] = __float2bfloat16_rn(v - hi);
    }
}

// launch 0: convA(remap, hidden) [blocks 0..8191] + QKV weight transpose [8192..11263]
__global__ void __launch_bounds__(256) prep1_k(const float* __restrict__ hidden,
                                               const float* __restrict__ Wq,
                                               const float* __restrict__ Wk,
                                               const float* __restrict__ Wv) {
    int b = blockIdx.x, tid = threadIdx.x;
    if (b < 8192) { convA_body<1>(hidden, b, tid); return; }
    int idx = b - 8192;           // 0..3071
    int z = idx >> 10, r = idx & 1023;
    const float* in = (z == 0) ? Wq : (z == 1) ? Wk : Wv;
    int N = (z == 0) ? 1024 : 256;
    int rowoff = (z == 0) ? 0 : (z == 1) ? 1024 : 1280;
    transsplit_body(in, N, rowoff, r & 31, r >> 5, tid);
}

// launch 4: convA(no-remap, g_o) [0..8191] + Wo transpose [8192..9215]
__global__ void __launch_bounds__(256) prep3_k(const float* __restrict__ Wo) {
    int b = blockIdx.x, tid = threadIdx.x;
    if (b < 8192) { convA_body<0>(g_o, b, tid); return; }
    int r = b - 8192;             // 0..1023
    transsplit_body(Wo, 1024, 0, r & 31, r >> 5, tid);
}

// launch 2: rope+split [blocks 0..20479] + V transpose+split [20480..22527]
__global__ void __launch_bounds__(256) prep2_k() {
    __shared__ float t[32][33];
    int b = blockIdx.x, tid = threadIdx.x;
    if (b < 20480) {
        int idx = b * 256 + tid;
        const int QP = NTOK * 16 * 32;
        const float* base;
        __nv_bfloat16 *oh, *ol;
        int i, tok;
        float scale;
        if (idx < QP) {
            i = idx & 31;
            int r = idx >> 5;
            tok = r >> 4;
            size_t off = (size_t)tok * 1024 + (r & 15) * 64;
            base = g_q + off; oh = g_qh + off; ol = g_ql + off;
            scale = 0.125f * 1.4426950408889634f;   // fold log2(e)
        } else {
            int j = idx - QP;
            i = j & 31;
            int r = j >> 5;
            tok = r >> 2;
            size_t off = (size_t)tok * 256 + (r & 3) * 64;
            base = g_k + off; oh = g_kh + off; ol = g_kl + off;
            scale = 1.0f;
        }
        int tt = tok & 511;
        float invf = expf(-(float)i * 0.28782313662425574f);
        float ang = (float)tt * invf, s, c;
        sincosf(ang, &s, &c);
        float x1 = base[i], x2 = base[i + 32];
        float y1 = (x1 * c - x2 * s) * scale;
        float y2 = (x1 * s + x2 * c) * scale;
        float h1 = __bfloat162float(__float2bfloat16_rn(y1));
        float h2 = __bfloat162float(__float2bfloat16_rn(y2));
        oh[i]      = __float2bfloat16_rn(h1);
        ol[i]      = __float2bfloat16_rn(y1 - h1);
        oh[i + 32] = __float2bfloat16_rn(h2);
        ol[i + 32] = __float2bfloat16_rn(y2 - h2);
        return;
    }
    // convV: idx 0..2047 maps to (bx<16, by<2, g<64)
    int idx = b - 20480;
    int bx = idx & 15, by = (idx >> 4) & 1, g = idx >> 5;
    int bp = g >> 2, hkv = g & 3;
    int k0 = bx * 32, d0 = by * 32, x = tid & 31, y = tid >> 5;
    for (int j = y; j < 32; j += 8)
        t[j][x] = g_v[(size_t)(bp * 512 + k0 + j) * 256 + hkv * 64 + d0 + x];
    __syncthreads();
    for (int j = y; j < 32; j += 8) {
        float v = t[x][j];
        float hi = __bfloat162float(__float2bfloat16_rn(v));
        size_t o = (size_t)g * 32768 + (size_t)(d0 + j) * 512 + k0 + x;
        g_vth[o] = __float2bfloat16_rn(hi);
        g_vtl[o] = __float2bfloat16_rn(v - hi);
    }
}

// ---------------------------------------------------------------------------
// GEMM core (unchanged from R8)
// ---------------------------------------------------------------------------
#define ASTR 40
struct GemmCore {
    __nv_bfloat16* SM;
    int tid, wid, lane, wm, wn;
    float acc[4][4][4];

    __device__ __forceinline__ void init(__nv_bfloat16* sm, int t) {
        SM = sm; tid = t; wid = t >> 5; lane = t & 31;
        wm = (wid >> 2) * 64; wn = (wid & 3) * 32;
        #pragma unroll
        for (int i = 0; i < 4; i++)
            #pragma unroll
            for (int j = 0; j < 4; j++)
                #pragma unroll
                for (int q = 0; q < 4; q++) acc[i][j][q] = 0.f;
    }
    __device__ __forceinline__ void issue(const __nv_bfloat16* Agh, const __nv_bfloat16* Agl,
                                          const __nv_bfloat16* Bgh, const __nv_bfloat16* Bgl,
                                          int am0, int bn0, int k0, int s) {
        __nv_bfloat16* stg = SM + s * (4 * 128 * ASTR);
        #pragma unroll
        for (int i = 0; i < 8; i++) {
            int arr = i >> 1;
            int cc = (i & 1) * 256 + tid;
            int r = cc >> 2, kc = (cc & 3) * 8;
            uint32_t dst = smem_u32(stg + arr * 128 * ASTR + r * ASTR + kc);
            const __nv_bfloat16* src;
            if (arr == 0)      src = Agh + (size_t)(am0 + r) * 1024 + k0 + kc;
            else if (arr == 1) src = Agl + (size_t)(am0 + r) * 1024 + k0 + kc;
            else if (arr == 2) src = Bgh + (size_t)(bn0 + r) * 1024 + k0 + kc;
            else               src = Bgl + (size_t)(bn0 + r) * 1024 + k0 + kc;
            CP16(dst, src);
        }
    }
    __device__ __forceinline__ void compute(int s) {
        __nv_bfloat16* stg = SM + s * (4 * 128 * ASTR);
        __nv_bfloat16* sAh = stg;
        __nv_bfloat16* sAl = stg + 128 * ASTR;
        __nv_bfloat16* sBh = stg + 2 * 128 * ASTR;
        __nv_bfloat16* sBl = stg + 3 * 128 * ASTR;
        #pragma unroll
        for (int ks = 0; ks < 2; ks++) {
            int koff = ks * 16 + ((lane >> 4) << 3);
            int arow = wm + (lane & 15);
            uint32_t ah[4][4], al[4][4];
            #pragma unroll
            for (int mf = 0; mf < 4; mf++) {
                LDSM4(ah[mf][0], ah[mf][1], ah[mf][2], ah[mf][3], smem_u32(&sAh[(arow + mf * 16) * ASTR + koff]));
                LDSM4(al[mf][0], al[mf][1], al[mf][2], al[mf][3], smem_u32(&sAl[(arow + mf * 16) * ASTR + koff]));
            }
            uint32_t bh[4][2], bl[4][2];
            #pragma unroll
            for (int jp = 0; jp < 4; jp += 2) {
                int brow = wn + jp * 8 + (lane & 15);
                uint32_t r0, r1, r2, r3;
                LDSM4(r0, r1, r2, r3, smem_u32(&sBh[brow * ASTR + koff]));
                bh[jp][0] = r0; bh[jp + 1][0] = r1; bh[jp][1] = r2; bh[jp + 1][1] = r3;
                LDSM4(r0, r1, r2, r3, smem_u32(&sBl[brow * ASTR + koff]));
                bl[jp][0] = r0; bl[jp + 1][0] = r1; bl[jp][1] = r2; bl[jp + 1][1] = r3;
            }
            #pragma unroll
            for (int mf = 0; mf < 4; mf++)
                #pragma unroll
                for (int nf = 0; nf < 4; nf++) {
                    MMA16816(acc[mf][nf], ah[mf][0], ah[mf][1], ah[mf][2], ah[mf][3], bh[nf][0], bh[nf][1]);
                    MMA16816(acc[mf][nf], ah[mf][0], ah[mf][1], ah[mf][2], ah[mf][3], bl[nf][0], bl[nf][1]);
                    MMA16816(acc[mf][nf], al[mf][0], al[mf][1], al[mf][2], al[mf][3], bh[nf][0], bh[nf][1]);
                }
        }
    }
};

__global__ void __launch_bounds__(256) bfgemmQKV_k() {
    extern __shared__ __nv_bfloat16 SM[];
    GemmCore g;
    g.init(SM, threadIdx.x);
    int bm = blockIdx.y, bn = blockIdx.x;
    int am0 = bm * 128, bn0 = bn * 128;

    g.issue(g_ah, g_al, g_wth, g_wtl, am0, bn0, 0, 0);
    CP_COMMIT();
    for (int it = 0; it < 32; it++) {
        CP_WAIT0();
        __syncthreads();
        if (it + 1 < 32) { g.issue(g_ah, g_al, g_wth, g_wtl, am0, bn0, (it + 1) * 32, (it + 1) & 1); CP_COMMIT(); }
        g.compute(it & 1);
    }

    float* C; int Ntot, colb;
    if (bn < 8)       { C = g_q; Ntot = 1024; colb = bn * 128; }
    else if (bn < 10) { C = g_k; Ntot = 256;  colb = (bn - 8) * 128; }
    else              { C = g_v; Ntot = 256;  colb = (bn - 10) * 128; }
    #pragma unroll
    for (int mf = 0; mf < 4; mf++) {
        int r0 = am0 + g.wm + mf * 16 + (g.lane >> 2);
        int r1 = r0 + 8;
        #pragma unroll
        for (int nf = 0; nf < 4; nf++) {
            int col = colb + g.wn + nf * 8 + (g.lane & 3) * 2;
            *(float2*)(C + (size_t)r0 * Ntot + col) = make_float2(g.acc[mf][nf][0], g.acc[mf][nf][1]);
            *(float2*)(C + (size_t)r1 * Ntot + col) = make_float2(g.acc[mf][nf][2], g.acc[mf][nf][3]);
        }
    }
}

__global__ void __launch_bounds__(256) bfgemmO_k(float* __restrict__ C) {
    extern __shared__ __nv_bfloat16 SM[];
    GemmCore g;
    g.init(SM, threadIdx.x);
    int bm = blockIdx.y, bn = blockIdx.x;
    int am0 = bm * 128, bn0 = bn * 128;

    g.issue(g_ah, g_al, g_wth, g_wtl, am0, bn0, 0, 0);
    CP_COMMIT();
    for (int it = 0; it < 32; it++) {
        CP_WAIT0();
        __syncthreads();
        if (it + 1 < 32) { g.issue(g_ah, g_al, g_wth, g_wtl, am0, bn0, (it + 1) * 32, (it + 1) & 1); CP_COMMIT(); }
        g.compute(it & 1);
    }
    #pragma unroll
    for (int mf = 0; mf < 4; mf++) {
        int r0 = remap_bpt(am0 + g.wm + mf * 16 + (g.lane >> 2));
        int r1 = remap_bpt(am0 + g.wm + mf * 16 + (g.lane >> 2) + 8);
        #pragma unroll
        for (int nf = 0; nf < 4; nf++) {
            int col = bn0 + g.wn + nf * 8 + (g.lane & 3) * 2;
            *(float2*)(C + (size_t)r0 * 1024 + col) = make_float2(g.acc[mf][nf][0], g.acc[mf][nf][1]);
            *(float2*)(C + (size_t)r1 * 1024 + col) = make_float2(g.acc[mf][nf][2], g.acc[mf][nf][3]);
        }
    }
}

// ---------------------------------------------------------------------------
// Flash attention: 64-q-row CTAs, 4 warps, 3 CTAs/SM target.
// Per-warp work identical to R8 (16 q rows x full 64-k width).
// ---------------------------------------------------------------------------
#define KSTR 72
__global__ void __launch_bounds__(128, 3) attn3_k() {
    extern __shared__ __nv_bfloat16 ASM[];
    const int STG = 4 * 64 * KSTR;   // 18432 elems per stage

    int tid = threadIdx.x, wid = tid >> 5, lane = tid & 31;
    int bph = blockIdx.y, h = bph & 15, bp = bph >> 4, hkv = h >> 2;
    int qt0 = blockIdx.x << 6;
    int qrow0 = bp * 512 + qt0;
    size_t vbase = (size_t)(bp * 4 + hkv) * 32768;

    // ---- Q tile (64 rows) into stage0 region, then frags to registers ----
    {
        #pragma unroll
        for (int i = 0; i < 8; i++) {
            int half = i >> 2;
            int cc = (i & 3) * 128 + tid;            // 0..511
            int r = cc >> 3, kc = (cc & 7) * 8;
            uint32_t dst = smem_u32(ASM + half * 64 * KSTR + r * KSTR + kc);
            const __nv_bfloat16* src = (half ? g_ql : g_qh) + (size_t)(qrow0 + r) * 1024 + h * 64 + kc;
            CP16(dst, src);
        }
        CP_COMMIT(); CP_WAIT0();
        __syncthreads();
    }
    uint32_t qh[4][4], ql[4][4];
    {
        __nv_bfloat16* Qhi = ASM;
        __nv_bfloat16* Qlo = ASM + 64 * KSTR;
        int row = wid * 16 + (lane & 15);
        #pragma unroll
        for (int ks = 0; ks < 4; ks++) {
            int koff = ks * 16 + ((lane >> 4) << 3);
            LDSM4(qh[ks][0], qh[ks][1], qh[ks][2], qh[ks][3], smem_u32(&Qhi[row * KSTR + koff]));
            LDSM4(ql[ks][0], ql[ks][1], ql[ks][2], ql[ks][3], smem_u32(&Qlo[row * KSTR + koff]));
        }
    }
    __syncthreads();

    auto issue = [&](int it, int s) {
        __nv_bfloat16* stg = ASM + s * STG;
        int kt = it * 64;
        #pragma unroll
        for (int i = 0; i < 16; i++) {
            int arr = i >> 2;
            int cc = (i & 3) * 128 + tid;            // 0..511
            int r = cc >> 3, kc = (cc & 7) * 8;
            uint32_t dst = smem_u32(stg + arr * 64 * KSTR + r * KSTR + kc);
            const __nv_bfloat16* src;
            if (arr == 0)      src = g_kh + (size_t)(bp * 512 + kt + r) * 256 + hkv * 64 + kc;
            else if (arr == 1) src = g_kl + (size_t)(bp * 512 + kt + r) * 256 + hkv * 64 + kc;
            else if (arr == 2) src = g_vth + vbase + (size_t)r * 512 + kt + kc;
            else               src = g_vtl + vbase + (size_t)r * 512 + kt + kc;
            CP16(dst, src);
        }
    };

    float o[8][4];
    #pragma unroll
    for (int nf = 0; nf < 8; nf++)
        #pragma unroll
        for (int c = 0; c < 4; c++) o[nf][c] = 0.f;
    float m0 = -INFINITY, m1 = -INFINITY, l0 = 0.f, l1 = 0.f;

    issue(0, 0);
    CP_COMMIT();

    for (int it = 0; it < 8; it++) {
        CP_WAIT0();
        __syncthreads();
        if (it + 1 < 8) { issue(it + 1, (it + 1) & 1); CP_COMMIT(); }

        __nv_bfloat16* stg = ASM + (it & 1) * STG;
        __nv_bfloat16* Khi = stg;
        __nv_bfloat16* Klo = stg + 64 * KSTR;
        __nv_bfloat16* Vth = stg + 2 * 64 * KSTR;
        __nv_bfloat16* Vtl = stg + 3 * 64 * KSTR;

        float s[8][4];
        #pragma unroll
        for (int nf = 0; nf < 8; nf++)
            #pragma unroll
            for (int c = 0; c < 4; c++) s[nf][c] = 0.f;

        #pragma unroll
        for (int ks = 0; ks < 4; ks++) {
            int koff = ks * 16 + ((lane >> 4) << 3);
            #pragma unroll
            for (int jp = 0; jp < 8; jp += 2) {
                int brow = jp * 8 + (lane & 15);
                uint32_t r0, r1, r2, r3, t0, t1, t2, t3;
                LDSM4(r0, r1, r2, r3, smem_u32(&Khi[brow * KSTR + koff]));
                LDSM4(t0, t1, t2, t3, smem_u32(&Klo[brow * KSTR + koff]));
                MMA16816(s[jp],     qh[ks][0], qh[ks][1], qh[ks][2], qh[ks][3], r0, r2);
                MMA16816(s[jp],     qh[ks][0], qh[ks][1], qh[ks][2], qh[ks][3], t0, t2);
                MMA16816(s[jp],     ql[ks][0], ql[ks][1], ql[ks][2], ql[ks][3], r0, r2);
                MMA16816(s[jp + 1], qh[ks][0], qh[ks][1], qh[ks][2], qh[ks][3], r1, r3);
                MMA16816(s[jp + 1], qh[ks][0], qh[ks][1], qh[ks][2], qh[ks][3], t1, t3);
                MMA16816(s[jp + 1], ql[ks][0], ql[ks][1], ql[ks][2], ql[ks][3], r1, r3);
            }
        }

        float rmax0 = -INFINITY, rmax1 = -INFINITY;
        #pragma unroll
        for (int nf = 0; nf < 8; nf++) {
            rmax0 = fmaxf(rmax0, fmaxf(s[nf][0], s[nf][1]));
            rmax1 = fmaxf(rmax1, fmaxf(s[nf][2], s[nf][3]));
        }
        rmax0 = fmaxf(rmax0, __shfl_xor_sync(0xffffffffu, rmax0, 1));
        rmax0 = fmaxf(rmax0, __shfl_xor_sync(0xffffffffu, rmax0, 2));
        rmax1 = fmaxf(rmax1, __shfl_xor_sync(0xffffffffu, rmax1, 1));
        rmax1 = fmaxf(rmax1, __shfl_xor_sync(0xffffffffu, rmax1, 2));
        float mn0 = fmaxf(m0, rmax0), mn1 = fmaxf(m1, rmax1);
        float al0 = exp2f(m0 - mn0), al1 = exp2f(m1 - mn1);
        float ps0 = 0.f, ps1 = 0.f;
        #pragma unroll
        for (int nf = 0; nf < 8; nf++) {
            s[nf][0] = exp2f(s[nf][0] - mn0); ps0 += s[nf][0];
            s[nf][1] = exp2f(s[nf][1] - mn0); ps0 += s[nf][1];
            s[nf][2] = exp2f(s[nf][2] - mn1); ps1 += s[nf][2];
            s[nf][3] = exp2f(s[nf][3] - mn1); ps1 += s[nf][3];
        }
        l0 = l0 * al0 + ps0; l1 = l1 * al1 + ps1;
        m0 = mn0; m1 = mn1;
        #pragma unroll
        for (int nf = 0; nf < 8; nf++) {
            o[nf][0] *= al0; o[nf][1] *= al0;
            o[nf][2] *= al1; o[nf][3] *= al1;
        }

        #pragma unroll
        for (int ks = 0; ks < 4; ks++) {
            float* pa = s[2 * ks];
            float* pb = s[2 * ks + 1];
            float ha0 = __bfloat162float(__float2bfloat16_rn(pa[0]));
            float ha1 = __bfloat162float(__float2bfloat16_rn(pa[1]));
            float ha2 = __bfloat162float(__float2bfloat16_rn(pa[2]));
            float ha3 = __bfloat162float(__float2bfloat16_rn(pa[3]));
            float hb0 = __bfloat162float(__float2bfloat16_rn(pb[0]));
            float hb1 = __bfloat162float(__float2bfloat16_rn(pb[1]));
            float hb2 = __bfloat162float(__float2bfloat16_rn(pb[2]));
            float hb3 = __bfloat162float(__float2bfloat16_rn(pb[3]));
            uint32_t ah0 = pk_bf2(ha0, ha1), ah1 = pk_bf2(ha2, ha3);
            uint32_t ah2 = pk_bf2(hb0, hb1), ah3 = pk_bf2(hb2, hb3);
            uint32_t pl0 = pk_bf2(pa[0] - ha0, pa[1] - ha1);
            uint32_t pl1 = pk_bf2(pa[2] - ha2, pa[3] - ha3);
            uint32_t pl2 = pk_bf2(pb[0] - hb0, pb[1] - hb1);
            uint32_t pl3 = pk_bf2(pb[2] - hb2, pb[3] - hb3);

            int koff = ks * 16 + ((lane >> 4) << 3);
            #pragma unroll
            for (int jp = 0; jp < 8; jp += 2) {
                int brow = jp * 8 + (lane & 15);
                uint32_t r0, r1, r2, r3, t0, t1, t2, t3;
                LDSM4(r0, r1, r2, r3, smem_u32(&Vth[brow * KSTR + koff]));
                LDSM4(t0, t1, t2, t3, smem_u32(&Vtl[brow * KSTR + koff]));
                MMA16816(o[jp],     ah0, ah1, ah2, ah3, r0, r2);
                MMA16816(o[jp],     ah0, ah1, ah2, ah3, t0, t2);
                MMA16816(o[jp],     pl0, pl1, pl2, pl3, r0, r2);
                MMA16816(o[jp + 1], ah0, ah1, ah2, ah3, r1, r3);
                MMA16816(o[jp + 1], ah0, ah1, ah2, ah3, t1, t3);
                MMA16816(o[jp + 1], pl0, pl1, pl2, pl3, r1, r3);
            }
        }
        __syncthreads();
    }

    l0 += __shfl_xor_sync(0xffffffffu, l0, 1);
    l0 += __shfl_xor_sync(0xffffffffu, l0, 2);
    l1 += __shfl_xor_sync(0xffffffffu, l1, 1);
    l1 += __shfl_xor_sync(0xffffffffu, l1, 2);
    float inv0 = 1.f / l0, inv1 = 1.f / l1;

    int row = qrow0 + wid * 16 + (lane >> 2);
    float* ob0 = g_o + (size_t)row * 1024 + h * 64 + (lane & 3) * 2;
    float* ob1 = ob0 + 8 * 1024;
    #pragma unroll
    for (int nf = 0; nf < 8; nf++) {
        *(float2*)(ob0 + nf * 8) = make_float2(o[nf][0] * inv0, o[nf][1] * inv0);
        *(float2*)(ob1 + nf * 8) = make_float2(o[nf][2] * inv1, o[nf][3] * inv1);
    }
}

// ---------------------------------------------------------------------------
extern "C" void kernel_launch(void* const* d_in, const int* in_sizes, int n_in,
                              void* d_out, int out_size) {
    (void)in_sizes; (void)n_in; (void)out_size;
    const float* hidden = (const float*)d_in[0];
    const float* Wq = (const float*)d_in[1];
    const float* Wk = (const float*)d_in[2];
    const float* Wv = (const float*)d_in[3];
    const float* Wo = (const float*)d_in[4];
    float* out = (float*)d_out;

    const int gsm = 2 * 4 * 128 * ASTR * 2;   // 81920 B
    const int asm_ = 2 * 4 * 64 * KSTR * 2;   // 73728 B
    cudaFuncSetAttribute(bfgemmQKV_k, cudaFuncAttributeMaxDynamicSharedMemorySize, gsm);
    cudaFuncSetAttribute(bfgemmO_k, cudaFuncAttributeMaxDynamicSharedMemorySize, gsm);
    cudaFuncSetAttribute(attn3_k, cudaFuncAttributeMaxDynamicSharedMemorySize, asm_);

    // 0: convA(hidden, remap) + QKV weight transpose+split
    prep1_k<<<11264, 256>>>(hidden, Wq, Wk, Wv);
    // 1: fused QKV projection
    bfgemmQKV_k<<<dim3(12, 64), 256, gsm>>>();
    // 2: rope+split + V transpose+split
    prep2_k<<<22528, 256>>>();
    // 3: attention  <- capture slot
    attn3_k<<<dim3(8, 256), 128, asm_>>>();
    // 4: convA(g_o) + Wo transpose+split
    prep3_k<<<9216, 256>>>(Wo);
    // 5: output projection
    bfgemmO_k<<<dim3(8, 64), 256, gsm>>>(out);
}

// round 10
// speedup vs baseline: 4.0453x; 1.0949x over previous
#include <cuda_runtime.h>
#include <cuda_bf16.h>
#include <cstdint>
#include <math.h>

#define NTOK 8192

// fp32 intermediates
__device__ float g_q[NTOK * 1024];
__device__ float g_k[NTOK * 256];
__device__ float g_v[NTOK * 256];
__device__ float g_o[NTOK * 1024];
// bf16 hi/lo preconverted operands
__device__ __nv_bfloat16 g_ah[NTOK * 1024], g_al[NTOK * 1024];
__device__ __nv_bfloat16 g_qh[NTOK * 1024], g_ql[NTOK * 1024];
__device__ __nv_bfloat16 g_kh[NTOK * 256],  g_kl[NTOK * 256];
__device__ __nv_bfloat16 g_vth[NTOK * 256], g_vtl[NTOK * 256];
__device__ __nv_bfloat16 g_wth[1536 * 1024], g_wtl[1536 * 1024];

__device__ __forceinline__ int remap_bpt(int r) {
    int b = r >> 12, p = (r >> 9) & 7, t = r & 511;
    return (b << 12) + (t << 3) + p;
}
__device__ __forceinline__ uint32_t smem_u32(const void* p) {
    uint32_t a;
    asm("{ .reg .u64 t; cvta.to.shared.u64 t, %1; cvt.u32.u64 %0, t; }" : "=r"(a) : "l"(p));
    return a;
}
#define LDSM4(r0, r1, r2, r3, a) \
    asm volatile("ldmatrix.sync.aligned.m8n8.x4.shared.b16 {%0,%1,%2,%3}, [%4];" \
        : "=r"(r0), "=r"(r1), "=r"(r2), "=r"(r3) : "r"(a))
#define MMA16816(c, a0, a1, a2, a3, b0, b1) \
    asm volatile("mma.sync.aligned.m16n8k16.row.col.f32.bf16.bf16.f32 " \
        "{%0,%1,%2,%3},{%4,%5,%6,%7},{%8,%9},{%0,%1,%2,%3};" \
        : "+f"((c)[0]), "+f"((c)[1]), "+f"((c)[2]), "+f"((c)[3]) \
        : "r"(a0), "r"(a1), "r"(a2), "r"(a3), "r"(b0), "r"(b1))
#define CP16(dst, src) \
    asm volatile("cp.async.cg.shared.global [%0], [%1], 16;" :: "r"(dst), "l"(src))
#define CP_COMMIT() asm volatile("cp.async.commit_group;" ::: "memory")
#define CP_WAIT1()  asm volatile("cp.async.wait_group 1;" ::: "memory")
#define CP_WAIT0()  asm volatile("cp.async.wait_group 0;" ::: "memory")

__device__ __forceinline__ uint32_t pk_bf2(float x, float y) {
    __nv_bfloat162 h = __floats2bfloat162_rn(x, y);
    return *(uint32_t*)&h;
}
__device__ __forceinline__ void split_store4(float4 v, void* ph, void* pl) {
    float hx = __bfloat162float(__float2bfloat16_rn(v.x));
    float hy = __bfloat162float(__float2bfloat16_rn(v.y));
    float hz = __bfloat162float(__float2bfloat16_rn(v.z));
    float hw = __bfloat162float(__float2bfloat16_rn(v.w));
    *(uint2*)ph = make_uint2(pk_bf2(hx, hy), pk_bf2(hz, hw));
    *(uint2*)pl = make_uint2(pk_bf2(v.x - hx, v.y - hy), pk_bf2(v.z - hz, v.w - hw));
}

// ---------------- prep bodies ----------------
template<int REMAP>
__device__ __forceinline__ void convA_body(const float* __restrict__ src, int blk, int tid) {
    int idx = blk * 256 + tid;
    int row = idx >> 8, c4 = (idx & 255) * 4;
    int srow = REMAP ? remap_bpt(row) : row;
    float4 v = *(const float4*)(src + (size_t)srow * 1024 + c4);
    split_store4(v, &g_ah[(size_t)row * 1024 + c4], &g_al[(size_t)row * 1024 + c4]);
}

__device__ __forceinline__ void transsplit_body(const float* __restrict__ in, int N,
                                                int rowoff, int bx, int by, int tid) {
    __shared__ float t[32][33];
    int n0 = bx * 32;
    if (n0 >= N) return;
    int k0 = by * 32, x = tid & 31, y = tid >> 5;
    for (int j = y; j < 32; j += 8)
        t[j][x] = in[(size_t)(k0 + j) * N + n0 + x];
    __syncthreads();
    for (int j = y; j < 32; j += 8) {
        float v = t[x][j];
        float hi = __bfloat162float(__float2bfloat16_rn(v));
        size_t o = (size_t)(rowoff + n0 + j) * 1024 + k0 + x;
        g_wth[o] = __float2bfloat16_rn(hi);
        g_wtl[o] = __float2bfloat16_rn(v - hi);
    }
}

// launch 0: convert hidden (remap-gathered)
__global__ void __launch_bounds__(256) convAin_k(const float* __restrict__ hidden) {
    convA_body<1>(hidden, blockIdx.x, threadIdx.x);
}
// launch 1: Wq transpose+split (rows 0..1023)
__global__ void __launch_bounds__(256) transWq_k(const float* __restrict__ Wq) {
    int r = blockIdx.x;
    transsplit_body(Wq, 1024, 0, r & 31, r >> 5, threadIdx.x);
}
// launch 2: Wk (rows 1024..1279) + Wv (rows 1280..1535)
__global__ void __launch_bounds__(256) transWkv_k(const float* __restrict__ Wk,
                                                  const float* __restrict__ Wv) {
    int b = blockIdx.x;                   // 0..2047
    int z = b >> 10, r = b & 1023;
    transsplit_body(z ? Wv : Wk, 256, z ? 1280 : 1024, r & 31, r >> 5, threadIdx.x);
}
// launch 6: convA(g_o) [0..8191] + Wo transpose [8192..9215]
__global__ void __launch_bounds__(256) prep3_k(const float* __restrict__ Wo) {
    int b = blockIdx.x, tid = threadIdx.x;
    if (b < 8192) { convA_body<0>(g_o, b, tid); return; }
    int r = b - 8192;
    transsplit_body(Wo, 1024, 0, r & 31, r >> 5, tid);
}
// launch 4: rope+split + V transpose+split
__global__ void __launch_bounds__(256) prep2_k() {
    __shared__ float t[32][33];
    int b = blockIdx.x, tid = threadIdx.x;
    if (b < 20480) {
        int idx = b * 256 + tid;
        const int QP = NTOK * 16 * 32;
        const float* base;
        __nv_bfloat16 *oh, *ol;
        int i, tok;
        float scale;
        if (idx < QP) {
            i = idx & 31;
            int r = idx >> 5;
            tok = r >> 4;
            size_t off = (size_t)tok * 1024 + (r & 15) * 64;
            base = g_q + off; oh = g_qh + off; ol = g_ql + off;
            scale = 0.125f * 1.4426950408889634f;   // fold log2(e)
        } else {
            int j = idx - QP;
            i = j & 31;
            int r = j >> 5;
            tok = r >> 2;
            size_t off = (size_t)tok * 256 + (r & 3) * 64;
            base = g_k + off; oh = g_kh + off; ol = g_kl + off;
            scale = 1.0f;
        }
        int tt = tok & 511;
        float invf = expf(-(float)i * 0.28782313662425574f);
        float ang = (float)tt * invf, s, c;
        sincosf(ang, &s, &c);
        float x1 = base[i], x2 = base[i + 32];
        float y1 = (x1 * c - x2 * s) * scale;
        float y2 = (x1 * s + x2 * c) * scale;
        float h1 = __bfloat162float(__float2bfloat16_rn(y1));
        float h2 = __bfloat162float(__float2bfloat16_rn(y2));
        oh[i]      = __float2bfloat16_rn(h1);
        ol[i]      = __float2bfloat16_rn(y1 - h1);
        oh[i + 32] = __float2bfloat16_rn(h2);
        ol[i + 32] = __float2bfloat16_rn(y2 - h2);
        return;
    }
    int idx = b - 20480;
    int bx = idx & 15, by = (idx >> 4) & 1, g = idx >> 5;
    int bp = g >> 2, hkv = g & 3;
    int k0 = bx * 32, d0 = by * 32, x = tid & 31, y = tid >> 5;
    for (int j = y; j < 32; j += 8)
        t[j][x] = g_v[(size_t)(bp * 512 + k0 + j) * 256 + hkv * 64 + d0 + x];
    __syncthreads();
    for (int j = y; j < 32; j += 8) {
        float v = t[x][j];
        float hi = __bfloat162float(__float2bfloat16_rn(v));
        size_t o = (size_t)g * 32768 + (size_t)(d0 + j) * 512 + k0 + x;
        g_vth[o] = __float2bfloat16_rn(hi);
        g_vtl[o] = __float2bfloat16_rn(v - hi);
    }
}

// ---------------------------------------------------------------------------
// GEMM core: 3-stage cp.async pipeline, XOR-swizzled smem (64B rows, no pad).
// Stage = 4 arrays x 128 rows x 32 bf16 = 32KB; 3 stages = 96KB.
// Swizzle: phys = row*32 + ((chunk ^ ((row>>1)&3)) << 3)  [elements, chunk=16B]
// -> 8 rows of one chunk map to 8 distinct 16B slots mod 128B (ldmatrix clean).
// ---------------------------------------------------------------------------
#define SARR 4096    // elems per array per stage (128*32)
#define SSTG 16384   // elems per stage

struct GemmCore {
    uint32_t smbase;   // smem byte address of SM[0]
    int tid, wid, lane, wm, wn;
    float acc[4][4][4];

    __device__ __forceinline__ void init(const __nv_bfloat16* sm, int t) {
        smbase = smem_u32(sm);
        tid = t; wid = t >> 5; lane = t & 31;
        wm = (wid >> 2) * 64; wn = (wid & 3) * 32;
        #pragma unroll
        for (int i = 0; i < 4; i++)
            #pragma unroll
            for (int j = 0; j < 4; j++)
                #pragma unroll
                for (int q = 0; q < 4; q++) acc[i][j][q] = 0.f;
    }
    __device__ __forceinline__ static uint32_t swz(int row, int chunk) {
        return (uint32_t)(row * 32 + ((chunk ^ ((row >> 1) & 3)) << 3));
    }
    __device__ __forceinline__ void issue(const __nv_bfloat16* Agh, const __nv_bfloat16* Agl,
                                          const __nv_bfloat16* Bgh, const __nv_bfloat16* Bgl,
                                          int am0, int bn0, int k0, int s) {
        uint32_t stg = smbase + (uint32_t)s * SSTG * 2;
        #pragma unroll
        for (int i = 0; i < 8; i++) {
            int arr = i >> 1;
            int cc = (i & 1) * 256 + tid;      // 0..511
            int r = cc >> 2, ch = cc & 3;      // row, 16B chunk
            uint32_t dst = stg + (arr * SARR + swz(r, ch)) * 2;
            const __nv_bfloat16* src;
            if (arr == 0)      src = Agh + (size_t)(am0 + r) * 1024 + k0 + ch * 8;
            else if (arr == 1) src = Agl + (size_t)(am0 + r) * 1024 + k0 + ch * 8;
            else if (arr == 2) src = Bgh + (size_t)(bn0 + r) * 1024 + k0 + ch * 8;
            else               src = Bgl + (size_t)(bn0 + r) * 1024 + k0 + ch * 8;
            CP16(dst, src);
        }
    }
    __device__ __forceinline__ void compute(int s) {
        uint32_t stg = smbase + (uint32_t)s * SSTG * 2;
        #pragma unroll
        for (int ks = 0; ks < 2; ks++) {
            int koff = ks * 16 + ((lane >> 4) << 3);
            int chunk = koff >> 3;
            int arow = wm + (lane & 15);
            uint32_t ah[4][4], al[4][4];
            #pragma unroll
            for (int mf = 0; mf < 4; mf++) {
                int row = arow + mf * 16;
                uint32_t off = swz(row, chunk) * 2;
                LDSM4(ah[mf][0], ah[mf][1], ah[mf][2], ah[mf][3], stg + 0 * SARR * 2 + off);
                LDSM4(al[mf][0], al[mf][1], al[mf][2], al[mf][3], stg + 1 * SARR * 2 + off);
            }
            uint32_t bh[4][2], bl[4][2];
            #pragma unroll
            for (int jp = 0; jp < 4; jp += 2) {
                int brow = wn + jp * 8 + (lane & 15);
                uint32_t off = swz(brow, chunk) * 2;
                uint32_t r0, r1, r2, r3;
                LDSM4(r0, r1, r2, r3, stg + 2 * SARR * 2 + off);
                bh[jp][0] = r0; bh[jp + 1][0] = r1; bh[jp][1] = r2; bh[jp + 1][1] = r3;
                LDSM4(r0, r1, r2, r3, stg + 3 * SARR * 2 + off);
                bl[jp][0] = r0; bl[jp + 1][0] = r1; bl[jp][1] = r2; bl[jp + 1][1] = r3;
            }
            #pragma unroll
            for (int mf = 0; mf < 4; mf++)
                #pragma unroll
                for (int nf = 0; nf < 4; nf++) {
                    MMA16816(acc[mf][nf], ah[mf][0], ah[mf][1], ah[mf][2], ah[mf][3], bh[nf][0], bh[nf][1]);
                    MMA16816(acc[mf][nf], ah[mf][0], ah[mf][1], ah[mf][2], ah[mf][3], bl[nf][0], bl[nf][1]);
                    MMA16816(acc[mf][nf], al[mf][0], al[mf][1], al[mf][2], al[mf][3], bh[nf][0], bh[nf][1]);
                }
        }
    }
    // 3-stage main loop over K=1024 (32 iters of BK=32)
    __device__ __forceinline__ void run(const __nv_bfloat16* Agh, const __nv_bfloat16* Agl,
                                        const __nv_bfloat16* Bgh, const __nv_bfloat16* Bgl,
                                        int am0, int bn0) {
        issue(Agh, Agl, Bgh, Bgl, am0, bn0, 0, 0);  CP_COMMIT();
        issue(Agh, Agl, Bgh, Bgl, am0, bn0, 32, 1); CP_COMMIT();
        int s = 0, sn = 2;
        for (int it = 0; it < 32; it++) {
            if (it < 31) { CP_WAIT1(); } else { CP_WAIT0(); }
            __syncthreads();
            if (it + 2 < 32) {
                issue(Agh, Agl, Bgh, Bgl, am0, bn0, (it + 2) * 32, sn);
                CP_COMMIT();
            }
            compute(s);
            s = (s == 2) ? 0 : s + 1;
            sn = (sn == 2) ? 0 : sn + 1;
        }
    }
};

__global__ void __launch_bounds__(256) bfgemmQKV_k() {
    extern __shared__ __nv_bfloat16 SM[];
    GemmCore g;
    g.init(SM, threadIdx.x);
    int bm = blockIdx.y, bn = blockIdx.x;
    g.run(g_ah, g_al, g_wth, g_wtl, bm * 128, bn * 128);

    float* C; int Ntot, colb;
    if (bn < 8)       { C = g_q; Ntot = 1024; colb = bn * 128; }
    else if (bn < 10) { C = g_k; Ntot = 256;  colb = (bn - 8) * 128; }
    else              { C = g_v; Ntot = 256;  colb = (bn - 10) * 128; }
    #pragma unroll
    for (int mf = 0; mf < 4; mf++) {
        int r0 = bm * 128 + g.wm + mf * 16 + (g.lane >> 2);
        int r1 = r0 + 8;
        #pragma unroll
        for (int nf = 0; nf < 4; nf++) {
            int col = colb + g.wn + nf * 8 + (g.lane & 3) * 2;
            *(float2*)(C + (size_t)r0 * Ntot + col) = make_float2(g.acc[mf][nf][0], g.acc[mf][nf][1]);
            *(float2*)(C + (size_t)r1 * Ntot + col) = make_float2(g.acc[mf][nf][2], g.acc[mf][nf][3]);
        }
    }
}

__global__ void __launch_bounds__(256) bfgemmO_k(float* __restrict__ C) {
    extern __shared__ __nv_bfloat16 SM[];
    GemmCore g;
    g.init(SM, threadIdx.x);
    int bm = blockIdx.y, bn = blockIdx.x;
    g.run(g_ah, g_al, g_wth, g_wtl, bm * 128, bn * 128);
    #pragma unroll
    for (int mf = 0; mf < 4; mf++) {
        int r0 = remap_bpt(bm * 128 + g.wm + mf * 16 + (g.lane >> 2));
        int r1 = remap_bpt(bm * 128 + g.wm + mf * 16 + (g.lane >> 2) + 8);
        #pragma unroll
        for (int nf = 0; nf < 4; nf++) {
            int col = bn * 128 + g.wn + nf * 8 + (g.lane & 3) * 2;
            *(float2*)(C + (size_t)r0 * 1024 + col) = make_float2(g.acc[mf][nf][0], g.acc[mf][nf][1]);
            *(float2*)(C + (size_t)r1 * 1024 + col) = make_float2(g.acc[mf][nf][2], g.acc[mf][nf][3]);
        }
    }
}

// ---------------------------------------------------------------------------
// Flash attention (unchanged from R9: 64-q CTAs, 4 warps, 3 CTAs/SM)
// ---------------------------------------------------------------------------
#define KSTR 72
__global__ void __launch_bounds__(128, 3) attn3_k() {
    extern __shared__ __nv_bfloat16 ASM[];
    const int STG = 4 * 64 * KSTR;

    int tid = threadIdx.x, wid = tid >> 5, lane = tid & 31;
    int bph = blockIdx.y, h = bph & 15, bp = bph >> 4, hkv = h >> 2;
    int qt0 = blockIdx.x << 6;
    int qrow0 = bp * 512 + qt0;
    size_t vbase = (size_t)(bp * 4 + hkv) * 32768;

    {
        #pragma unroll
        for (int i = 0; i < 8; i++) {
            int half = i >> 2;
            int cc = (i & 3) * 128 + tid;
            int r = cc >> 3, kc = (cc & 7) * 8;
            uint32_t dst = smem_u32(ASM + half * 64 * KSTR + r * KSTR + kc);
            const __nv_bfloat16* src = (half ? g_ql : g_qh) + (size_t)(qrow0 + r) * 1024 + h * 64 + kc;
            CP16(dst, src);
        }
        CP_COMMIT(); CP_WAIT0();
        __syncthreads();
    }
    uint32_t qh[4][4], ql[4][4];
    {
        __nv_bfloat16* Qhi = ASM;
        __nv_bfloat16* Qlo = ASM + 64 * KSTR;
        int row = wid * 16 + (lane & 15);
        #pragma unroll
        for (int ks = 0; ks < 4; ks++) {
            int koff = ks * 16 + ((lane >> 4) << 3);
            LDSM4(qh[ks][0], qh[ks][1], qh[ks][2], qh[ks][3], smem_u32(&Qhi[row * KSTR + koff]));
            LDSM4(ql[ks][0], ql[ks][1], ql[ks][2], ql[ks][3], smem_u32(&Qlo[row * KSTR + koff]));
        }
    }
    __syncthreads();

    auto issue = [&](int it, int s) {
        __nv_bfloat16* stg = ASM + s * STG;
        int kt = it * 64;
        #pragma unroll
        for (int i = 0; i < 16; i++) {
            int arr = i >> 2;
            int cc = (i & 3) * 128 + tid;
            int r = cc >> 3, kc = (cc & 7) * 8;
            uint32_t dst = smem_u32(stg + arr * 64 * KSTR + r * KSTR + kc);
            const __nv_bfloat16* src;
            if (arr == 0)      src = g_kh + (size_t)(bp * 512 + kt + r) * 256 + hkv * 64 + kc;
            else if (arr == 1) src = g_kl + (size_t)(bp * 512 + kt + r) * 256 + hkv * 64 + kc;
            else if (arr == 2) src = g_vth + vbase + (size_t)r * 512 + kt + kc;
            else               src = g_vtl + vbase + (size_t)r * 512 + kt + kc;
            CP16(dst, src);
        }
    };

    float o[8][4];
    #pragma unroll
    for (int nf = 0; nf < 8; nf++)
        #pragma unroll
        for (int c = 0; c < 4; c++) o[nf][c] = 0.f;
    float m0 = -INFINITY, m1 = -INFINITY, l0 = 0.f, l1 = 0.f;

    issue(0, 0);
    CP_COMMIT();

    for (int it = 0; it < 8; it++) {
        CP_WAIT0();
        __syncthreads();
        if (it + 1 < 8) { issue(it + 1, (it + 1) & 1); CP_COMMIT(); }

        __nv_bfloat16* stg = ASM + (it & 1) * STG;
        __nv_bfloat16* Khi = stg;
        __nv_bfloat16* Klo = stg + 64 * KSTR;
        __nv_bfloat16* Vth = stg + 2 * 64 * KSTR;
        __nv_bfloat16* Vtl = stg + 3 * 64 * KSTR;

        float s[8][4];
        #pragma unroll
        for (int nf = 0; nf < 8; nf++)
            #pragma unroll
            for (int c = 0; c < 4; c++) s[nf][c] = 0.f;

        #pragma unroll
        for (int ks = 0; ks < 4; ks++) {
            int koff = ks * 16 + ((lane >> 4) << 3);
            #pragma unroll
            for (int jp = 0; jp < 8; jp += 2) {
                int brow = jp * 8 + (lane & 15);
                uint32_t r0, r1, r2, r3, t0, t1, t2, t3;
                LDSM4(r0, r1, r2, r3, smem_u32(&Khi[brow * KSTR + koff]));
                LDSM4(t0, t1, t2, t3, smem_u32(&Klo[brow * KSTR + koff]));
                MMA16816(s[jp],     qh[ks][0], qh[ks][1], qh[ks][2], qh[ks][3], r0, r2);
                MMA16816(s[jp],     qh[ks][0], qh[ks][1], qh[ks][2], qh[ks][3], t0, t2);
                MMA16816(s[jp],     ql[ks][0], ql[ks][1], ql[ks][2], ql[ks][3], r0, r2);
                MMA16816(s[jp + 1], qh[ks][0], qh[ks][1], qh[ks][2], qh[ks][3], r1, r3);
                MMA16816(s[jp + 1], qh[ks][0], qh[ks][1], qh[ks][2], qh[ks][3], t1, t3);
                MMA16816(s[jp + 1], ql[ks][0], ql[ks][1], ql[ks][2], ql[ks][3], r1, r3);
            }
        }

        float rmax0 = -INFINITY, rmax1 = -INFINITY;
        #pragma unroll
        for (int nf = 0; nf < 8; nf++) {
            rmax0 = fmaxf(rmax0, fmaxf(s[nf][0], s[nf][1]));
            rmax1 = fmaxf(rmax1, fmaxf(s[nf][2], s[nf][3]));
        }
        rmax0 = fmaxf(rmax0, __shfl_xor_sync(0xffffffffu, rmax0, 1));
        rmax0 = fmaxf(rmax0, __shfl_xor_sync(0xffffffffu, rmax0, 2));
        rmax1 = fmaxf(rmax1, __shfl_xor_sync(0xffffffffu, rmax1, 1));
        rmax1 = fmaxf(rmax1, __shfl_xor_sync(0xffffffffu, rmax1, 2));
        float mn0 = fmaxf(m0, rmax0), mn1 = fmaxf(m1, rmax1);
        float al0 = exp2f(m0 - mn0), al1 = exp2f(m1 - mn1);
        float ps0 = 0.f, ps1 = 0.f;
        #pragma unroll
        for (int nf = 0; nf < 8; nf++) {
            s[nf][0] = exp2f(s[nf][0] - mn0); ps0 += s[nf][0];
            s[nf][1] = exp2f(s[nf][1] - mn0); ps0 += s[nf][1];
            s[nf][2] = exp2f(s[nf][2] - mn1); ps1 += s[nf][2];
            s[nf][3] = exp2f(s[nf][3] - mn1); ps1 += s[nf][3];
        }
        l0 = l0 * al0 + ps0; l1 = l1 * al1 + ps1;
        m0 = mn0; m1 = mn1;
        #pragma unroll
        for (int nf = 0; nf < 8; nf++) {
            o[nf][0] *= al0; o[nf][1] *= al0;
            o[nf][2] *= al1; o[nf][3] *= al1;
        }

        #pragma unroll
        for (int ks = 0; ks < 4; ks++) {
            float* pa = s[2 * ks];
            float* pb = s[2 * ks + 1];
            float ha0 = __bfloat162float(__float2bfloat16_rn(pa[0]));
            float ha1 = __bfloat162float(__float2bfloat16_rn(pa[1]));
            float ha2 = __bfloat162float(__float2bfloat16_rn(pa[2]));
            float ha3 = __bfloat162float(__float2bfloat16_rn(pa[3]));
            float hb0 = __bfloat162float(__float2bfloat16_rn(pb[0]));
            float hb1 = __bfloat162float(__float2bfloat16_rn(pb[1]));
            float hb2 = __bfloat162float(__float2bfloat16_rn(pb[2]));
            float hb3 = __bfloat162float(__float2bfloat16_rn(pb[3]));
            uint32_t ah0 = pk_bf2(ha0, ha1), ah1 = pk_bf2(ha2, ha3);
            uint32_t ah2 = pk_bf2(hb0, hb1), ah3 = pk_bf2(hb2, hb3);
            uint32_t pl0 = pk_bf2(pa[0] - ha0, pa[1] - ha1);
            uint32_t pl1 = pk_bf2(pa[2] - ha2, pa[3] - ha3);
            uint32_t pl2 = pk_bf2(pb[0] - hb0, pb[1] - hb1);
            uint32_t pl3 = pk_bf2(pb[2] - hb2, pb[3] - hb3);

            int koff = ks * 16 + ((lane >> 4) << 3);
            #pragma unroll
            for (int jp = 0; jp < 8; jp += 2) {
                int brow = jp * 8 + (lane & 15);
                uint32_t r0, r1, r2, r3, t0, t1, t2, t3;
                LDSM4(r0, r1, r2, r3, smem_u32(&Vth[brow * KSTR + koff]));
                LDSM4(t0, t1, t2, t3, smem_u32(&Vtl[brow * KSTR + koff]));
                MMA16816(o[jp],     ah0, ah1, ah2, ah3, r0, r2);
                MMA16816(o[jp],     ah0, ah1, ah2, ah3, t0, t2);
                MMA16816(o[jp],     pl0, pl1, pl2, pl3, r0, r2);
                MMA16816(o[jp + 1], ah0, ah1, ah2, ah3, r1, r3);
                MMA16816(o[jp + 1], ah0, ah1, ah2, ah3, t1, t3);
                MMA16816(o[jp + 1], pl0, pl1, pl2, pl3, r1, r3);
            }
        }
        __syncthreads();
    }

    l0 += __shfl_xor_sync(0xffffffffu, l0, 1);
    l0 += __shfl_xor_sync(0xffffffffu, l0, 2);
    l1 += __shfl_xor_sync(0xffffffffu, l1, 1);
    l1 += __shfl_xor_sync(0xffffffffu, l1, 2);
    float inv0 = 1.f / l0, inv1 = 1.f / l1;

    int row = qrow0 + wid * 16 + (lane >> 2);
    float* ob0 = g_o + (size_t)row * 1024 + h * 64 + (lane & 3) * 2;
    float* ob1 = ob0 + 8 * 1024;
    #pragma unroll
    for (int nf = 0; nf < 8; nf++) {
        *(float2*)(ob0 + nf * 8) = make_float2(o[nf][0] * inv0, o[nf][1] * inv0);
        *(float2*)(ob1 + nf * 8) = make_float2(o[nf][2] * inv1, o[nf][3] * inv1);
    }
}

// ---------------------------------------------------------------------------
extern "C" void kernel_launch(void* const* d_in, const int* in_sizes, int n_in,
                              void* d_out, int out_size) {
    (void)in_sizes; (void)n_in; (void)out_size;
    const float* hidden = (const float*)d_in[0];
    const float* Wq = (const float*)d_in[1];
    const float* Wk = (const float*)d_in[2];
    const float* Wv = (const float*)d_in[3];
    const float* Wo = (const float*)d_in[4];
    float* out = (float*)d_out;

    const int gsm = 3 * SSTG * 2;             // 98304 B (3 stages x 32KB)
    const int asm_ = 2 * 4 * 64 * KSTR * 2;   // 73728 B
    cudaFuncSetAttribute(bfgemmQKV_k, cudaFuncAttributeMaxDynamicSharedMemorySize, gsm);
    cudaFuncSetAttribute(bfgemmO_k, cudaFuncAttributeMaxDynamicSharedMemorySize, gsm);
    cudaFuncSetAttribute(attn3_k, cudaFuncAttributeMaxDynamicSharedMemorySize, asm_);

    // 0: convert hidden (remap)
    convAin_k<<<8192, 256>>>(hidden);
    // 1: Wq transpose+split
    transWq_k<<<1024, 256>>>(Wq);
    // 2: Wk + Wv transpose+split
    transWkv_k<<<2048, 256>>>(Wk, Wv);
    // 3: fused QKV projection  <- capture slot
    bfgemmQKV_k<<<dim3(12, 64), 256, gsm>>>();
    // 4: rope+split + V transpose+split
    prep2_k<<<22528, 256>>>();
    // 5: attention
    attn3_k<<<dim3(8, 256), 128, asm_>>>();
    // 6: convA(g_o) + Wo transpose+split
    prep3_k<<<9216, 256>>>(Wo);
    // 7: output projection
    bfgemmO_k<<<dim3(8, 64), 256, gsm>>>(out);
}

// round 11
// speedup vs baseline: 4.0527x; 1.0018x over previous
#include <cuda_runtime.h>
#include <cuda_bf16.h>
#include <cstdint>
#include <math.h>

#define NTOK 8192

// fp32 intermediates
__device__ float g_q[NTOK * 1024];
__device__ float g_k[NTOK * 256];
__device__ float g_v[NTOK * 256];
// bf16 hi/lo preconverted operands
__device__ __nv_bfloat16 g_ah[NTOK * 1024], g_al[NTOK * 1024];
__device__ __nv_bfloat16 g_qh[NTOK * 1024], g_ql[NTOK * 1024];
__device__ __nv_bfloat16 g_kh[NTOK * 256],  g_kl[NTOK * 256];
__device__ __nv_bfloat16 g_vth[NTOK * 256], g_vtl[NTOK * 256];
__device__ __nv_bfloat16 g_wth[1536 * 1024], g_wtl[1536 * 1024];

__device__ __forceinline__ int remap_bpt(int r) {
    int b = r >> 12, p = (r >> 9) & 7, t = r & 511;
    return (b << 12) + (t << 3) + p;
}
__device__ __forceinline__ uint32_t smem_u32(const void* p) {
    uint32_t a;
    asm("{ .reg .u64 t; cvta.to.shared.u64 t, %1; cvt.u32.u64 %0, t; }" : "=r"(a) : "l"(p));
    return a;
}
#define LDSM4(r0, r1, r2, r3, a) \
    asm volatile("ldmatrix.sync.aligned.m8n8.x4.shared.b16 {%0,%1,%2,%3}, [%4];" \
        : "=r"(r0), "=r"(r1), "=r"(r2), "=r"(r3) : "r"(a))
#define MMA16816(c, a0, a1, a2, a3, b0, b1) \
    asm volatile("mma.sync.aligned.m16n8k16.row.col.f32.bf16.bf16.f32 " \
        "{%0,%1,%2,%3},{%4,%5,%6,%7},{%8,%9},{%0,%1,%2,%3};" \
        : "+f"((c)[0]), "+f"((c)[1]), "+f"((c)[2]), "+f"((c)[3]) \
        : "r"(a0), "r"(a1), "r"(a2), "r"(a3), "r"(b0), "r"(b1))
#define CP16(dst, src) \
    asm volatile("cp.async.cg.shared.global [%0], [%1], 16;" :: "r"(dst), "l"(src))
#define CP_COMMIT() asm volatile("cp.async.commit_group;" ::: "memory")
#define CP_WAIT1()  asm volatile("cp.async.wait_group 1;" ::: "memory")
#define CP_WAIT0()  asm volatile("cp.async.wait_group 0;" ::: "memory")

__device__ __forceinline__ uint32_t pk_bf2(float x, float y) {
    __nv_bfloat162 h = __floats2bfloat162_rn(x, y);
    return *(uint32_t*)&h;
}
__device__ __forceinline__ void split_store4(float4 v, void* ph, void* pl) {
    float hx = __bfloat162float(__float2bfloat16_rn(v.x));
    float hy = __bfloat162float(__float2bfloat16_rn(v.y));
    float hz = __bfloat162float(__float2bfloat16_rn(v.z));
    float hw = __bfloat162float(__float2bfloat16_rn(v.w));
    *(uint2*)ph = make_uint2(pk_bf2(hx, hy), pk_bf2(hz, hw));
    *(uint2*)pl = make_uint2(pk_bf2(v.x - hx, v.y - hy), pk_bf2(v.z - hz, v.w - hw));
}

// ---------------- prep bodies ----------------
__device__ __forceinline__ void convA_body(const float* __restrict__ src, int blk, int tid) {
    int idx = blk * 256 + tid;
    int row = idx >> 8, c4 = (idx & 255) * 4;
    int srow = remap_bpt(row);
    float4 v = *(const float4*)(src + (size_t)srow * 1024 + c4);
    split_store4(v, &g_ah[(size_t)row * 1024 + c4], &g_al[(size_t)row * 1024 + c4]);
}

__device__ __forceinline__ void transsplit_body(const float* __restrict__ in, int N,
                                                int rowoff, int bx, int by, int tid) {
    __shared__ float t[32][33];
    int n0 = bx * 32;
    if (n0 >= N) return;
    int k0 = by * 32, x = tid & 31, y = tid >> 5;
    for (int j = y; j < 32; j += 8)
        t[j][x] = in[(size_t)(k0 + j) * N + n0 + x];
    __syncthreads();
    for (int j = y; j < 32; j += 8) {
        float v = t[x][j];
        float hi = __bfloat162float(__float2bfloat16_rn(v));
        size_t o = (size_t)(rowoff + n0 + j) * 1024 + k0 + x;
        g_wth[o] = __float2bfloat16_rn(hi);
        g_wtl[o] = __float2bfloat16_rn(v - hi);
    }
}

__global__ void __launch_bounds__(256) convAin_k(const float* __restrict__ hidden) {
    convA_body(hidden, blockIdx.x, threadIdx.x);
}
__global__ void __launch_bounds__(256) transWq_k(const float* __restrict__ Wq) {
    int r = blockIdx.x;
    transsplit_body(Wq, 1024, 0, r & 31, r >> 5, threadIdx.x);
}
__global__ void __launch_bounds__(256) transWkv_k(const float* __restrict__ Wk,
                                                  const float* __restrict__ Wv) {
    int b = blockIdx.x;
    int z = b >> 10, r = b & 1023;
    transsplit_body(z ? Wv : Wk, 256, z ? 1280 : 1024, r & 31, r >> 5, threadIdx.x);
}
__global__ void __launch_bounds__(256) transWo_k(const float* __restrict__ Wo) {
    int r = blockIdx.x;
    transsplit_body(Wo, 1024, 0, r & 31, r >> 5, threadIdx.x);
}
__global__ void __launch_bounds__(256) prep2_k() {
    __shared__ float t[32][33];
    int b = blockIdx.x, tid = threadIdx.x;
    if (b < 20480) {
        int idx = b * 256 + tid;
        const int QP = NTOK * 16 * 32;
        const float* base;
        __nv_bfloat16 *oh, *ol;
        int i, tok;
        float scale;
        if (idx < QP) {
            i = idx & 31;
            int r = idx >> 5;
            tok = r >> 4;
            size_t off = (size_t)tok * 1024 + (r & 15) * 64;
            base = g_q + off; oh = g_qh + off; ol = g_ql + off;
            scale = 0.125f * 1.4426950408889634f;
        } else {
            int j = idx - QP;
            i = j & 31;
            int r = j >> 5;
            tok = r >> 2;
            size_t off = (size_t)tok * 256 + (r & 3) * 64;
            base = g_k + off; oh = g_kh + off; ol = g_kl + off;
            scale = 1.0f;
        }
        int tt = tok & 511;
        float invf = expf(-(float)i * 0.28782313662425574f);
        float ang = (float)tt * invf, s, c;
        sincosf(ang, &s, &c);
        float x1 = base[i], x2 = base[i + 32];
        float y1 = (x1 * c - x2 * s) * scale;
        float y2 = (x1 * s + x2 * c) * scale;
        float h1 = __bfloat162float(__float2bfloat16_rn(y1));
        float h2 = __bfloat162float(__float2bfloat16_rn(y2));
        oh[i]      = __float2bfloat16_rn(h1);
        ol[i]      = __float2bfloat16_rn(y1 - h1);
        oh[i + 32] = __float2bfloat16_rn(h2);
        ol[i + 32] = __float2bfloat16_rn(y2 - h2);
        return;
    }
    int idx = b - 20480;
    int bx = idx & 15, by = (idx >> 4) & 1, g = idx >> 5;
    int bp = g >> 2, hkv = g & 3;
    int k0 = bx * 32, d0 = by * 32, x = tid & 31, y = tid >> 5;
    for (int j = y; j < 32; j += 8)
        t[j][x] = g_v[(size_t)(bp * 512 + k0 + j) * 256 + hkv * 64 + d0 + x];
    __syncthreads();
    for (int j = y; j < 32; j += 8) {
        float v = t[x][j];
        float hi = __bfloat162float(__float2bfloat16_rn(v));
        size_t o = (size_t)g * 32768 + (size_t)(d0 + j) * 512 + k0 + x;
        g_vth[o] = __float2bfloat16_rn(hi);
        g_vtl[o] = __float2bfloat16_rn(v - hi);
    }
}

// ---------------------------------------------------------------------------
// GEMM core: 3-stage cp.async, XOR-swizzled smem, TERM-MAJOR MMA ordering
// (all 16 hh, then 16 hl, then 16 lh: acc dependency distance 16, not 1).
// ---------------------------------------------------------------------------
#define SARR 4096
#define SSTG 16384

struct GemmCore {
    uint32_t smbase;
    int tid, wid, lane, wm, wn;
    float acc[4][4][4];

    __device__ __forceinline__ void init(const __nv_bfloat16* sm, int t) {
        smbase = smem_u32(sm);
        tid = t; wid = t >> 5; lane = t & 31;
        wm = (wid >> 2) * 64; wn = (wid & 3) * 32;
        #pragma unroll
        for (int i = 0; i < 4; i++)
            #pragma unroll
            for (int j = 0; j < 4; j++)
                #pragma unroll
                for (int q = 0; q < 4; q++) acc[i][j][q] = 0.f;
    }
    __device__ __forceinline__ static uint32_t swz(int row, int chunk) {
        return (uint32_t)(row * 32 + ((chunk ^ ((row >> 1) & 3)) << 3));
    }
    __device__ __forceinline__ void issue(const __nv_bfloat16* Agh, const __nv_bfloat16* Agl,
                                          const __nv_bfloat16* Bgh, const __nv_bfloat16* Bgl,
                                          int am0, int bn0, int k0, int s) {
        uint32_t stg = smbase + (uint32_t)s * SSTG * 2;
        #pragma unroll
        for (int i = 0; i < 8; i++) {
            int arr = i >> 1;
            int cc = (i & 1) * 256 + tid;
            int r = cc >> 2, ch = cc & 3;
            uint32_t dst = stg + (arr * SARR + swz(r, ch)) * 2;
            const __nv_bfloat16* src;
            if (arr == 0)      src = Agh + (size_t)(am0 + r) * 1024 + k0 + ch * 8;
            else if (arr == 1) src = Agl + (size_t)(am0 + r) * 1024 + k0 + ch * 8;
            else if (arr == 2) src = Bgh + (size_t)(bn0 + r) * 1024 + k0 + ch * 8;
            else               src = Bgl + (size_t)(bn0 + r) * 1024 + k0 + ch * 8;
            CP16(dst, src);
        }
    }
    __device__ __forceinline__ void compute(int s) {
        uint32_t stg = smbase + (uint32_t)s * SSTG * 2;
        #pragma unroll
        for (int ks = 0; ks < 2; ks++) {
            int koff = ks * 16 + ((lane >> 4) << 3);
            int chunk = koff >> 3;
            int arow = wm + (lane & 15);
            uint32_t ah[4][4], al[4][4];
            #pragma unroll
            for (int mf = 0; mf < 4; mf++) {
                int row = arow + mf * 16;
                uint32_t off = swz(row, chunk) * 2;
                LDSM4(ah[mf][0], ah[mf][1], ah[mf][2], ah[mf][3], stg + 0 * SARR * 2 + off);
                LDSM4(al[mf][0], al[mf][1], al[mf][2], al[mf][3], stg + 1 * SARR * 2 + off);
            }
            uint32_t bh[4][2], bl[4][2];
            #pragma unroll
            for (int jp = 0; jp < 4; jp += 2) {
                int brow = wn + jp * 8 + (lane & 15);
                uint32_t off = swz(brow, chunk) * 2;
                uint32_t r0, r1, r2, r3;
                LDSM4(r0, r1, r2, r3, stg + 2 * SARR * 2 + off);
                bh[jp][0] = r0; bh[jp + 1][0] = r1; bh[jp][1] = r2; bh[jp + 1][1] = r3;
                LDSM4(r0, r1, r2, r3, stg + 3 * SARR * 2 + off);
                bl[jp][0] = r0; bl[jp + 1][0] = r1; bl[jp][1] = r2; bl[jp + 1][1] = r3;
            }
            // term-major: 16 independent MMAs per term
            #pragma unroll
            for (int mf = 0; mf < 4; mf++)
                #pragma unroll
                for (int nf = 0; nf < 4; nf++)
                    MMA16816(acc[mf][nf], ah[mf][0], ah[mf][1], ah[mf][2], ah[mf][3], bh[nf][0], bh[nf][1]);
            #pragma unroll
            for (int mf = 0; mf < 4; mf++)
                #pragma unroll
                for (int nf = 0; nf < 4; nf++)
                    MMA16816(acc[mf][nf], ah[mf][0], ah[mf][1], ah[mf][2], ah[mf][3], bl[nf][0], bl[nf][1]);
            #pragma unroll
            for (int mf = 0; mf < 4; mf++)
                #pragma unroll
                for (int nf = 0; nf < 4; nf++)
                    MMA16816(acc[mf][nf], al[mf][0], al[mf][1], al[mf][2], al[mf][3], bh[nf][0], bh[nf][1]);
        }
    }
    __device__ __forceinline__ void run(const __nv_bfloat16* Agh, const __nv_bfloat16* Agl,
                                        const __nv_bfloat16* Bgh, const __nv_bfloat16* Bgl,
                                        int am0, int bn0) {
        issue(Agh, Agl, Bgh, Bgl, am0, bn0, 0, 0);  CP_COMMIT();
        issue(Agh, Agl, Bgh, Bgl, am0, bn0, 32, 1); CP_COMMIT();
        int s = 0, sn = 2;
        for (int it = 0; it < 32; it++) {
            if (it < 31) { CP_WAIT1(); } else { CP_WAIT0(); }
            __syncthreads();
            if (it + 2 < 32) {
                issue(Agh, Agl, Bgh, Bgl, am0, bn0, (it + 2) * 32, sn);
                CP_COMMIT();
            }
            compute(s);
            s = (s == 2) ? 0 : s + 1;
            sn = (sn == 2) ? 0 : sn + 1;
        }
    }
};

__global__ void __launch_bounds__(256) bfgemmQKV_k() {
    extern __shared__ __nv_bfloat16 SM[];
    GemmCore g;
    g.init(SM, threadIdx.x);
    int bm = blockIdx.y, bn = blockIdx.x;
    g.run(g_ah, g_al, g_wth, g_wtl, bm * 128, bn * 128);

    float* C; int Ntot, colb;
    if (bn < 8)       { C = g_q; Ntot = 1024; colb = bn * 128; }
    else if (bn < 10) { C = g_k; Ntot = 256;  colb = (bn - 8) * 128; }
    else              { C = g_v; Ntot = 256;  colb = (bn - 10) * 128; }
    #pragma unroll
    for (int mf = 0; mf < 4; mf++) {
        int r0 = bm * 128 + g.wm + mf * 16 + (g.lane >> 2);
        int r1 = r0 + 8;
        #pragma unroll
        for (int nf = 0; nf < 4; nf++) {
            int col = colb + g.wn + nf * 8 + (g.lane & 3) * 2;
            *(float2*)(C + (size_t)r0 * Ntot + col) = make_float2(g.acc[mf][nf][0], g.acc[mf][nf][1]);
            *(float2*)(C + (size_t)r1 * Ntot + col) = make_float2(g.acc[mf][nf][2], g.acc[mf][nf][3]);
        }
    }
}

__global__ void __launch_bounds__(256) bfgemmO_k(float* __restrict__ C) {
    extern __shared__ __nv_bfloat16 SM[];
    GemmCore g;
    g.init(SM, threadIdx.x);
    int bm = blockIdx.y, bn = blockIdx.x;
    g.run(g_ah, g_al, g_wth, g_wtl, bm * 128, bn * 128);
    #pragma unroll
    for (int mf = 0; mf < 4; mf++) {
        int r0 = remap_bpt(bm * 128 + g.wm + mf * 16 + (g.lane >> 2));
        int r1 = remap_bpt(bm * 128 + g.wm + mf * 16 + (g.lane >> 2) + 8);
        #pragma unroll
        for (int nf = 0; nf < 4; nf++) {
            int col = bn * 128 + g.wn + nf * 8 + (g.lane & 3) * 2;
            *(float2*)(C + (size_t)r0 * 1024 + col) = make_float2(g.acc[mf][nf][0], g.acc[mf][nf][1]);
            *(float2*)(C + (size_t)r1 * 1024 + col) = make_float2(g.acc[mf][nf][2], g.acc[mf][nf][3]);
        }
    }
}

// ---------------------------------------------------------------------------
// Flash attention: distance-2 MMA reorder; epilogue writes bf16 hi/lo directly
// into g_ah/g_al (gemmO's A operand) — no fp32 roundtrip.
// ---------------------------------------------------------------------------
#define KSTR 72
__global__ void __launch_bounds__(128, 3) attn3_k() {
    extern __shared__ __nv_bfloat16 ASM[];
    const int STG = 4 * 64 * KSTR;

    int tid = threadIdx.x, wid = tid >> 5, lane = tid & 31;
    int bph = blockIdx.y, h = bph & 15, bp = bph >> 4, hkv = h >> 2;
    int qt0 = blockIdx.x << 6;
    int qrow0 = bp * 512 + qt0;
    size_t vbase = (size_t)(bp * 4 + hkv) * 32768;

    {
        #pragma unroll
        for (int i = 0; i < 8; i++) {
            int half = i >> 2;
            int cc = (i & 3) * 128 + tid;
            int r = cc >> 3, kc = (cc & 7) * 8;
            uint32_t dst = smem_u32(ASM + half * 64 * KSTR + r * KSTR + kc);
            const __nv_bfloat16* src = (half ? g_ql : g_qh) + (size_t)(qrow0 + r) * 1024 + h * 64 + kc;
            CP16(dst, src);
        }
        CP_COMMIT(); CP_WAIT0();
        __syncthreads();
    }
    uint32_t qh[4][4], ql[4][4];
    {
        __nv_bfloat16* Qhi = ASM;
        __nv_bfloat16* Qlo = ASM + 64 * KSTR;
        int row = wid * 16 + (lane & 15);
        #pragma unroll
        for (int ks = 0; ks < 4; ks++) {
            int koff = ks * 16 + ((lane >> 4) << 3);
            LDSM4(qh[ks][0], qh[ks][1], qh[ks][2], qh[ks][3], smem_u32(&Qhi[row * KSTR + koff]));
            LDSM4(ql[ks][0], ql[ks][1], ql[ks][2], ql[ks][3], smem_u32(&Qlo[row * KSTR + koff]));
        }
    }
    __syncthreads();

    auto issue = [&](int it, int s) {
        __nv_bfloat16* stg = ASM + s * STG;
        int kt = it * 64;
        #pragma unroll
        for (int i = 0; i < 16; i++) {
            int arr = i >> 2;
            int cc = (i & 3) * 128 + tid;
            int r = cc >> 3, kc = (cc & 7) * 8;
            uint32_t dst = smem_u32(stg + arr * 64 * KSTR + r * KSTR + kc);
            const __nv_bfloat16* src;
            if (arr == 0)      src = g_kh + (size_t)(bp * 512 + kt + r) * 256 + hkv * 64 + kc;
            else if (arr == 1) src = g_kl + (size_t)(bp * 512 + kt + r) * 256 + hkv * 64 + kc;
            else if (arr == 2) src = g_vth + vbase + (size_t)r * 512 + kt + kc;
            else               src = g_vtl + vbase + (size_t)r * 512 + kt + kc;
            CP16(dst, src);
        }
    };

    float o[8][4];
    #pragma unroll
    for (int nf = 0; nf < 8; nf++)
        #pragma unroll
        for (int c = 0; c < 4; c++) o[nf][c] = 0.f;
    float m0 = -INFINITY, m1 = -INFINITY, l0 = 0.f, l1 = 0.f;

    issue(0, 0);
    CP_COMMIT();

    for (int it = 0; it < 8; it++) {
        CP_WAIT0();
        __syncthreads();
        if (it + 1 < 8) { issue(it + 1, (it + 1) & 1); CP_COMMIT(); }

        __nv_bfloat16* stg = ASM + (it & 1) * STG;
        __nv_bfloat16* Khi = stg;
        __nv_bfloat16* Klo = stg + 64 * KSTR;
        __nv_bfloat16* Vth = stg + 2 * 64 * KSTR;
        __nv_bfloat16* Vtl = stg + 3 * 64 * KSTR;

        float s[8][4];
        #pragma unroll
        for (int nf = 0; nf < 8; nf++)
            #pragma unroll
            for (int c = 0; c < 4; c++) s[nf][c] = 0.f;

        #pragma unroll
        for (int ks = 0; ks < 4; ks++) {
            int koff = ks * 16 + ((lane >> 4) << 3);
            #pragma unroll
            for (int jp = 0; jp < 8; jp += 2) {
                int brow = jp * 8 + (lane & 15);
                uint32_t r0, r1, r2, r3, t0, t1, t2, t3;
                LDSM4(r0, r1, r2, r3, smem_u32(&Khi[brow * KSTR + koff]));
                LDSM4(t0, t1, t2, t3, smem_u32(&Klo[brow * KSTR + koff]));
                // term-interleaved: same-acc dependency distance 2
                MMA16816(s[jp],     qh[ks][0], qh[ks][1], qh[ks][2], qh[ks][3], r0, r2);
                MMA16816(s[jp + 1], qh[ks][0], qh[ks][1], qh[ks][2], qh[ks][3], r1, r3);
                MMA16816(s[jp],     qh[ks][0], qh[ks][1], qh[ks][2], qh[ks][3], t0, t2);
                MMA16816(s[jp + 1], qh[ks][0], qh[ks][1], qh[ks][2], qh[ks][3], t1, t3);
                MMA16816(s[jp],     ql[ks][0], ql[ks][1], ql[ks][2], ql[ks][3], r0, r2);
                MMA16816(s[jp + 1], ql[ks][0], ql[ks][1], ql[ks][2], ql[ks][3], r1, r3);
            }
        }

        float rmax0 = -INFINITY, rmax1 = -INFINITY;
        #pragma unroll
        for (int nf = 0; nf < 8; nf++) {
            rmax0 = fmaxf(rmax0, fmaxf(s[nf][0], s[nf][1]));
            rmax1 = fmaxf(rmax1, fmaxf(s[nf][2], s[nf][3]));
        }
        rmax0 = fmaxf(rmax0, __shfl_xor_sync(0xffffffffu, rmax0, 1));
        rmax0 = fmaxf(rmax0, __shfl_xor_sync(0xffffffffu, rmax0, 2));
        rmax1 = fmaxf(rmax1, __shfl_xor_sync(0xffffffffu, rmax1, 1));
        rmax1 = fmaxf(rmax1, __shfl_xor_sync(0xffffffffu, rmax1, 2));
        float mn0 = fmaxf(m0, rmax0), mn1 = fmaxf(m1, rmax1);
        float al0 = exp2f(m0 - mn0), al1 = exp2f(m1 - mn1);
        float ps0 = 0.f, ps1 = 0.f;
        #pragma unroll
        for (int nf = 0; nf < 8; nf++) {
            s[nf][0] = exp2f(s[nf][0] - mn0); ps0 += s[nf][0];
            s[nf][1] = exp2f(s[nf][1] - mn0); ps0 += s[nf][1];
            s[nf][2] = exp2f(s[nf][2] - mn1); ps1 += s[nf][2];
            s[nf][3] = exp2f(s[nf][3] - mn1); ps1 += s[nf][3];
        }
        l0 = l0 * al0 + ps0; l1 = l1 * al1 + ps1;
        m0 = mn0; m1 = mn1;
        #pragma unroll
        for (int nf = 0; nf < 8; nf++) {
            o[nf][0] *= al0; o[nf][1] *= al0;
            o[nf][2] *= al1; o[nf][3] *= al1;
        }

        #pragma unroll
        for (int ks = 0; ks < 4; ks++) {
            float* pa = s[2 * ks];
            float* pb = s[2 * ks + 1];
            float ha0 = __bfloat162float(__float2bfloat16_rn(pa[0]));
            float ha1 = __bfloat162float(__float2bfloat16_rn(pa[1]));
            float ha2 = __bfloat162float(__float2bfloat16_rn(pa[2]));
            float ha3 = __bfloat162float(__float2bfloat16_rn(pa[3]));
            float hb0 = __bfloat162float(__float2bfloat16_rn(pb[0]));
            float hb1 = __bfloat162float(__float2bfloat16_rn(pb[1]));
            float hb2 = __bfloat162float(__float2bfloat16_rn(pb[2]));
            float hb3 = __bfloat162float(__float2bfloat16_rn(pb[3]));
            uint32_t ah0 = pk_bf2(ha0, ha1), ah1 = pk_bf2(ha2, ha3);
            uint32_t ah2 = pk_bf2(hb0, hb1), ah3 = pk_bf2(hb2, hb3);
            uint32_t pl0 = pk_bf2(pa[0] - ha0, pa[1] - ha1);
            uint32_t pl1 = pk_bf2(pa[2] - ha2, pa[3] - ha3);
            uint32_t pl2 = pk_bf2(pb[0] - hb0, pb[1] - hb1);
            uint32_t pl3 = pk_bf2(pb[2] - hb2, pb[3] - hb3);

            int koff = ks * 16 + ((lane >> 4) << 3);
            #pragma unroll
            for (int jp = 0; jp < 8; jp += 2) {
                int brow = jp * 8 + (lane & 15);
                uint32_t r0, r1, r2, r3, t0, t1, t2, t3;
                LDSM4(r0, r1, r2, r3, smem_u32(&Vth[brow * KSTR + koff]));
                LDSM4(t0, t1, t2, t3, smem_u32(&Vtl[brow * KSTR + koff]));
                MMA16816(o[jp],     ah0, ah1, ah2, ah3, r0, r2);
                MMA16816(o[jp + 1], ah0, ah1, ah2, ah3, r1, r3);
                MMA16816(o[jp],     ah0, ah1, ah2, ah3, t0, t2);
                MMA16816(o[jp + 1], ah0, ah1, ah2, ah3, t1, t3);
                MMA16816(o[jp],     pl0, pl1, pl2, pl3, r0, r2);
                MMA16816(o[jp + 1], pl0, pl1, pl2, pl3, r1, r3);
            }
        }
        __syncthreads();
    }

    l0 += __shfl_xor_sync(0xffffffffu, l0, 1);
    l0 += __shfl_xor_sync(0xffffffffu, l0, 2);
    l1 += __shfl_xor_sync(0xffffffffu, l1, 1);
    l1 += __shfl_xor_sync(0xffffffffu, l1, 2);
    float inv0 = 1.f / l0, inv1 = 1.f / l1;

    // Write bf16 hi/lo directly into gemmO's A operand
    int row0 = qrow0 + wid * 16 + (lane >> 2);
    size_t b0 = (size_t)row0 * 1024 + h * 64 + (lane & 3) * 2;
    size_t b1 = b0 + 8 * 1024;
    #pragma unroll
    for (int nf = 0; nf < 8; nf++) {
        float x0 = o[nf][0] * inv0, y0 = o[nf][1] * inv0;
        float hx0 = __bfloat162float(__float2bfloat16_rn(x0));
        float hy0 = __bfloat162float(__float2bfloat16_rn(y0));
        *(uint32_t*)&g_ah[b0 + nf * 8] = pk_bf2(hx0, hy0);
        *(uint32_t*)&g_al[b0 + nf * 8] = pk_bf2(x0 - hx0, y0 - hy0);
        float x1 = o[nf][2] * inv1, y1 = o[nf][3] * inv1;
        float hx1 = __bfloat162float(__float2bfloat16_rn(x1));
        float hy1 = __bfloat162float(__float2bfloat16_rn(y1));
        *(uint32_t*)&g_ah[b1 + nf * 8] = pk_bf2(hx1, hy1);
        *(uint32_t*)&g_al[b1 + nf * 8] = pk_bf2(x1 - hx1, y1 - hy1);
    }
}

// ---------------------------------------------------------------------------
extern "C" void kernel_launch(void* const* d_in, const int* in_sizes, int n_in,
                              void* d_out, int out_size) {
    (void)in_sizes; (void)n_in; (void)out_size;
    const float* hidden = (const float*)d_in[0];
    const float* Wq = (const float*)d_in[1];
    const float* Wk = (const float*)d_in[2];
    const float* Wv = (const float*)d_in[3];
    const float* Wo = (const float*)d_in[4];
    float* out = (float*)d_out;

    const int gsm = 3 * SSTG * 2;             // 98304 B
    const int asm_ = 2 * 4 * 64 * KSTR * 2;   // 73728 B
    cudaFuncSetAttribute(bfgemmQKV_k, cudaFuncAttributeMaxDynamicSharedMemorySize, gsm);
    cudaFuncSetAttribute(bfgemmO_k, cudaFuncAttributeMaxDynamicSharedMemorySize, gsm);
    cudaFuncSetAttribute(attn3_k, cudaFuncAttributeMaxDynamicSharedMemorySize, asm_);

    // 0: convert hidden (remap)
    convAin_k<<<8192, 256>>>(hidden);
    // 1: Wq transpose+split
    transWq_k<<<1024, 256>>>(Wq);
    // 2: Wk + Wv transpose+split
    transWkv_k<<<2048, 256>>>(Wk, Wv);
    // 3: fused QKV projection  <- capture slot (compare tensor% vs 51.6)
    bfgemmQKV_k<<<dim3(12, 64), 256, gsm>>>();
    // 4: rope+split + V transpose+split
    prep2_k<<<22528, 256>>>();
    // 5: attention (writes bf16 hi/lo to g_ah/g_al)
    attn3_k<<<dim3(8, 256), 128, asm_>>>();
    // 6: Wo transpose+split
    transWo_k<<<1024, 256>>>(Wo);
    // 7: output projection
    bfgemmO_k<<<dim3(8, 64), 256, gsm>>>(out);
}

// round 12
// speedup vs baseline: 4.5914x; 1.1329x over previous
#include <cuda_runtime.h>
#include <cuda_fp16.h>
#include <cstdint>
#include <math.h>

#define NTOK 8192

// fp32 intermediates
__device__ float g_q[NTOK * 1024];
__device__ float g_k[NTOK * 256];
__device__ float g_v[NTOK * 256];
// fp16 hi/lo preconverted operands
__device__ __half g_ah[NTOK * 1024], g_al[NTOK * 1024];
__device__ __half g_qh[NTOK * 1024], g_ql[NTOK * 1024];
__device__ __half g_kh[NTOK * 256],  g_kl[NTOK * 256];
__device__ __half g_vth[NTOK * 256];
__device__ __half g_wth[2560 * 1024], g_wtl[2560 * 1024];  // QKV rows 0-1535, Wo rows 1536-2559

__device__ __forceinline__ int remap_bpt(int r) {
    int b = r >> 12, p = (r >> 9) & 7, t = r & 511;
    return (b << 12) + (t << 3) + p;
}
__device__ __forceinline__ uint32_t smem_u32(const void* p) {
    uint32_t a;
    asm("{ .reg .u64 t; cvta.to.shared.u64 t, %1; cvt.u32.u64 %0, t; }" : "=r"(a) : "l"(p));
    return a;
}
#define LDSM4(r0, r1, r2, r3, a) \
    asm volatile("ldmatrix.sync.aligned.m8n8.x4.shared.b16 {%0,%1,%2,%3}, [%4];" \
        : "=r"(r0), "=r"(r1), "=r"(r2), "=r"(r3) : "r"(a))
#define MMA16816(c, a0, a1, a2, a3, b0, b1) \
    asm volatile("mma.sync.aligned.m16n8k16.row.col.f32.f16.f16.f32 " \
        "{%0,%1,%2,%3},{%4,%5,%6,%7},{%8,%9},{%0,%1,%2,%3};" \
        : "+f"((c)[0]), "+f"((c)[1]), "+f"((c)[2]), "+f"((c)[3]) \
        : "r"(a0), "r"(a1), "r"(a2), "r"(a3), "r"(b0), "r"(b1))
#define CP16(dst, src) \
    asm volatile("cp.async.cg.shared.global [%0], [%1], 16;" :: "r"(dst), "l"(src))
#define CP_COMMIT() asm volatile("cp.async.commit_group;" ::: "memory")
#define CP_WAIT1()  asm volatile("cp.async.wait_group 1;" ::: "memory")
#define CP_WAIT0()  asm volatile("cp.async.wait_group 0;" ::: "memory")

__device__ __forceinline__ uint32_t pk_h2(float x, float y) {
    __half2 h = __floats2half2_rn(x, y);
    return *(uint32_t*)&h;
}
__device__ __forceinline__ void split_store4(float4 v, void* ph, void* pl) {
    float hx = __half2float(__float2half_rn(v.x));
    float hy = __half2float(__float2half_rn(v.y));
    float hz = __half2float(__float2half_rn(v.z));
    float hw = __half2float(__float2half_rn(v.w));
    *(uint2*)ph = make_uint2(pk_h2(hx, hy), pk_h2(hz, hw));
    *(uint2*)pl = make_uint2(pk_h2(v.x - hx, v.y - hy), pk_h2(v.z - hz, v.w - hw));
}

// ---------------- prep bodies ----------------
__device__ __forceinline__ void convA_body(const float* __restrict__ src, int blk, int tid) {
    int idx = blk * 256 + tid;
    int row = idx >> 8, c4 = (idx & 255) * 4;
    int srow = remap_bpt(row);
    float4 v = *(const float4*)(src + (size_t)srow * 1024 + c4);
    split_store4(v, &g_ah[(size_t)row * 1024 + c4], &g_al[(size_t)row * 1024 + c4]);
}

__device__ __forceinline__ void transsplit_body(const float* __restrict__ in, int N,
                                                int rowoff, int bx, int by, int tid) {
    __shared__ float t[32][33];
    int n0 = bx * 32;
    if (n0 >= N) return;
    int k0 = by * 32, x = tid & 31, y = tid >> 5;
    for (int j = y; j < 32; j += 8)
        t[j][x] = in[(size_t)(k0 + j) * N + n0 + x];
    __syncthreads();
    for (int j = y; j < 32; j += 8) {
        float v = t[x][j];
        float hi = __half2float(__float2half_rn(v));
        size_t o = (size_t)(rowoff + n0 + j) * 1024 + k0 + x;
        g_wth[o] = __float2half_rn(hi);
        g_wtl[o] = __float2half_rn(v - hi);
    }
}

// launch 0 (independent): Wo transpose+split into rows 1536..2559
__global__ void __launch_bounds__(256) transWo_k(const float* __restrict__ Wo) {
    int r = blockIdx.x;
    transsplit_body(Wo, 1024, 1536, r & 31, r >> 5, threadIdx.x);
}
// launch 1: convert hidden (remap-gathered)
__global__ void __launch_bounds__(256) convAin_k(const float* __restrict__ hidden) {
    convA_body(hidden, blockIdx.x, threadIdx.x);
}
// launch 2: Wq [0..1023] + Wk [1024..2047] + Wv [2048..3071]
__global__ void __launch_bounds__(256) transWqkv_k(const float* __restrict__ Wq,
                                                   const float* __restrict__ Wk,
                                                   const float* __restrict__ Wv) {
    int b = blockIdx.x;
    int z = b >> 10, r = b & 1023;
    const float* in = (z == 0) ? Wq : (z == 1) ? Wk : Wv;
    int N = (z == 0) ? 1024 : 256;
    int rowoff = (z == 0) ? 0 : (z == 1) ? 1024 : 1280;
    transsplit_body(in, N, rowoff, r & 31, r >> 5, threadIdx.x);
}
// launch 4: rope+split + V transpose (hi only)
__global__ void __launch_bounds__(256) prep2_k() {
    __shared__ float t[32][33];
    int b = blockIdx.x, tid = threadIdx.x;
    if (b < 20480) {
        int idx = b * 256 + tid;
        const int QP = NTOK * 16 * 32;
        const float* base;
        __half *oh, *ol;
        int i, tok;
        float scale;
        if (idx < QP) {
            i = idx & 31;
            int r = idx >> 5;
            tok = r >> 4;
            size_t off = (size_t)tok * 1024 + (r & 15) * 64;
            base = g_q + off; oh = g_qh + off; ol = g_ql + off;
            scale = 0.125f * 1.4426950408889634f;
        } else {
            int j = idx - QP;
            i = j & 31;
            int r = j >> 5;
            tok = r >> 2;
            size_t off = (size_t)tok * 256 + (r & 3) * 64;
            base = g_k + off; oh = g_kh + off; ol = g_kl + off;
            scale = 1.0f;
        }
        int tt = tok & 511;
        float invf = expf(-(float)i * 0.28782313662425574f);
        float ang = (float)tt * invf, s, c;
        sincosf(ang, &s, &c);
        float x1 = base[i], x2 = base[i + 32];
        float y1 = (x1 * c - x2 * s) * scale;
        float y2 = (x1 * s + x2 * c) * scale;
        float h1 = __half2float(__float2half_rn(y1));
        float h2 = __half2float(__float2half_rn(y2));
        oh[i]      = __float2half_rn(h1);
        ol[i]      = __float2half_rn(y1 - h1);
        oh[i + 32] = __float2half_rn(h2);
        ol[i + 32] = __float2half_rn(y2 - h2);
        return;
    }
    int idx = b - 20480;
    int bx = idx & 15, by = (idx >> 4) & 1, g = idx >> 5;
    int bp = g >> 2, hkv = g & 3;
    int k0 = bx * 32, d0 = by * 32, x = tid & 31, y = tid >> 5;
    for (int j = y; j < 32; j += 8)
        t[j][x] = g_v[(size_t)(bp * 512 + k0 + j) * 256 + hkv * 64 + d0 + x];
    __syncthreads();
    for (int j = y; j < 32; j += 8) {
        size_t o = (size_t)g * 32768 + (size_t)(d0 + j) * 512 + k0 + x;
        g_vth[o] = __float2half_rn(t[x][j]);
    }
}

// ---------------------------------------------------------------------------
// GEMM core: 3-stage cp.async, XOR-swizzled smem. BL=1: 3-term; BL=0: 2-term
// (AhBh + AlBh; B lo never loaded).
// ---------------------------------------------------------------------------
#define SARR 4096
#define SSTG 16384

template<int BL>
struct GemmCore {
    uint32_t smbase;
    int tid, wid, lane, wm, wn;
    float acc[4][4][4];

    __device__ __forceinline__ void init(const __half* sm, int t) {
        smbase = smem_u32(sm);
        tid = t; wid = t >> 5; lane = t & 31;
        wm = (wid >> 2) * 64; wn = (wid & 3) * 32;
        #pragma unroll
        for (int i = 0; i < 4; i++)
            #pragma unroll
            for (int j = 0; j < 4; j++)
                #pragma unroll
                for (int q = 0; q < 4; q++) acc[i][j][q] = 0.f;
    }
    __device__ __forceinline__ static uint32_t swz(int row, int chunk) {
        return (uint32_t)(row * 32 + ((chunk ^ ((row >> 1) & 3)) << 3));
    }
    __device__ __forceinline__ void issue(const __half* Agh, const __half* Agl,
                                          const __half* Bgh, const __half* Bgl,
                                          int am0, int bn0, int k0, int s) {
        uint32_t stg = smbase + (uint32_t)s * SSTG * 2;
        #pragma unroll
        for (int i = 0; i < 8; i++) {
            int arr = i >> 1;
            if (!BL && arr == 3) continue;
            int cc = (i & 1) * 256 + tid;
            int r = cc >> 2, ch = cc & 3;
            uint32_t dst = stg + (arr * SARR + swz(r, ch)) * 2;
            const __half* src;
            if (arr == 0)      src = Agh + (size_t)(am0 + r) * 1024 + k0 + ch * 8;
            else if (arr == 1) src = Agl + (size_t)(am0 + r) * 1024 + k0 + ch * 8;
            else if (arr == 2) src = Bgh + (size_t)(bn0 + r) * 1024 + k0 + ch * 8;
            else               src = Bgl + (size_t)(bn0 + r) * 1024 + k0 + ch * 8;
            CP16(dst, src);
        }
    }
    __device__ __forceinline__ void compute(int s) {
        uint32_t stg = smbase + (uint32_t)s * SSTG * 2;
        #pragma unroll
        for (int ks = 0; ks < 2; ks++) {
            int koff = ks * 16 + ((lane >> 4) << 3);
            int chunk = koff >> 3;
            int arow = wm + (lane & 15);
            uint32_t ah[4][4], al[4][4];
            #pragma unroll
            for (int mf = 0; mf < 4; mf++) {
                int row = arow + mf * 16;
                uint32_t off = swz(row, chunk) * 2;
                LDSM4(ah[mf][0], ah[mf][1], ah[mf][2], ah[mf][3], stg + 0 * SARR * 2 + off);
                LDSM4(al[mf][0], al[mf][1], al[mf][2], al[mf][3], stg + 1 * SARR * 2 + off);
            }
            uint32_t bh[4][2], bl[4][2];
            #pragma unroll
            for (int jp = 0; jp < 4; jp += 2) {
                int brow = wn + jp * 8 + (lane & 15);
                uint32_t off = swz(brow, chunk) * 2;
                uint32_t r0, r1, r2, r3;
                LDSM4(r0, r1, r2, r3, stg + 2 * SARR * 2 + off);
                bh[jp][0] = r0; bh[jp + 1][0] = r1; bh[jp][1] = r2; bh[jp + 1][1] = r3;
                if (BL) {
                    LDSM4(r0, r1, r2, r3, stg + 3 * SARR * 2 + off);
                    bl[jp][0] = r0; bl[jp + 1][0] = r1; bl[jp][1] = r2; bl[jp + 1][1] = r3;
                }
            }
            #pragma unroll
            for (int mf = 0; mf < 4; mf++)
                #pragma unroll
                for (int nf = 0; nf < 4; nf++)
                    MMA16816(acc[mf][nf], ah[mf][0], ah[mf][1], ah[mf][2], ah[mf][3], bh[nf][0], bh[nf][1]);
            #pragma unroll
            for (int mf = 0; mf < 4; mf++)
                #pragma unroll
                for (int nf = 0; nf < 4; nf++)
                    MMA16816(acc[mf][nf], al[mf][0], al[mf][1], al[mf][2], al[mf][3], bh[nf][0], bh[nf][1]);
            if (BL) {
                #pragma unroll
                for (int mf = 0; mf < 4; mf++)
                    #pragma unroll
                    for (int nf = 0; nf < 4; nf++)
                        MMA16816(acc[mf][nf], ah[mf][0], ah[mf][1], ah[mf][2], ah[mf][3], bl[nf][0], bl[nf][1]);
            }
        }
    }
    __device__ __forceinline__ void run(const __half* Agh, const __half* Agl,
                                        const __half* Bgh, const __half* Bgl,
                                        int am0, int bn0) {
        issue(Agh, Agl, Bgh, Bgl, am0, bn0, 0, 0);  CP_COMMIT();
        issue(Agh, Agl, Bgh, Bgl, am0, bn0, 32, 1); CP_COMMIT();
        int s = 0, sn = 2;
        for (int it = 0; it < 32; it++) {
            if (it < 31) { CP_WAIT1(); } else { CP_WAIT0(); }
            __syncthreads();
            if (it + 2 < 32) {
                issue(Agh, Agl, Bgh, Bgl, am0, bn0, (it + 2) * 32, sn);
                CP_COMMIT();
            }
            compute(s);
            s = (s == 2) ? 0 : s + 1;
            sn = (sn == 2) ? 0 : sn + 1;
        }
    }
};

__global__ void __launch_bounds__(256) bfgemmQKV_k() {
    extern __shared__ __half SM[];
    GemmCore<1> g;
    g.init(SM, threadIdx.x);
    int bm = blockIdx.y, bn = blockIdx.x;
    g.run(g_ah, g_al, g_wth, g_wtl, bm * 128, bn * 128);

    float* C; int Ntot, colb;
    if (bn < 8)       { C = g_q; Ntot = 1024; colb = bn * 128; }
    else if (bn < 10) { C = g_k; Ntot = 256;  colb = (bn - 8) * 128; }
    else              { C = g_v; Ntot = 256;  colb = (bn - 10) * 128; }
    #pragma unroll
    for (int mf = 0; mf < 4; mf++) {
        int r0 = bm * 128 + g.wm + mf * 16 + (g.lane >> 2);
        int r1 = r0 + 8;
        #pragma unroll
        for (int nf = 0; nf < 4; nf++) {
            int col = colb + g.wn + nf * 8 + (g.lane & 3) * 2;
            *(float2*)(C + (size_t)r0 * Ntot + col) = make_float2(g.acc[mf][nf][0], g.acc[mf][nf][1]);
            *(float2*)(C + (size_t)r1 * Ntot + col) = make_float2(g.acc[mf][nf][2], g.acc[mf][nf][3]);
        }
    }
}

__global__ void __launch_bounds__(256) bfgemmO_k(float* __restrict__ C) {
    extern __shared__ __half SM[];
    GemmCore<0> g;   // 2-term: A fully split, Wo hi only
    g.init(SM, threadIdx.x);
    int bm = blockIdx.y, bn = blockIdx.x;
    g.run(g_ah, g_al, g_wth + (size_t)1536 * 1024, g_wtl, bm * 128, bn * 128);
    #pragma unroll
    for (int mf = 0; mf < 4; mf++) {
        int r0 = remap_bpt(bm * 128 + g.wm + mf * 16 + (g.lane >> 2));
        int r1 = remap_bpt(bm * 128 + g.wm + mf * 16 + (g.lane >> 2) + 8);
        #pragma unroll
        for (int nf = 0; nf < 4; nf++) {
            int col = bn * 128 + g.wn + nf * 8 + (g.lane & 3) * 2;
            *(float2*)(C + (size_t)r0 * 1024 + col) = make_float2(g.acc[mf][nf][0], g.acc[mf][nf][1]);
            *(float2*)(C + (size_t)r1 * 1024 + col) = make_float2(g.acc[mf][nf][2], g.acc[mf][nf][3]);
        }
    }
}

// ---------------------------------------------------------------------------
// Flash attention: QK 3-term fp16, PV 2-term (V hi only). Epilogue -> g_ah/g_al.
// ---------------------------------------------------------------------------
#define KSTR 72
__global__ void __launch_bounds__(128, 3) attn3_k() {
    extern __shared__ __half ASM[];
    const int STG = 3 * 64 * KSTR;   // 3 arrays now (Khi, Klo, Vth)

    int tid = threadIdx.x, wid = tid >> 5, lane = tid & 31;
    int bph = blockIdx.y, h = bph & 15, bp = bph >> 4, hkv = h >> 2;
    int qt0 = blockIdx.x << 6;
    int qrow0 = bp * 512 + qt0;
    size_t vbase = (size_t)(bp * 4 + hkv) * 32768;

    {
        #pragma unroll
        for (int i = 0; i < 8; i++) {
            int half_ = i >> 2;
            int cc = (i & 3) * 128 + tid;
            int r = cc >> 3, kc = (cc & 7) * 8;
            uint32_t dst = smem_u32(ASM + half_ * 64 * KSTR + r * KSTR + kc);
            const __half* src = (half_ ? g_ql : g_qh) + (size_t)(qrow0 + r) * 1024 + h * 64 + kc;
            CP16(dst, src);
        }
        CP_COMMIT(); CP_WAIT0();
        __syncthreads();
    }
    uint32_t qh[4][4], ql[4][4];
    {
        __half* Qhi = ASM;
        __half* Qlo = ASM + 64 * KSTR;
        int row = wid * 16 + (lane & 15);
        #pragma unroll
        for (int ks = 0; ks < 4; ks++) {
            int koff = ks * 16 + ((lane >> 4) << 3);
            LDSM4(qh[ks][0], qh[ks][1], qh[ks][2], qh[ks][3], smem_u32(&Qhi[row * KSTR + koff]));
            LDSM4(ql[ks][0], ql[ks][1], ql[ks][2], ql[ks][3], smem_u32(&Qlo[row * KSTR + koff]));
        }
    }
    __syncthreads();

    auto issue = [&](int it, int s) {
        __half* stg = ASM + s * STG;
        int kt = it * 64;
        #pragma unroll
        for (int i = 0; i < 12; i++) {
            int arr = i >> 2;
            int cc = (i & 3) * 128 + tid;
            int r = cc >> 3, kc = (cc & 7) * 8;
            uint32_t dst = smem_u32(stg + arr * 64 * KSTR + r * KSTR + kc);
            const __half* src;
            if (arr == 0)      src = g_kh + (size_t)(bp * 512 + kt + r) * 256 + hkv * 64 + kc;
            else if (arr == 1) src = g_kl + (size_t)(bp * 512 + kt + r) * 256 + hkv * 64 + kc;
            else               src = g_vth + vbase + (size_t)r * 512 + kt + kc;
            CP16(dst, src);
        }
    };

    float o[8][4];
    #pragma unroll
    for (int nf = 0; nf < 8; nf++)
        #pragma unroll
        for (int c = 0; c < 4; c++) o[nf][c] = 0.f;
    float m0 = -INFINITY, m1 = -INFINITY, l0 = 0.f, l1 = 0.f;

    issue(0, 0);
    CP_COMMIT();

    for (int it = 0; it < 8; it++) {
        CP_WAIT0();
        __syncthreads();
        if (it + 1 < 8) { issue(it + 1, (it + 1) & 1); CP_COMMIT(); }

        __half* stg = ASM + (it & 1) * STG;
        __half* Khi = stg;
        __half* Klo = stg + 64 * KSTR;
        __half* Vth = stg + 2 * 64 * KSTR;

        float s[8][4];
        #pragma unroll
        for (int nf = 0; nf < 8; nf++)
            #pragma unroll
            for (int c = 0; c < 4; c++) s[nf][c] = 0.f;

        #pragma unroll
        for (int ks = 0; ks < 4; ks++) {
            int koff = ks * 16 + ((lane >> 4) << 3);
            #pragma unroll
            for (int jp = 0; jp < 8; jp += 2) {
                int brow = jp * 8 + (lane & 15);
                uint32_t r0, r1, r2, r3, t0, t1, t2, t3;
                LDSM4(r0, r1, r2, r3, smem_u32(&Khi[brow * KSTR + koff]));
                LDSM4(t0, t1, t2, t3, smem_u32(&Klo[brow * KSTR + koff]));
                MMA16816(s[jp],     qh[ks][0], qh[ks][1], qh[ks][2], qh[ks][3], r0, r2);
                MMA16816(s[jp + 1], qh[ks][0], qh[ks][1], qh[ks][2], qh[ks][3], r1, r3);
                MMA16816(s[jp],     qh[ks][0], qh[ks][1], qh[ks][2], qh[ks][3], t0, t2);
                MMA16816(s[jp + 1], qh[ks][0], qh[ks][1], qh[ks][2], qh[ks][3], t1, t3);
                MMA16816(s[jp],     ql[ks][0], ql[ks][1], ql[ks][2], ql[ks][3], r0, r2);
                MMA16816(s[jp + 1], ql[ks][0], ql[ks][1], ql[ks][2], ql[ks][3], r1, r3);
            }
        }

        float rmax0 = -INFINITY, rmax1 = -INFINITY;
        #pragma unroll
        for (int nf = 0; nf < 8; nf++) {
            rmax0 = fmaxf(rmax0, fmaxf(s[nf][0], s[nf][1]));
            rmax1 = fmaxf(rmax1, fmaxf(s[nf][2], s[nf][3]));
        }
        rmax0 = fmaxf(rmax0, __shfl_xor_sync(0xffffffffu, rmax0, 1));
        rmax0 = fmaxf(rmax0, __shfl_xor_sync(0xffffffffu, rmax0, 2));
        rmax1 = fmaxf(rmax1, __shfl_xor_sync(0xffffffffu, rmax1, 1));
        rmax1 = fmaxf(rmax1, __shfl_xor_sync(0xffffffffu, rmax1, 2));
        float mn0 = fmaxf(m0, rmax0), mn1 = fmaxf(m1, rmax1);
        float al0 = exp2f(m0 - mn0), al1 = exp2f(m1 - mn1);
        float ps0 = 0.f, ps1 = 0.f;
        #pragma unroll
        for (int nf = 0; nf < 8; nf++) {
            s[nf][0] = exp2f(s[nf][0] - mn0); ps0 += s[nf][0];
            s[nf][1] = exp2f(s[nf][1] - mn0); ps0 += s[nf][1];
            s[nf][2] = exp2f(s[nf][2] - mn1); ps1 += s[nf][2];
            s[nf][3] = exp2f(s[nf][3] - mn1); ps1 += s[nf][3];
        }
        l0 = l0 * al0 + ps0; l1 = l1 * al1 + ps1;
        m0 = mn0; m1 = mn1;
        #pragma unroll
        for (int nf = 0; nf < 8; nf++) {
            o[nf][0] *= al0; o[nf][1] *= al0;
            o[nf][2] *= al1; o[nf][3] *= al1;
        }

        #pragma unroll
        for (int ks = 0; ks < 4; ks++) {
            float* pa = s[2 * ks];
            float* pb = s[2 * ks + 1];
            float ha0 = __half2float(__float2half_rn(pa[0]));
            float ha1 = __half2float(__float2half_rn(pa[1]));
            float ha2 = __half2float(__float2half_rn(pa[2]));
            float ha3 = __half2float(__float2half_rn(pa[3]));
            float hb0 = __half2float(__float2half_rn(pb[0]));
            float hb1 = __half2float(__float2half_rn(pb[1]));
            float hb2 = __half2float(__float2half_rn(pb[2]));
            float hb3 = __half2float(__float2half_rn(pb[3]));
            uint32_t ah0 = pk_h2(ha0, ha1), ah1 = pk_h2(ha2, ha3);
            uint32_t ah2 = pk_h2(hb0, hb1), ah3 = pk_h2(hb2, hb3);
            uint32_t pl0 = pk_h2(pa[0] - ha0, pa[1] - ha1);
            uint32_t pl1 = pk_h2(pa[2] - ha2, pa[3] - ha3);
            uint32_t pl2 = pk_h2(pb[0] - hb0, pb[1] - hb1);
            uint32_t pl3 = pk_h2(pb[2] - hb2, pb[3] - hb3);

            int koff = ks * 16 + ((lane >> 4) << 3);
            #pragma unroll
            for (int jp = 0; jp < 8; jp += 2) {
                int brow = jp * 8 + (lane & 15);
                uint32_t r0, r1, r2, r3;
                LDSM4(r0, r1, r2, r3, smem_u32(&Vth[brow * KSTR + koff]));
                MMA16816(o[jp],     ah0, ah1, ah2, ah3, r0, r2);
                MMA16816(o[jp + 1], ah0, ah1, ah2, ah3, r1, r3);
                MMA16816(o[jp],     pl0, pl1, pl2, pl3, r0, r2);
                MMA16816(o[jp + 1], pl0, pl1, pl2, pl3, r1, r3);
            }
        }
        __syncthreads();
    }

    l0 += __shfl_xor_sync(0xffffffffu, l0, 1);
    l0 += __shfl_xor_sync(0xffffffffu, l0, 2);
    l1 += __shfl_xor_sync(0xffffffffu, l1, 1);
    l1 += __shfl_xor_sync(0xffffffffu, l1, 2);
    float inv0 = 1.f / l0, inv1 = 1.f / l1;

    int row0 = qrow0 + wid * 16 + (lane >> 2);
    size_t b0 = (size_t)row0 * 1024 + h * 64 + (lane & 3) * 2;
    size_t b1 = b0 + 8 * 1024;
    #pragma unroll
    for (int nf = 0; nf < 8; nf++) {
        float x0 = o[nf][0] * inv0, y0 = o[nf][1] * inv0;
        float hx0 = __half2float(__float2half_rn(x0));
        float hy0 = __half2float(__float2half_rn(y0));
        *(uint32_t*)&g_ah[b0 + nf * 8] = pk_h2(hx0, hy0);
        *(uint32_t*)&g_al[b0 + nf * 8] = pk_h2(x0 - hx0, y0 - hy0);
        float x1 = o[nf][2] * inv1, y1 = o[nf][3] * inv1;
        float hx1 = __half2float(__float2half_rn(x1));
        float hy1 = __half2float(__float2half_rn(y1));
        *(uint32_t*)&g_ah[b1 + nf * 8] = pk_h2(hx1, hy1);
        *(uint32_t*)&g_al[b1 + nf * 8] = pk_h2(x1 - hx1, y1 - hy1);
    }
}

// ---------------------------------------------------------------------------
extern "C" void kernel_launch(void* const* d_in, const int* in_sizes, int n_in,
                              void* d_out, int out_size) {
    (void)in_sizes; (void)n_in; (void)out_size;
    const float* hidden = (const float*)d_in[0];
    const float* Wq = (const float*)d_in[1];
    const float* Wk = (const float*)d_in[2];
    const float* Wv = (const float*)d_in[3];
    const float* Wo = (const float*)d_in[4];
    float* out = (float*)d_out;

    const int gsm = 3 * SSTG * 2;             // 98304 B
    const int asm_ = 2 * 3 * 64 * KSTR * 2;   // 55296 B (3 arrays per stage)
    cudaFuncSetAttribute(bfgemmQKV_k, cudaFuncAttributeMaxDynamicSharedMemorySize, gsm);
    cudaFuncSetAttribute(bfgemmO_k, cudaFuncAttributeMaxDynamicSharedMemorySize, gsm);
    cudaFuncSetAttribute(attn3_k, cudaFuncAttributeMaxDynamicSharedMemorySize, asm_);

    // 0: Wo transpose+split (independent)
    transWo_k<<<1024, 256>>>(Wo);
    // 1: convert hidden (remap)
    convAin_k<<<8192, 256>>>(hidden);
    // 2: Wq + Wk + Wv transpose+split
    transWqkv_k<<<3072, 256>>>(Wq, Wk, Wv);
    // 3: fused QKV projection  <- capture slot
    bfgemmQKV_k<<<dim3(12, 64), 256, gsm>>>();
    // 4: rope+split + V transpose
    prep2_k<<<22528, 256>>>();
    // 5: attention (QK 3-term, PV 2-term; writes fp16 hi/lo to g_ah/g_al)
    attn3_k<<<dim3(8, 256), 128, asm_>>>();
    // 6: output projection (2-term)
    bfgemmO_k<<<dim3(8, 64), 256, gsm>>>(out);
}

// round 13
// speedup vs baseline: 5.3321x; 1.1613x over previous
#include <cuda_runtime.h>
#include <cuda_fp16.h>
#include <cstdint>
#include <math.h>

#define NTOK 8192

// fp32 intermediates
__device__ float g_q[NTOK * 1024];
__device__ float g_k[NTOK * 256];
__device__ float g_v[NTOK * 256];
// fp16 hi/lo preconverted operands
__device__ __half g_ah[NTOK * 1024], g_al[NTOK * 1024];
__device__ __half g_qh[NTOK * 1024], g_ql[NTOK * 1024];
__device__ __half g_kh[NTOK * 256],  g_kl[NTOK * 256];
__device__ __half g_vth[NTOK * 256];
__device__ __half g_wth[2560 * 1024];   // QKV rows 0-1535, Wo rows 1536-2559 (hi only)

__device__ __forceinline__ int remap_bpt(int r) {
    int b = r >> 12, p = (r >> 9) & 7, t = r & 511;
    return (b << 12) + (t << 3) + p;
}
__device__ __forceinline__ uint32_t smem_u32(const void* p) {
    uint32_t a;
    asm("{ .reg .u64 t; cvta.to.shared.u64 t, %1; cvt.u32.u64 %0, t; }" : "=r"(a) : "l"(p));
    return a;
}
#define LDSM4(r0, r1, r2, r3, a) \
    asm volatile("ldmatrix.sync.aligned.m8n8.x4.shared.b16 {%0,%1,%2,%3}, [%4];" \
        : "=r"(r0), "=r"(r1), "=r"(r2), "=r"(r3) : "r"(a))
#define MMA16816(c, a0, a1, a2, a3, b0, b1) \
    asm volatile("mma.sync.aligned.m16n8k16.row.col.f32.f16.f16.f32 " \
        "{%0,%1,%2,%3},{%4,%5,%6,%7},{%8,%9},{%0,%1,%2,%3};" \
        : "+f"((c)[0]), "+f"((c)[1]), "+f"((c)[2]), "+f"((c)[3]) \
        : "r"(a0), "r"(a1), "r"(a2), "r"(a3), "r"(b0), "r"(b1))
#define CP16(dst, src) \
    asm volatile("cp.async.cg.shared.global [%0], [%1], 16;" :: "r"(dst), "l"(src))
#define CP_COMMIT() asm volatile("cp.async.commit_group;" ::: "memory")
#define CP_WAIT1()  asm volatile("cp.async.wait_group 1;" ::: "memory")
#define CP_WAIT0()  asm volatile("cp.async.wait_group 0;" ::: "memory")

__device__ __forceinline__ uint32_t pk_h2(float x, float y) {
    __half2 h = __floats2half2_rn(x, y);
    return *(uint32_t*)&h;
}
__device__ __forceinline__ void split_store4(float4 v, void* ph, void* pl) {
    float hx = __half2float(__float2half_rn(v.x));
    float hy = __half2float(__float2half_rn(v.y));
    float hz = __half2float(__float2half_rn(v.z));
    float hw = __half2float(__float2half_rn(v.w));
    *(uint2*)ph = make_uint2(pk_h2(hx, hy), pk_h2(hz, hw));
    *(uint2*)pl = make_uint2(pk_h2(v.x - hx, v.y - hy), pk_h2(v.z - hz, v.w - hw));
}

// ---------------- prep bodies ----------------
__device__ __forceinline__ void convA_body(const float* __restrict__ src, int blk, int tid) {
    int idx = blk * 256 + tid;
    int row = idx >> 8, c4 = (idx & 255) * 4;
    int srow = remap_bpt(row);
    float4 v = *(const float4*)(src + (size_t)srow * 1024 + c4);
    split_store4(v, &g_ah[(size_t)row * 1024 + c4], &g_al[(size_t)row * 1024 + c4]);
}

// hi-only weight transpose
__device__ __forceinline__ void transhi_body(const float* __restrict__ in, int N,
                                             int rowoff, int bx, int by, int tid) {
    __shared__ float t[32][33];
    int n0 = bx * 32;
    if (n0 >= N) return;
    int k0 = by * 32, x = tid & 31, y = tid >> 5;
    for (int j = y; j < 32; j += 8)
        t[j][x] = in[(size_t)(k0 + j) * N + n0 + x];
    __syncthreads();
    for (int j = y; j < 32; j += 8)
        g_wth[(size_t)(rowoff + n0 + j) * 1024 + k0 + x] = __float2half_rn(t[x][j]);
}

__global__ void __launch_bounds__(256) transWo_k(const float* __restrict__ Wo) {
    int r = blockIdx.x;
    transhi_body(Wo, 1024, 1536, r & 31, r >> 5, threadIdx.x);
}
__global__ void __launch_bounds__(256) convAin_k(const float* __restrict__ hidden) {
    convA_body(hidden, blockIdx.x, threadIdx.x);
}
__global__ void __launch_bounds__(256) transWqkv_k(const float* __restrict__ Wq,
                                                   const float* __restrict__ Wk,
                                                   const float* __restrict__ Wv) {
    int b = blockIdx.x;
    int z = b >> 10, r = b & 1023;
    const float* in = (z == 0) ? Wq : (z == 1) ? Wk : Wv;
    int N = (z == 0) ? 1024 : 256;
    int rowoff = (z == 0) ? 0 : (z == 1) ? 1024 : 1280;
    transhi_body(in, N, rowoff, r & 31, r >> 5, threadIdx.x);
}
__global__ void __launch_bounds__(256) prep2_k() {
    __shared__ float t[32][33];
    int b = blockIdx.x, tid = threadIdx.x;
    if (b < 20480) {
        int idx = b * 256 + tid;
        const int QP = NTOK * 16 * 32;
        const float* base;
        __half *oh, *ol;
        int i, tok;
        float scale;
        if (idx < QP) {
            i = idx & 31;
            int r = idx >> 5;
            tok = r >> 4;
            size_t off = (size_t)tok * 1024 + (r & 15) * 64;
            base = g_q + off; oh = g_qh + off; ol = g_ql + off;
            scale = 0.125f * 1.4426950408889634f;
        } else {
            int j = idx - QP;
            i = j & 31;
            int r = j >> 5;
            tok = r >> 2;
            size_t off = (size_t)tok * 256 + (r & 3) * 64;
            base = g_k + off; oh = g_kh + off; ol = g_kl + off;
            scale = 1.0f;
        }
        int tt = tok & 511;
        float invf = expf(-(float)i * 0.28782313662425574f);
        float ang = (float)tt * invf, s, c;
        sincosf(ang, &s, &c);
        float x1 = base[i], x2 = base[i + 32];
        float y1 = (x1 * c - x2 * s) * scale;
        float y2 = (x1 * s + x2 * c) * scale;
        float h1 = __half2float(__float2half_rn(y1));
        float h2 = __half2float(__float2half_rn(y2));
        oh[i]      = __float2half_rn(h1);
        ol[i]      = __float2half_rn(y1 - h1);
        oh[i + 32] = __float2half_rn(h2);
        ol[i + 32] = __float2half_rn(y2 - h2);
        return;
    }
    int idx = b - 20480;
    int bx = idx & 15, by = (idx >> 4) & 1, g = idx >> 5;
    int bp = g >> 2, hkv = g & 3;
    int k0 = bx * 32, d0 = by * 32, x = tid & 31, y = tid >> 5;
    for (int j = y; j < 32; j += 8)
        t[j][x] = g_v[(size_t)(bp * 512 + k0 + j) * 256 + hkv * 64 + d0 + x];
    __syncthreads();
    for (int j = y; j < 32; j += 8) {
        size_t o = (size_t)g * 32768 + (size_t)(d0 + j) * 512 + k0 + x;
        g_vth[o] = __float2half_rn(t[x][j]);
    }
}

// ---------------------------------------------------------------------------
// GEMM core: 2-term (Ah·Bh + Al·Bh), 3-stage cp.async, XOR-swizzled smem.
// Stage = 3 arrays (Ah, Al, Bh) x 128 x 32 fp16 = 24KB; 3 stages = 72KB.
// ---------------------------------------------------------------------------
#define SARR 4096
#define SSTG 12288

struct GemmCore {
    uint32_t smbase;
    int tid, wid, lane, wm, wn;
    float acc[4][4][4];

    __device__ __forceinline__ void init(const __half* sm, int t) {
        smbase = smem_u32(sm);
        tid = t; wid = t >> 5; lane = t & 31;
        wm = (wid >> 2) * 64; wn = (wid & 3) * 32;
        #pragma unroll
        for (int i = 0; i < 4; i++)
            #pragma unroll
            for (int j = 0; j < 4; j++)
                #pragma unroll
                for (int q = 0; q < 4; q++) acc[i][j][q] = 0.f;
    }
    __device__ __forceinline__ static uint32_t swz(int row, int chunk) {
        return (uint32_t)(row * 32 + ((chunk ^ ((row >> 1) & 3)) << 3));
    }
    __device__ __forceinline__ void issue(const __half* Agh, const __half* Agl,
                                          const __half* Bgh,
                                          int am0, int bn0, int k0, int s) {
        uint32_t stg = smbase + (uint32_t)s * SSTG * 2;
        #pragma unroll
        for (int i = 0; i < 6; i++) {
            int arr = i >> 1;
            int cc = (i & 1) * 256 + tid;
            int r = cc >> 2, ch = cc & 3;
            uint32_t dst = stg + (arr * SARR + swz(r, ch)) * 2;
            const __half* src;
            if (arr == 0)      src = Agh + (size_t)(am0 + r) * 1024 + k0 + ch * 8;
            else if (arr == 1) src = Agl + (size_t)(am0 + r) * 1024 + k0 + ch * 8;
            else               src = Bgh + (size_t)(bn0 + r) * 1024 + k0 + ch * 8;
            CP16(dst, src);
        }
    }
    __device__ __forceinline__ void compute(int s) {
        uint32_t stg = smbase + (uint32_t)s * SSTG * 2;
        #pragma unroll
        for (int ks = 0; ks < 2; ks++) {
            int koff = ks * 16 + ((lane >> 4) << 3);
            int chunk = koff >> 3;
            int arow = wm + (lane & 15);
            uint32_t ah[4][4], al[4][4];
            #pragma unroll
            for (int mf = 0; mf < 4; mf++) {
                int row = arow + mf * 16;
                uint32_t off = swz(row, chunk) * 2;
                LDSM4(ah[mf][0], ah[mf][1], ah[mf][2], ah[mf][3], stg + 0 * SARR * 2 + off);
                LDSM4(al[mf][0], al[mf][1], al[mf][2], al[mf][3], stg + 1 * SARR * 2 + off);
            }
            uint32_t bh[4][2];
            #pragma unroll
            for (int jp = 0; jp < 4; jp += 2) {
                int brow = wn + jp * 8 + (lane & 15);
                uint32_t off = swz(brow, chunk) * 2;
                uint32_t r0, r1, r2, r3;
                LDSM4(r0, r1, r2, r3, stg + 2 * SARR * 2 + off);
                bh[jp][0] = r0; bh[jp + 1][0] = r1; bh[jp][1] = r2; bh[jp + 1][1] = r3;
            }
            #pragma unroll
            for (int mf = 0; mf < 4; mf++)
                #pragma unroll
                for (int nf = 0; nf < 4; nf++)
                    MMA16816(acc[mf][nf], ah[mf][0], ah[mf][1], ah[mf][2], ah[mf][3], bh[nf][0], bh[nf][1]);
            #pragma unroll
            for (int mf = 0; mf < 4; mf++)
                #pragma unroll
                for (int nf = 0; nf < 4; nf++)
                    MMA16816(acc[mf][nf], al[mf][0], al[mf][1], al[mf][2], al[mf][3], bh[nf][0], bh[nf][1]);
        }
    }
    __device__ __forceinline__ void run(const __half* Agh, const __half* Agl,
                                        const __half* Bgh, int am0, int bn0) {
        issue(Agh, Agl, Bgh, am0, bn0, 0, 0);  CP_COMMIT();
        issue(Agh, Agl, Bgh, am0, bn0, 32, 1); CP_COMMIT();
        int s = 0, sn = 2;
        for (int it = 0; it < 32; it++) {
            if (it < 31) { CP_WAIT1(); } else { CP_WAIT0(); }
            __syncthreads();
            if (it + 2 < 32) {
                issue(Agh, Agl, Bgh, am0, bn0, (it + 2) * 32, sn);
                CP_COMMIT();
            }
            compute(s);
            s = (s == 2) ? 0 : s + 1;
            sn = (sn == 2) ? 0 : sn + 1;
        }
    }
};

__global__ void __launch_bounds__(256) bfgemmQKV_k() {
    extern __shared__ __half SM[];
    GemmCore g;
    g.init(SM, threadIdx.x);
    int bm = blockIdx.y, bn = blockIdx.x;
    g.run(g_ah, g_al, g_wth, bm * 128, bn * 128);

    float* C; int Ntot, colb;
    if (bn < 8)       { C = g_q; Ntot = 1024; colb = bn * 128; }
    else if (bn < 10) { C = g_k; Ntot = 256;  colb = (bn - 8) * 128; }
    else              { C = g_v; Ntot = 256;  colb = (bn - 10) * 128; }
    #pragma unroll
    for (int mf = 0; mf < 4; mf++) {
        int r0 = bm * 128 + g.wm + mf * 16 + (g.lane >> 2);
        int r1 = r0 + 8;
        #pragma unroll
        for (int nf = 0; nf < 4; nf++) {
            int col = colb + g.wn + nf * 8 + (g.lane & 3) * 2;
            *(float2*)(C + (size_t)r0 * Ntot + col) = make_float2(g.acc[mf][nf][0], g.acc[mf][nf][1]);
            *(float2*)(C + (size_t)r1 * Ntot + col) = make_float2(g.acc[mf][nf][2], g.acc[mf][nf][3]);
        }
    }
}

__global__ void __launch_bounds__(256) bfgemmO_k(float* __restrict__ C) {
    extern __shared__ __half SM[];
    GemmCore g;
    g.init(SM, threadIdx.x);
    int bm = blockIdx.y, bn = blockIdx.x;
    g.run(g_ah, g_al, g_wth + (size_t)1536 * 1024, bm * 128, bn * 128);
    #pragma unroll
    for (int mf = 0; mf < 4; mf++) {
        int r0 = remap_bpt(bm * 128 + g.wm + mf * 16 + (g.lane >> 2));
        int r1 = remap_bpt(bm * 128 + g.wm + mf * 16 + (g.lane >> 2) + 8);
        #pragma unroll
        for (int nf = 0; nf < 4; nf++) {
            int col = bn * 128 + g.wn + nf * 8 + (g.lane & 3) * 2;
            *(float2*)(C + (size_t)r0 * 1024 + col) = make_float2(g.acc[mf][nf][0], g.acc[mf][nf][1]);
            *(float2*)(C + (size_t)r1 * 1024 + col) = make_float2(g.acc[mf][nf][2], g.acc[mf][nf][3]);
        }
    }
}

// ---------------------------------------------------------------------------
// Flash attention: QK 3-term fp16, PV 2-term (unchanged from R12).
// ---------------------------------------------------------------------------
#define KSTR 72
__global__ void __launch_bounds__(128, 3) attn3_k() {
    extern __shared__ __half ASM[];
    const int STG = 3 * 64 * KSTR;

    int tid = threadIdx.x, wid = tid >> 5, lane = tid & 31;
    int bph = blockIdx.y, h = bph & 15, bp = bph >> 4, hkv = h >> 2;
    int qt0 = blockIdx.x << 6;
    int qrow0 = bp * 512 + qt0;
    size_t vbase = (size_t)(bp * 4 + hkv) * 32768;

    {
        #pragma unroll
        for (int i = 0; i < 8; i++) {
            int half_ = i >> 2;
            int cc = (i & 3) * 128 + tid;
            int r = cc >> 3, kc = (cc & 7) * 8;
            uint32_t dst = smem_u32(ASM + half_ * 64 * KSTR + r * KSTR + kc);
            const __half* src = (half_ ? g_ql : g_qh) + (size_t)(qrow0 + r) * 1024 + h * 64 + kc;
            CP16(dst, src);
        }
        CP_COMMIT(); CP_WAIT0();
        __syncthreads();
    }
    uint32_t qh[4][4], ql[4][4];
    {
        __half* Qhi = ASM;
        __half* Qlo = ASM + 64 * KSTR;
        int row = wid * 16 + (lane & 15);
        #pragma unroll
        for (int ks = 0; ks < 4; ks++) {
            int koff = ks * 16 + ((lane >> 4) << 3);
            LDSM4(qh[ks][0], qh[ks][1], qh[ks][2], qh[ks][3], smem_u32(&Qhi[row * KSTR + koff]));
            LDSM4(ql[ks][0], ql[ks][1], ql[ks][2], ql[ks][3], smem_u32(&Qlo[row * KSTR + koff]));
        }
    }
    __syncthreads();

    auto issue = [&](int it, int s) {
        __half* stg = ASM + s * STG;
        int kt = it * 64;
        #pragma unroll
        for (int i = 0; i < 12; i++) {
            int arr = i >> 2;
            int cc = (i & 3) * 128 + tid;
            int r = cc >> 3, kc = (cc & 7) * 8;
            uint32_t dst = smem_u32(stg + arr * 64 * KSTR + r * KSTR + kc);
            const __half* src;
            if (arr == 0)      src = g_kh + (size_t)(bp * 512 + kt + r) * 256 + hkv * 64 + kc;
            else if (arr == 1) src = g_kl + (size_t)(bp * 512 + kt + r) * 256 + hkv * 64 + kc;
            else               src = g_vth + vbase + (size_t)r * 512 + kt + kc;
            CP16(dst, src);
        }
    };

    float o[8][4];
    #pragma unroll
    for (int nf = 0; nf < 8; nf++)
        #pragma unroll
        for (int c = 0; c < 4; c++) o[nf][c] = 0.f;
    float m0 = -INFINITY, m1 = -INFINITY, l0 = 0.f, l1 = 0.f;

    issue(0, 0);
    CP_COMMIT();

    for (int it = 0; it < 8; it++) {
        CP_WAIT0();
        __syncthreads();
        if (it + 1 < 8) { issue(it + 1, (it + 1) & 1); CP_COMMIT(); }

        __half* stg = ASM + (it & 1) * STG;
        __half* Khi = stg;
        __half* Klo = stg + 64 * KSTR;
        __half* Vth = stg + 2 * 64 * KSTR;

        float s[8][4];
        #pragma unroll
        for (int nf = 0; nf < 8; nf++)
            #pragma unroll
            for (int c = 0; c < 4; c++) s[nf][c] = 0.f;

        #pragma unroll
        for (int ks = 0; ks < 4; ks++) {
            int koff = ks * 16 + ((lane >> 4) << 3);
            #pragma unroll
            for (int jp = 0; jp < 8; jp += 2) {
                int brow = jp * 8 + (lane & 15);
                uint32_t r0, r1, r2, r3, t0, t1, t2, t3;
                LDSM4(r0, r1, r2, r3, smem_u32(&Khi[brow * KSTR + koff]));
                LDSM4(t0, t1, t2, t3, smem_u32(&Klo[brow * KSTR + koff]));
                MMA16816(s[jp],     qh[ks][0], qh[ks][1], qh[ks][2], qh[ks][3], r0, r2);
                MMA16816(s[jp + 1], qh[ks][0], qh[ks][1], qh[ks][2], qh[ks][3], r1, r3);
                MMA16816(s[jp],     qh[ks][0], qh[ks][1], qh[ks][2], qh[ks][3], t0, t2);
                MMA16816(s[jp + 1], qh[ks][0], qh[ks][1], qh[ks][2], qh[ks][3], t1, t3);
                MMA16816(s[jp],     ql[ks][0], ql[ks][1], ql[ks][2], ql[ks][3], r0, r2);
                MMA16816(s[jp + 1], ql[ks][0], ql[ks][1], ql[ks][2], ql[ks][3], r1, r3);
            }
        }

        float rmax0 = -INFINITY, rmax1 = -INFINITY;
        #pragma unroll
        for (int nf = 0; nf < 8; nf++) {
            rmax0 = fmaxf(rmax0, fmaxf(s[nf][0], s[nf][1]));
            rmax1 = fmaxf(rmax1, fmaxf(s[nf][2], s[nf][3]));
        }
        rmax0 = fmaxf(rmax0, __shfl_xor_sync(0xffffffffu, rmax0, 1));
        rmax0 = fmaxf(rmax0, __shfl_xor_sync(0xffffffffu, rmax0, 2));
        rmax1 = fmaxf(rmax1, __shfl_xor_sync(0xffffffffu, rmax1, 1));
        rmax1 = fmaxf(rmax1, __shfl_xor_sync(0xffffffffu, rmax1, 2));
        float mn0 = fmaxf(m0, rmax0), mn1 = fmaxf(m1, rmax1);
        float al0 = exp2f(m0 - mn0), al1 = exp2f(m1 - mn1);
        float ps0 = 0.f, ps1 = 0.f;
        #pragma unroll
        for (int nf = 0; nf < 8; nf++) {
            s[nf][0] = exp2f(s[nf][0] - mn0); ps0 += s[nf][0];
            s[nf][1] = exp2f(s[nf][1] - mn0); ps0 += s[nf][1];
            s[nf][2] = exp2f(s[nf][2] - mn1); ps1 += s[nf][2];
            s[nf][3] = exp2f(s[nf][3] - mn1); ps1 += s[nf][3];
        }
        l0 = l0 * al0 + ps0; l1 = l1 * al1 + ps1;
        m0 = mn0; m1 = mn1;
        #pragma unroll
        for (int nf = 0; nf < 8; nf++) {
            o[nf][0] *= al0; o[nf][1] *= al0;
            o[nf][2] *= al1; o[nf][3] *= al1;
        }

        #pragma unroll
        for (int ks = 0; ks < 4; ks++) {
            float* pa = s[2 * ks];
            float* pb = s[2 * ks + 1];
            float ha0 = __half2float(__float2half_rn(pa[0]));
            float ha1 = __half2float(__float2half_rn(pa[1]));
            float ha2 = __half2float(__float2half_rn(pa[2]));
            float ha3 = __half2float(__float2half_rn(pa[3]));
            float hb0 = __half2float(__float2half_rn(pb[0]));
            float hb1 = __half2float(__float2half_rn(pb[1]));
            float hb2 = __half2float(__float2half_rn(pb[2]));
            float hb3 = __half2float(__float2half_rn(pb[3]));
            uint32_t ah0 = pk_h2(ha0, ha1), ah1 = pk_h2(ha2, ha3);
            uint32_t ah2 = pk_h2(hb0, hb1), ah3 = pk_h2(hb2, hb3);
            uint32_t pl0 = pk_h2(pa[0] - ha0, pa[1] - ha1);
            uint32_t pl1 = pk_h2(pa[2] - ha2, pa[3] - ha3);
            uint32_t pl2 = pk_h2(pb[0] - hb0, pb[1] - hb1);
            uint32_t pl3 = pk_h2(pb[2] - hb2, pb[3] - hb3);

            int koff = ks * 16 + ((lane >> 4) << 3);
            #pragma unroll
            for (int jp = 0; jp < 8; jp += 2) {
                int brow = jp * 8 + (lane & 15);
                uint32_t r0, r1, r2, r3;
                LDSM4(r0, r1, r2, r3, smem_u32(&Vth[brow * KSTR + koff]));
                MMA16816(o[jp],     ah0, ah1, ah2, ah3, r0, r2);
                MMA16816(o[jp + 1], ah0, ah1, ah2, ah3, r1, r3);
                MMA16816(o[jp],     pl0, pl1, pl2, pl3, r0, r2);
                MMA16816(o[jp + 1], pl0, pl1, pl2, pl3, r1, r3);
            }
        }
        __syncthreads();
    }

    l0 += __shfl_xor_sync(0xffffffffu, l0, 1);
    l0 += __shfl_xor_sync(0xffffffffu, l0, 2);
    l1 += __shfl_xor_sync(0xffffffffu, l1, 1);
    l1 += __shfl_xor_sync(0xffffffffu, l1, 2);
    float inv0 = 1.f / l0, inv1 = 1.f / l1;

    int row0 = qrow0 + wid * 16 + (lane >> 2);
    size_t b0 = (size_t)row0 * 1024 + h * 64 + (lane & 3) * 2;
    size_t b1 = b0 + 8 * 1024;
    #pragma unroll
    for (int nf = 0; nf < 8; nf++) {
        float x0 = o[nf][0] * inv0, y0 = o[nf][1] * inv0;
        float hx0 = __half2float(__float2half_rn(x0));
        float hy0 = __half2float(__float2half_rn(y0));
        *(uint32_t*)&g_ah[b0 + nf * 8] = pk_h2(hx0, hy0);
        *(uint32_t*)&g_al[b0 + nf * 8] = pk_h2(x0 - hx0, y0 - hy0);
        float x1 = o[nf][2] * inv1, y1 = o[nf][3] * inv1;
        float hx1 = __half2float(__float2half_rn(x1));
        float hy1 = __half2float(__float2half_rn(y1));
        *(uint32_t*)&g_ah[b1 + nf * 8] = pk_h2(hx1, hy1);
        *(uint32_t*)&g_al[b1 + nf * 8] = pk_h2(x1 - hx1, y1 - hy1);
    }
}

// ---------------------------------------------------------------------------
extern "C" void kernel_launch(void* const* d_in, const int* in_sizes, int n_in,
                              void* d_out, int out_size) {
    (void)in_sizes; (void)n_in; (void)out_size;
    const float* hidden = (const float*)d_in[0];
    const float* Wq = (const float*)d_in[1];
    const float* Wk = (const float*)d_in[2];
    const float* Wv = (const float*)d_in[3];
    const float* Wo = (const float*)d_in[4];
    float* out = (float*)d_out;

    const int gsm = 3 * SSTG * 2;             // 73728 B (3 stages x 24KB)
    const int asm_ = 2 * 3 * 64 * KSTR * 2;   // 55296 B
    cudaFuncSetAttribute(bfgemmQKV_k, cudaFuncAttributeMaxDynamicSharedMemorySize, gsm);
    cudaFuncSetAttribute(bfgemmO_k, cudaFuncAttributeMaxDynamicSharedMemorySize, gsm);
    cudaFuncSetAttribute(attn3_k, cudaFuncAttributeMaxDynamicSharedMemorySize, asm_);

    // 0: Wo transpose (hi only)
    transWo_k<<<1024, 256>>>(Wo);
    // 1: convert hidden (remap) to fp16 hi/lo
    convAin_k<<<8192, 256>>>(hidden);
    // 2: Wq + Wk + Wv transpose (hi only)
    transWqkv_k<<<3072, 256>>>(Wq, Wk, Wv);
    // 3: fused QKV projection, 2-term  <- capture slot
    bfgemmQKV_k<<<dim3(12, 64), 256, gsm>>>();
    // 4: rope+split + V transpose
    prep2_k<<<22528, 256>>>();
    // 5: attention (QK 3-term, PV 2-term)
    attn3_k<<<dim3(8, 256), 128, asm_>>>();
    // 6: output projection, 2-term
    bfgemmO_k<<<dim3(8, 64), 256, gsm>>>(out);
}

// round 14
// speedup vs baseline: 6.0826x; 1.1407x over previous
#include <cuda_runtime.h>
#include <cuda_fp16.h>
#include <cstdint>
#include <math.h>

#define NTOK 8192

// fp32 intermediates
__device__ float g_q[NTOK * 1024];
__device__ float g_k[NTOK * 256];
__device__ float g_v[NTOK * 256];
// fp16 hi/lo preconverted operands
__device__ __half g_ah[NTOK * 1024], g_al[NTOK * 1024];
__device__ __half g_qh[NTOK * 1024], g_ql[NTOK * 1024];
__device__ __half g_kh[NTOK * 256];
__device__ __half g_vth[NTOK * 256];
__device__ __half g_wth[2560 * 1024];   // QKV rows 0-1535, Wo rows 1536-2559 (hi only)

__device__ __forceinline__ int remap_bpt(int r) {
    int b = r >> 12, p = (r >> 9) & 7, t = r & 511;
    return (b << 12) + (t << 3) + p;
}
__device__ __forceinline__ uint32_t smem_u32(const void* p) {
    uint32_t a;
    asm("{ .reg .u64 t; cvta.to.shared.u64 t, %1; cvt.u32.u64 %0, t; }" : "=r"(a) : "l"(p));
    return a;
}
#define LDSM4(r0, r1, r2, r3, a) \
    asm volatile("ldmatrix.sync.aligned.m8n8.x4.shared.b16 {%0,%1,%2,%3}, [%4];" \
        : "=r"(r0), "=r"(r1), "=r"(r2), "=r"(r3) : "r"(a))
#define MMA16816(c, a0, a1, a2, a3, b0, b1) \
    asm volatile("mma.sync.aligned.m16n8k16.row.col.f32.f16.f16.f32 " \
        "{%0,%1,%2,%3},{%4,%5,%6,%7},{%8,%9},{%0,%1,%2,%3};" \
        : "+f"((c)[0]), "+f"((c)[1]), "+f"((c)[2]), "+f"((c)[3]) \
        : "r"(a0), "r"(a1), "r"(a2), "r"(a3), "r"(b0), "r"(b1))
#define CP16(dst, src) \
    asm volatile("cp.async.cg.shared.global [%0], [%1], 16;" :: "r"(dst), "l"(src))
#define CP_COMMIT() asm volatile("cp.async.commit_group;" ::: "memory")
#define CP_WAIT0()  asm volatile("cp.async.wait_group 0;" ::: "memory")

__device__ __forceinline__ uint32_t pk_h2(float x, float y) {
    __half2 h = __floats2half2_rn(x, y);
    return *(uint32_t*)&h;
}
__device__ __forceinline__ void split_store4(float4 v, void* ph, void* pl) {
    float hx = __half2float(__float2half_rn(v.x));
    float hy = __half2float(__float2half_rn(v.y));
    float hz = __half2float(__float2half_rn(v.z));
    float hw = __half2float(__float2half_rn(v.w));
    *(uint2*)ph = make_uint2(pk_h2(hx, hy), pk_h2(hz, hw));
    *(uint2*)pl = make_uint2(pk_h2(v.x - hx, v.y - hy), pk_h2(v.z - hz, v.w - hw));
}

// ---------------- prep ----------------
__global__ void __launch_bounds__(256) convAin_k(const float* __restrict__ hidden) {
    int idx = blockIdx.x * 256 + threadIdx.x;
    int row = idx >> 8, c4 = (idx & 255) * 4;
    int srow = remap_bpt(row);
    float4 v = *(const float4*)(hidden + (size_t)srow * 1024 + c4);
    split_store4(v, &g_ah[(size_t)row * 1024 + c4], &g_al[(size_t)row * 1024 + c4]);
}

__device__ __forceinline__ void transhi_body(const float* __restrict__ in, int N,
                                             int rowoff, int bx, int by, int tid) {
    __shared__ float t[32][33];
    int n0 = bx * 32;
    if (n0 >= N) return;
    int k0 = by * 32, x = tid & 31, y = tid >> 5;
    for (int j = y; j < 32; j += 8)
        t[j][x] = in[(size_t)(k0 + j) * N + n0 + x];
    __syncthreads();
    for (int j = y; j < 32; j += 8)
        g_wth[(size_t)(rowoff + n0 + j) * 1024 + k0 + x] = __float2half_rn(t[x][j]);
}
__global__ void __launch_bounds__(256) transWo_k(const float* __restrict__ Wo) {
    int r = blockIdx.x;
    transhi_body(Wo, 1024, 1536, r & 31, r >> 5, threadIdx.x);
}
__global__ void __launch_bounds__(256) transWqkv_k(const float* __restrict__ Wq,
                                                   const float* __restrict__ Wk,
                                                   const float* __restrict__ Wv) {
    int b = blockIdx.x;
    int z = b >> 10, r = b & 1023;
    const float* in = (z == 0) ? Wq : (z == 1) ? Wk : Wv;
    int N = (z == 0) ? 1024 : 256;
    int rowoff = (z == 0) ? 0 : (z == 1) ? 1024 : 1280;
    transhi_body(in, N, rowoff, r & 31, r >> 5, threadIdx.x);
}
__global__ void __launch_bounds__(256) prep2_k() {
    __shared__ float t[32][33];
    int b = blockIdx.x, tid = threadIdx.x;
    if (b < 20480) {
        int idx = b * 256 + tid;
        const int QP = NTOK * 16 * 32;
        int i, tok;
        if (idx < QP) {
            i = idx & 31;
            int r = idx >> 5;
            tok = r >> 4;
            size_t off = (size_t)tok * 1024 + (r & 15) * 64;
            const float* base = g_q + off;
            int tt = tok & 511;
            float invf = expf(-(float)i * 0.28782313662425574f);
            float ang = (float)tt * invf, s, c;
            sincosf(ang, &s, &c);
            const float scale = 0.125f * 1.4426950408889634f;
            float x1 = base[i], x2 = base[i + 32];
            float y1 = (x1 * c - x2 * s) * scale;
            float y2 = (x1 * s + x2 * c) * scale;
            float h1 = __half2float(__float2half_rn(y1));
            float h2 = __half2float(__float2half_rn(y2));
            g_qh[off + i]      = __float2half_rn(h1);
            g_ql[off + i]      = __float2half_rn(y1 - h1);
            g_qh[off + i + 32] = __float2half_rn(h2);
            g_ql[off + i + 32] = __float2half_rn(y2 - h2);
        } else {
            int j = idx - QP;
            i = j & 31;
            int r = j >> 5;
            tok = r >> 2;
            size_t off = (size_t)tok * 256 + (r & 3) * 64;
            const float* base = g_k + off;
            int tt = tok & 511;
            float invf = expf(-(float)i * 0.28782313662425574f);
            float ang = (float)tt * invf, s, c;
            sincosf(ang, &s, &c);
            float x1 = base[i], x2 = base[i + 32];
            g_kh[off + i]      = __float2half_rn(x1 * c - x2 * s);
            g_kh[off + i + 32] = __float2half_rn(x1 * s + x2 * c);
        }
        return;
    }
    int idx = b - 20480;
    int bx = idx & 15, by = (idx >> 4) & 1, g = idx >> 5;
    int bp = g >> 2, hkv = g & 3;
    int k0 = bx * 32, d0 = by * 32, x = tid & 31, y = tid >> 5;
    for (int j = y; j < 32; j += 8)
        t[j][x] = g_v[(size_t)(bp * 512 + k0 + j) * 256 + hkv * 64 + d0 + x];
    __syncthreads();
    for (int j = y; j < 32; j += 8) {
        size_t o = (size_t)g * 32768 + (size_t)(d0 + j) * 512 + k0 + x;
        g_vth[o] = __float2half_rn(t[x][j]);
    }
}

// ---------------------------------------------------------------------------
// GEMM core: 2-term, BK=64, 2-stage cp.async.
// Stage = 3 arrays (Ah, Al, Bh) x 128 rows x 64 fp16 (128B rows) = 48KB.
// Swizzle: phys = row*64 + ((chunk ^ (row & 7)) << 3)   (8-slot permutation)
// ---------------------------------------------------------------------------
#define SARR 8192    // elems per array per stage (128*64)
#define SSTG 24576   // elems per stage (3 arrays)

struct GemmCore {
    uint32_t smbase;
    int tid, wid, lane, wm, wn;
    float acc[4][4][4];

    __device__ __forceinline__ void init(const __half* sm, int t) {
        smbase = smem_u32(sm);
        tid = t; wid = t >> 5; lane = t & 31;
        wm = (wid >> 2) * 64; wn = (wid & 3) * 32;
        #pragma unroll
        for (int i = 0; i < 4; i++)
            #pragma unroll
            for (int j = 0; j < 4; j++)
                #pragma unroll
                for (int q = 0; q < 4; q++) acc[i][j][q] = 0.f;
    }
    __device__ __forceinline__ static uint32_t swz(int row, int chunk) {
        return (uint32_t)(row * 64 + ((chunk ^ (row & 7)) << 3));
    }
    __device__ __forceinline__ void issue(const __half* Agh, const __half* Agl,
                                          const __half* Bgh,
                                          int am0, int bn0, int k0, int s) {
        uint32_t stg = smbase + (uint32_t)s * SSTG * 2;
        #pragma unroll
        for (int i = 0; i < 12; i++) {
            int arr = i >> 2;
            int cc = (i & 3) * 256 + tid;      // 0..1023
            int r = cc >> 3, ch = cc & 7;
            uint32_t dst = stg + (arr * SARR + swz(r, ch)) * 2;
            const __half* src;
            if (arr == 0)      src = Agh + (size_t)(am0 + r) * 1024 + k0 + ch * 8;
            else if (arr == 1) src = Agl + (size_t)(am0 + r) * 1024 + k0 + ch * 8;
            else               src = Bgh + (size_t)(bn0 + r) * 1024 + k0 + ch * 8;
            CP16(dst, src);
        }
    }
    __device__ __forceinline__ void compute(int s) {
        uint32_t stg = smbase + (uint32_t)s * SSTG * 2;
        #pragma unroll
        for (int ks = 0; ks < 4; ks++) {
            int koff = ks * 16 + ((lane >> 4) << 3);
            int chunk = koff >> 3;
            int arow = wm + (lane & 15);
            uint32_t ah[4][4], al[4][4];
            #pragma unroll
            for (int mf = 0; mf < 4; mf++) {
                int row = arow + mf * 16;
                uint32_t off = swz(row, chunk) * 2;
                LDSM4(ah[mf][0], ah[mf][1], ah[mf][2], ah[mf][3], stg + 0 * SARR * 2 + off);
                LDSM4(al[mf][0], al[mf][1], al[mf][2], al[mf][3], stg + 1 * SARR * 2 + off);
            }
            uint32_t bh[4][2];
            #pragma unroll
            for (int jp = 0; jp < 4; jp += 2) {
                int brow = wn + jp * 8 + (lane & 15);
                uint32_t off = swz(brow, chunk) * 2;
                uint32_t r0, r1, r2, r3;
                LDSM4(r0, r1, r2, r3, stg + 2 * SARR * 2 + off);
                bh[jp][0] = r0; bh[jp + 1][0] = r1; bh[jp][1] = r2; bh[jp + 1][1] = r3;
            }
            #pragma unroll
            for (int mf = 0; mf < 4; mf++)
                #pragma unroll
                for (int nf = 0; nf < 4; nf++)
                    MMA16816(acc[mf][nf], ah[mf][0], ah[mf][1], ah[mf][2], ah[mf][3], bh[nf][0], bh[nf][1]);
            #pragma unroll
            for (int mf = 0; mf < 4; mf++)
                #pragma unroll
                for (int nf = 0; nf < 4; nf++)
                    MMA16816(acc[mf][nf], al[mf][0], al[mf][1], al[mf][2], al[mf][3], bh[nf][0], bh[nf][1]);
        }
    }
    __device__ __forceinline__ void run(const __half* Agh, const __half* Agl,
                                        const __half* Bgh, int am0, int bn0) {
        issue(Agh, Agl, Bgh, am0, bn0, 0, 0);
        CP_COMMIT();
        for (int it = 0; it < 16; it++) {
            CP_WAIT0();
            __syncthreads();
            if (it + 1 < 16) { issue(Agh, Agl, Bgh, am0, bn0, (it + 1) * 64, (it + 1) & 1); CP_COMMIT(); }
            compute(it & 1);
        }
    }
};

__global__ void __launch_bounds__(256) bfgemmQKV_k() {
    extern __shared__ __half SM[];
    GemmCore g;
    g.init(SM, threadIdx.x);
    int bm = blockIdx.y, bn = blockIdx.x;
    g.run(g_ah, g_al, g_wth, bm * 128, bn * 128);

    float* C; int Ntot, colb;
    if (bn < 8)       { C = g_q; Ntot = 1024; colb = bn * 128; }
    else if (bn < 10) { C = g_k; Ntot = 256;  colb = (bn - 8) * 128; }
    else              { C = g_v; Ntot = 256;  colb = (bn - 10) * 128; }
    #pragma unroll
    for (int mf = 0; mf < 4; mf++) {
        int r0 = bm * 128 + g.wm + mf * 16 + (g.lane >> 2);
        int r1 = r0 + 8;
        #pragma unroll
        for (int nf = 0; nf < 4; nf++) {
            int col = colb + g.wn + nf * 8 + (g.lane & 3) * 2;
            *(float2*)(C + (size_t)r0 * Ntot + col) = make_float2(g.acc[mf][nf][0], g.acc[mf][nf][1]);
            *(float2*)(C + (size_t)r1 * Ntot + col) = make_float2(g.acc[mf][nf][2], g.acc[mf][nf][3]);
        }
    }
}

__global__ void __launch_bounds__(256) bfgemmO_k(float* __restrict__ C) {
    extern __shared__ __half SM[];
    GemmCore g;
    g.init(SM, threadIdx.x);
    int bm = blockIdx.y, bn = blockIdx.x;
    g.run(g_ah, g_al, g_wth + (size_t)1536 * 1024, bm * 128, bn * 128);
    #pragma unroll
    for (int mf = 0; mf < 4; mf++) {
        int r0 = remap_bpt(bm * 128 + g.wm + mf * 16 + (g.lane >> 2));
        int r1 = remap_bpt(bm * 128 + g.wm + mf * 16 + (g.lane >> 2) + 8);
        #pragma unroll
        for (int nf = 0; nf < 4; nf++) {
            int col = bn * 128 + g.wn + nf * 8 + (g.lane & 3) * 2;
            *(float2*)(C + (size_t)r0 * 1024 + col) = make_float2(g.acc[mf][nf][0], g.acc[mf][nf][1]);
            *(float2*)(C + (size_t)r1 * 1024 + col) = make_float2(g.acc[mf][nf][2], g.acc[mf][nf][3]);
        }
    }
}

// ---------------------------------------------------------------------------
// Flash attention: S = (Qh+Ql)·Kh (2-term, K lo dropped), PV 2-term.
// Stage = 2 arrays (Khi, Vth) x 64 x KSTR.
// ---------------------------------------------------------------------------
#define KSTR 72
__global__ void __launch_bounds__(128, 3) attn3_k() {
    extern __shared__ __half ASM[];
    const int STG = 2 * 64 * KSTR;   // 9216 elems

    int tid = threadIdx.x, wid = tid >> 5, lane = tid & 31;
    int bph = blockIdx.y, h = bph & 15, bp = bph >> 4, hkv = h >> 2;
    int qt0 = blockIdx.x << 6;
    int qrow0 = bp * 512 + qt0;
    size_t vbase = (size_t)(bp * 4 + hkv) * 32768;

    {
        #pragma unroll
        for (int i = 0; i < 8; i++) {
            int half_ = i >> 2;
            int cc = (i & 3) * 128 + tid;
            int r = cc >> 3, kc = (cc & 7) * 8;
            uint32_t dst = smem_u32(ASM + half_ * 64 * KSTR + r * KSTR + kc);
            const __half* src = (half_ ? g_ql : g_qh) + (size_t)(qrow0 + r) * 1024 + h * 64 + kc;
            CP16(dst, src);
        }
        CP_COMMIT(); CP_WAIT0();
        __syncthreads();
    }
    uint32_t qh[4][4], ql[4][4];
    {
        __half* Qhi = ASM;
        __half* Qlo = ASM + 64 * KSTR;
        int row = wid * 16 + (lane & 15);
        #pragma unroll
        for (int ks = 0; ks < 4; ks++) {
            int koff = ks * 16 + ((lane >> 4) << 3);
            LDSM4(qh[ks][0], qh[ks][1], qh[ks][2], qh[ks][3], smem_u32(&Qhi[row * KSTR + koff]));
            LDSM4(ql[ks][0], ql[ks][1], ql[ks][2], ql[ks][3], smem_u32(&Qlo[row * KSTR + koff]));
        }
    }
    __syncthreads();

    auto issue = [&](int it, int s) {
        __half* stg = ASM + s * STG;
        int kt = it * 64;
        #pragma unroll
        for (int i = 0; i < 8; i++) {
            int arr = i >> 2;
            int cc = (i & 3) * 128 + tid;
            int r = cc >> 3, kc = (cc & 7) * 8;
            uint32_t dst = smem_u32(stg + arr * 64 * KSTR + r * KSTR + kc);
            const __half* src;
            if (arr == 0) src = g_kh + (size_t)(bp * 512 + kt + r) * 256 + hkv * 64 + kc;
            else          src = g_vth + vbase + (size_t)r * 512 + kt + kc;
            CP16(dst, src);
        }
    };

    float o[8][4];
    #pragma unroll
    for (int nf = 0; nf < 8; nf++)
        #pragma unroll
        for (int c = 0; c < 4; c++) o[nf][c] = 0.f;
    float m0 = -INFINITY, m1 = -INFINITY, l0 = 0.f, l1 = 0.f;

    issue(0, 0);
    CP_COMMIT();

    for (int it = 0; it < 8; it++) {
        CP_WAIT0();
        __syncthreads();
        if (it + 1 < 8) { issue(it + 1, (it + 1) & 1); CP_COMMIT(); }

        __half* stg = ASM + (it & 1) * STG;
        __half* Khi = stg;
        __half* Vth = stg + 64 * KSTR;

        float s[8][4];
        #pragma unroll
        for (int nf = 0; nf < 8; nf++)
            #pragma unroll
            for (int c = 0; c < 4; c++) s[nf][c] = 0.f;

        #pragma unroll
        for (int ks = 0; ks < 4; ks++) {
            int koff = ks * 16 + ((lane >> 4) << 3);
            #pragma unroll
            for (int jp = 0; jp < 8; jp += 2) {
                int brow = jp * 8 + (lane & 15);
                uint32_t r0, r1, r2, r3;
                LDSM4(r0, r1, r2, r3, smem_u32(&Khi[brow * KSTR + koff]));
                MMA16816(s[jp],     qh[ks][0], qh[ks][1], qh[ks][2], qh[ks][3], r0, r2);
                MMA16816(s[jp + 1], qh[ks][0], qh[ks][1], qh[ks][2], qh[ks][3], r1, r3);
                MMA16816(s[jp],     ql[ks][0], ql[ks][1], ql[ks][2], ql[ks][3], r0, r2);
                MMA16816(s[jp + 1], ql[ks][0], ql[ks][1], ql[ks][2], ql[ks][3], r1, r3);
            }
        }

        float rmax0 = -INFINITY, rmax1 = -INFINITY;
        #pragma unroll
        for (int nf = 0; nf < 8; nf++) {
            rmax0 = fmaxf(rmax0, fmaxf(s[nf][0], s[nf][1]));
            rmax1 = fmaxf(rmax1, fmaxf(s[nf][2], s[nf][3]));
        }
        rmax0 = fmaxf(rmax0, __shfl_xor_sync(0xffffffffu, rmax0, 1));
        rmax0 = fmaxf(rmax0, __shfl_xor_sync(0xffffffffu, rmax0, 2));
        rmax1 = fmaxf(rmax1, __shfl_xor_sync(0xffffffffu, rmax1, 1));
        rmax1 = fmaxf(rmax1, __shfl_xor_sync(0xffffffffu, rmax1, 2));
        float mn0 = fmaxf(m0, rmax0), mn1 = fmaxf(m1, rmax1);
        float al0 = exp2f(m0 - mn0), al1 = exp2f(m1 - mn1);
        float ps0 = 0.f, ps1 = 0.f;
        #pragma unroll
        for (int nf = 0; nf < 8; nf++) {
            s[nf][0] = exp2f(s[nf][0] - mn0); ps0 += s[nf][0];
            s[nf][1] = exp2f(s[nf][1] - mn0); ps0 += s[nf][1];
            s[nf][2] = exp2f(s[nf][2] - mn1); ps1 += s[nf][2];
            s[nf][3] = exp2f(s[nf][3] - mn1); ps1 += s[nf][3];
        }
        l0 = l0 * al0 + ps0; l1 = l1 * al1 + ps1;
        m0 = mn0; m1 = mn1;
        #pragma unroll
        for (int nf = 0; nf < 8; nf++) {
            o[nf][0] *= al0; o[nf][1] *= al0;
            o[nf][2] *= al1; o[nf][3] *= al1;
        }

        #pragma unroll
        for (int ks = 0; ks < 4; ks++) {
            float* pa = s[2 * ks];
            float* pb = s[2 * ks + 1];
            float ha0 = __half2float(__float2half_rn(pa[0]));
            float ha1 = __half2float(__float2half_rn(pa[1]));
            float ha2 = __half2float(__float2half_rn(pa[2]));
            float ha3 = __half2float(__float2half_rn(pa[3]));
            float hb0 = __half2float(__float2half_rn(pb[0]));
            float hb1 = __half2float(__float2half_rn(pb[1]));
            float hb2 = __half2float(__float2half_rn(pb[2]));
            float hb3 = __half2float(__float2half_rn(pb[3]));
            uint32_t ah0 = pk_h2(ha0, ha1), ah1 = pk_h2(ha2, ha3);
            uint32_t ah2 = pk_h2(hb0, hb1), ah3 = pk_h2(hb2, hb3);
            uint32_t pl0 = pk_h2(pa[0] - ha0, pa[1] - ha1);
            uint32_t pl1 = pk_h2(pa[2] - ha2, pa[3] - ha3);
            uint32_t pl2 = pk_h2(pb[0] - hb0, pb[1] - hb1);
            uint32_t pl3 = pk_h2(pb[2] - hb2, pb[3] - hb3);

            int koff = ks * 16 + ((lane >> 4) << 3);
            #pragma unroll
            for (int jp = 0; jp < 8; jp += 2) {
                int brow = jp * 8 + (lane & 15);
                uint32_t r0, r1, r2, r3;
                LDSM4(r0, r1, r2, r3, smem_u32(&Vth[brow * KSTR + koff]));
                MMA16816(o[jp],     ah0, ah1, ah2, ah3, r0, r2);
                MMA16816(o[jp + 1], ah0, ah1, ah2, ah3, r1, r3);
                MMA16816(o[jp],     pl0, pl1, pl2, pl3, r0, r2);
                MMA16816(o[jp + 1], pl0, pl1, pl2, pl3, r1, r3);
            }
        }
        __syncthreads();
    }

    l0 += __shfl_xor_sync(0xffffffffu, l0, 1);
    l0 += __shfl_xor_sync(0xffffffffu, l0, 2);
    l1 += __shfl_xor_sync(0xffffffffu, l1, 1);
    l1 += __shfl_xor_sync(0xffffffffu, l1, 2);
    float inv0 = 1.f / l0, inv1 = 1.f / l1;

    int row0 = qrow0 + wid * 16 + (lane >> 2);
    size_t b0 = (size_t)row0 * 1024 + h * 64 + (lane & 3) * 2;
    size_t b1 = b0 + 8 * 1024;
    #pragma unroll
    for (int nf = 0; nf < 8; nf++) {
        float x0 = o[nf][0] * inv0, y0 = o[nf][1] * inv0;
        float hx0 = __half2float(__float2half_rn(x0));
        float hy0 = __half2float(__float2half_rn(y0));
        *(uint32_t*)&g_ah[b0 + nf * 8] = pk_h2(hx0, hy0);
        *(uint32_t*)&g_al[b0 + nf * 8] = pk_h2(x0 - hx0, y0 - hy0);
        float x1 = o[nf][2] * inv1, y1 = o[nf][3] * inv1;
        float hx1 = __half2float(__float2half_rn(x1));
        float hy1 = __half2float(__float2half_rn(y1));
        *(uint32_t*)&g_ah[b1 + nf * 8] = pk_h2(hx1, hy1);
        *(uint32_t*)&g_al[b1 + nf * 8] = pk_h2(x1 - hx1, y1 - hy1);
    }
}

// ---------------------------------------------------------------------------
extern "C" void kernel_launch(void* const* d_in, const int* in_sizes, int n_in,
                              void* d_out, int out_size) {
    (void)in_sizes; (void)n_in; (void)out_size;
    const float* hidden = (const float*)d_in[0];
    const float* Wq = (const float*)d_in[1];
    const float* Wk = (const float*)d_in[2];
    const float* Wv = (const float*)d_in[3];
    const float* Wo = (const float*)d_in[4];
    float* out = (float*)d_out;

    const int gsm = 2 * SSTG * 2;             // 98304 B (2 stages x 48KB)
    const int asm_ = 2 * 2 * 64 * KSTR * 2;   // 36864 B
    cudaFuncSetAttribute(bfgemmQKV_k, cudaFuncAttributeMaxDynamicSharedMemorySize, gsm);
    cudaFuncSetAttribute(bfgemmO_k, cudaFuncAttributeMaxDynamicSharedMemorySize, gsm);
    cudaFuncSetAttribute(attn3_k, cudaFuncAttributeMaxDynamicSharedMemorySize, asm_);

    // 0: Wo transpose (hi only)
    transWo_k<<<1024, 256>>>(Wo);
    // 1: convert hidden (remap) to fp16 hi/lo
    convAin_k<<<8192, 256>>>(hidden);
    // 2: Wq + Wk + Wv transpose (hi only)
    transWqkv_k<<<3072, 256>>>(Wq, Wk, Wv);
    // 3: fused QKV projection (2-term, BK=64)  <- capture slot
    bfgemmQKV_k<<<dim3(12, 64), 256, gsm>>>();
    // 4: rope + split(Q)/hi(K) + V transpose
    prep2_k<<<22528, 256>>>();
    // 5: attention (QK 2-term, PV 2-term)
    attn3_k<<<dim3(8, 256), 128, asm_>>>();
    // 6: output projection (2-term, BK=64)
    bfgemmO_k<<<dim3(8, 64), 256, gsm>>>(out);
}

// round 15
// speedup vs baseline: 7.4009x; 1.2167x over previous
#include <cuda_runtime.h>
#include <cuda_fp16.h>
#include <cstdint>
#include <math.h>

#define NTOK 8192

// fp32 intermediates
__device__ float g_q[NTOK * 1024];
__device__ float g_k[NTOK * 256];
__device__ float g_v[NTOK * 256];
// fp16 operands
__device__ __half g_ah[NTOK * 1024], g_al[NTOK * 1024];
__device__ __half g_qh[NTOK * 1024], g_ql[NTOK * 1024];
__device__ __half g_kh[NTOK * 256];
__device__ __half g_vth[NTOK * 256];
__device__ __half g_wth[2560 * 1024];   // QKV rows 0-1535, Wo rows 1536-2559 (hi only)

__device__ __forceinline__ int remap_bpt(int r) {
    int b = r >> 12, p = (r >> 9) & 7, t = r & 511;
    return (b << 12) + (t << 3) + p;
}
__device__ __forceinline__ uint32_t smem_u32(const void* p) {
    uint32_t a;
    asm("{ .reg .u64 t; cvta.to.shared.u64 t, %1; cvt.u32.u64 %0, t; }" : "=r"(a) : "l"(p));
    return a;
}
#define LDSM4(r0, r1, r2, r3, a) \
    asm volatile("ldmatrix.sync.aligned.m8n8.x4.shared.b16 {%0,%1,%2,%3}, [%4];" \
        : "=r"(r0), "=r"(r1), "=r"(r2), "=r"(r3) : "r"(a))
#define MMA16816(c, a0, a1, a2, a3, b0, b1) \
    asm volatile("mma.sync.aligned.m16n8k16.row.col.f32.f16.f16.f32 " \
        "{%0,%1,%2,%3},{%4,%5,%6,%7},{%8,%9},{%0,%1,%2,%3};" \
        : "+f"((c)[0]), "+f"((c)[1]), "+f"((c)[2]), "+f"((c)[3]) \
        : "r"(a0), "r"(a1), "r"(a2), "r"(a3), "r"(b0), "r"(b1))
#define CP16(dst, src) \
    asm volatile("cp.async.cg.shared.global [%0], [%1], 16;" :: "r"(dst), "l"(src))
#define CP_COMMIT() asm volatile("cp.async.commit_group;" ::: "memory")
#define CP_WAIT1()  asm volatile("cp.async.wait_group 1;" ::: "memory")
#define CP_WAIT0()  asm volatile("cp.async.wait_group 0;" ::: "memory")

__device__ __forceinline__ uint32_t pk_h2(float x, float y) {
    __half2 h = __floats2half2_rn(x, y);
    return *(uint32_t*)&h;
}

// ---------------- prep ----------------
// hidden -> g_ah only (QKV gemm is 1-term now; g_al is later owned by attention output)
__global__ void __launch_bounds__(256) convAin_k(const float* __restrict__ hidden) {
    int idx = blockIdx.x * 256 + threadIdx.x;
    int row = idx >> 8, c4 = (idx & 255) * 4;
    int srow = remap_bpt(row);
    float4 v = *(const float4*)(hidden + (size_t)srow * 1024 + c4);
    *(uint2*)&g_ah[(size_t)row * 1024 + c4] =
        make_uint2(pk_h2(v.x, v.y), pk_h2(v.z, v.w));
}

__device__ __forceinline__ void transhi_body(const float* __restrict__ in, int N,
                                             int rowoff, int bx, int by, int tid) {
    __shared__ float t[32][33];
    int n0 = bx * 32;
    if (n0 >= N) return;
    int k0 = by * 32, x = tid & 31, y = tid >> 5;
    for (int j = y; j < 32; j += 8)
        t[j][x] = in[(size_t)(k0 + j) * N + n0 + x];
    __syncthreads();
    for (int j = y; j < 32; j += 8)
        g_wth[(size_t)(rowoff + n0 + j) * 1024 + k0 + x] = __float2half_rn(t[x][j]);
}
__global__ void __launch_bounds__(256) transWo_k(const float* __restrict__ Wo) {
    int r = blockIdx.x;
    transhi_body(Wo, 1024, 1536, r & 31, r >> 5, threadIdx.x);
}
__global__ void __launch_bounds__(256) transWqkv_k(const float* __restrict__ Wq,
                                                   const float* __restrict__ Wk,
                                                   const float* __restrict__ Wv) {
    int b = blockIdx.x;
    int z = b >> 10, r = b & 1023;
    const float* in = (z == 0) ? Wq : (z == 1) ? Wk : Wv;
    int N = (z == 0) ? 1024 : 256;
    int rowoff = (z == 0) ? 0 : (z == 1) ? 1024 : 1280;
    transhi_body(in, N, rowoff, r & 31, r >> 5, threadIdx.x);
}
__global__ void __launch_bounds__(256) prep2_k() {
    __shared__ float t[32][33];
    int b = blockIdx.x, tid = threadIdx.x;
    if (b < 20480) {
        int idx = b * 256 + tid;
        const int QP = NTOK * 16 * 32;
        int i, tok;
        if (idx < QP) {
            i = idx & 31;
            int r = idx >> 5;
            tok = r >> 4;
            size_t off = (size_t)tok * 1024 + (r & 15) * 64;
            const float* base = g_q + off;
            int tt = tok & 511;
            float invf = expf(-(float)i * 0.28782313662425574f);
            float ang = (float)tt * invf, s, c;
            sincosf(ang, &s, &c);
            const float scale = 0.125f * 1.4426950408889634f;
            float x1 = base[i], x2 = base[i + 32];
            float y1 = (x1 * c - x2 * s) * scale;
            float y2 = (x1 * s + x2 * c) * scale;
            float h1 = __half2float(__float2half_rn(y1));
            float h2 = __half2float(__float2half_rn(y2));
            g_qh[off + i]      = __float2half_rn(h1);
            g_ql[off + i]      = __float2half_rn(y1 - h1);
            g_qh[off + i + 32] = __float2half_rn(h2);
            g_ql[off + i + 32] = __float2half_rn(y2 - h2);
        } else {
            int j = idx - QP;
            i = j & 31;
            int r = j >> 5;
            tok = r >> 2;
            size_t off = (size_t)tok * 256 + (r & 3) * 64;
            const float* base = g_k + off;
            int tt = tok & 511;
            float invf = expf(-(float)i * 0.28782313662425574f);
            float ang = (float)tt * invf, s, c;
            sincosf(ang, &s, &c);
            float x1 = base[i], x2 = base[i + 32];
            g_kh[off + i]      = __float2half_rn(x1 * c - x2 * s);
            g_kh[off + i + 32] = __float2half_rn(x1 * s + x2 * c);
        }
        return;
    }
    int idx = b - 20480;
    int bx = idx & 15, by = (idx >> 4) & 1, g = idx >> 5;
    int bp = g >> 2, hkv = g & 3;
    int k0 = bx * 32, d0 = by * 32, x = tid & 31, y = tid >> 5;
    for (int j = y; j < 32; j += 8)
        t[j][x] = g_v[(size_t)(bp * 512 + k0 + j) * 256 + hkv * 64 + d0 + x];
    __syncthreads();
    for (int j = y; j < 32; j += 8) {
        size_t o = (size_t)g * 32768 + (size_t)(d0 + j) * 512 + k0 + x;
        g_vth[o] = __float2half_rn(t[x][j]);
    }
}

// ---------------------------------------------------------------------------
// GEMM core, templated: TERMS A-arrays (+1 B array), NSTG cp.async stages.
// BK=64, 128B rows, swizzle chunk ^= row&7.
// QKV: TERMS=1, NSTG=3 (3 x 32KB). gemmO: TERMS=2, NSTG=2 (2 x 48KB).
// ---------------------------------------------------------------------------
template<int TERMS, int NSTG>
struct GemmCore {
    static constexpr int ARRS = TERMS + 1;
    static constexpr int SSTGE = ARRS * 8192;  // elems per stage
    uint32_t smbase;
    int tid, wid, lane, wm, wn;
    float acc[4][4][4];

    __device__ __forceinline__ void init(const __half* sm, int t) {
        smbase = smem_u32(sm);
        tid = t; wid = t >> 5; lane = t & 31;
        wm = (wid >> 2) * 64; wn = (wid & 3) * 32;
        #pragma unroll
        for (int i = 0; i < 4; i++)
            #pragma unroll
            for (int j = 0; j < 4; j++)
                #pragma unroll
                for (int q = 0; q < 4; q++) acc[i][j][q] = 0.f;
    }
    __device__ __forceinline__ static uint32_t swz(int row, int chunk) {
        return (uint32_t)(row * 64 + ((chunk ^ (row & 7)) << 3));
    }
    __device__ __forceinline__ void issue(const __half* A0, const __half* A1,
                                          const __half* B,
                                          int am0, int bn0, int k0, int s) {
        uint32_t stg = smbase + (uint32_t)s * SSTGE * 2;
        #pragma unroll
        for (int i = 0; i < 4 * ARRS; i++) {
            int arr = i >> 2;
            int cc = (i & 3) * 256 + tid;
            int r = cc >> 3, ch = cc & 7;
            uint32_t dst = stg + (arr * 8192 + swz(r, ch)) * 2;
            const __half* src;
            if (arr == 0)                   src = A0 + (size_t)(am0 + r) * 1024 + k0 + ch * 8;
            else if (TERMS == 2 && arr == 1) src = A1 + (size_t)(am0 + r) * 1024 + k0 + ch * 8;
            else                            src = B + (size_t)(bn0 + r) * 1024 + k0 + ch * 8;
            CP16(dst, src);
        }
    }
    __device__ __forceinline__ void compute(int s) {
        uint32_t stg = smbase + (uint32_t)s * SSTGE * 2;
        #pragma unroll
        for (int ks = 0; ks < 4; ks++) {
            int koff = ks * 16 + ((lane >> 4) << 3);
            int chunk = koff >> 3;
            int arow = wm + (lane & 15);
            uint32_t ah[4][4], al[4][4];
            #pragma unroll
            for (int mf = 0; mf < 4; mf++) {
                int row = arow + mf * 16;
                uint32_t off = swz(row, chunk) * 2;
                LDSM4(ah[mf][0], ah[mf][1], ah[mf][2], ah[mf][3], stg + off);
                if (TERMS == 2)
                    LDSM4(al[mf][0], al[mf][1], al[mf][2], al[mf][3], stg + 8192 * 2 + off);
            }
            uint32_t bh[4][2];
            #pragma unroll
            for (int jp = 0; jp < 4; jp += 2) {
                int brow = wn + jp * 8 + (lane & 15);
                uint32_t off = swz(brow, chunk) * 2;
                uint32_t r0, r1, r2, r3;
                LDSM4(r0, r1, r2, r3, stg + TERMS * 8192 * 2 + off);
                bh[jp][0] = r0; bh[jp + 1][0] = r1; bh[jp][1] = r2; bh[jp + 1][1] = r3;
            }
            #pragma unroll
            for (int mf = 0; mf < 4; mf++)
                #pragma unroll
                for (int nf = 0; nf < 4; nf++)
                    MMA16816(acc[mf][nf], ah[mf][0], ah[mf][1], ah[mf][2], ah[mf][3], bh[nf][0], bh[nf][1]);
            if (TERMS == 2) {
                #pragma unroll
                for (int mf = 0; mf < 4; mf++)
                    #pragma unroll
                    for (int nf = 0; nf < 4; nf++)
                        MMA16816(acc[mf][nf], al[mf][0], al[mf][1], al[mf][2], al[mf][3], bh[nf][0], bh[nf][1]);
            }
        }
    }
    __device__ __forceinline__ void run(const __half* A0, const __half* A1,
                                        const __half* B, int am0, int bn0) {
        #pragma unroll
        for (int p = 0; p < NSTG - 1; p++) {
            issue(A0, A1, B, am0, bn0, p * 64, p);
            CP_COMMIT();
        }
        for (int it = 0; it < 16; it++) {
            if (NSTG == 3) { if (it < 15) { CP_WAIT1(); } else { CP_WAIT0(); } }
            else           { CP_WAIT0(); }
            __syncthreads();
            if (it + NSTG - 1 < 16) {
                issue(A0, A1, B, am0, bn0, (it + NSTG - 1) * 64, (it + NSTG - 1) % NSTG);
                CP_COMMIT();
            }
            compute(it % NSTG);
        }
    }
};

__global__ void __launch_bounds__(256) bfgemmQKV_k() {
    extern __shared__ __half SM[];
    GemmCore<1, 3> g;
    g.init(SM, threadIdx.x);
    int bm = blockIdx.y, bn = blockIdx.x;
    g.run(g_ah, g_ah, g_wth, bm * 128, bn * 128);

    float* C; int Ntot, colb;
    if (bn < 8)       { C = g_q; Ntot = 1024; colb = bn * 128; }
    else if (bn < 10) { C = g_k; Ntot = 256;  colb = (bn - 8) * 128; }
    else              { C = g_v; Ntot = 256;  colb = (bn - 10) * 128; }
    #pragma unroll
    for (int mf = 0; mf < 4; mf++) {
        int r0 = bm * 128 + g.wm + mf * 16 + (g.lane >> 2);
        int r1 = r0 + 8;
        #pragma unroll
        for (int nf = 0; nf < 4; nf++) {
            int col = colb + g.wn + nf * 8 + (g.lane & 3) * 2;
            *(float2*)(C + (size_t)r0 * Ntot + col) = make_float2(g.acc[mf][nf][0], g.acc[mf][nf][1]);
            *(float2*)(C + (size_t)r1 * Ntot + col) = make_float2(g.acc[mf][nf][2], g.acc[mf][nf][3]);
        }
    }
}

__global__ void __launch_bounds__(256) bfgemmO_k(float* __restrict__ C) {
    extern __shared__ __half SM[];
    GemmCore<2, 2> g;
    g.init(SM, threadIdx.x);
    int bm = blockIdx.y, bn = blockIdx.x;
    g.run(g_ah, g_al, g_wth + (size_t)1536 * 1024, bm * 128, bn * 128);
    #pragma unroll
    for (int mf = 0; mf < 4; mf++) {
        int r0 = remap_bpt(bm * 128 + g.wm + mf * 16 + (g.lane >> 2));
        int r1 = remap_bpt(bm * 128 + g.wm + mf * 16 + (g.lane >> 2) + 8);
        #pragma unroll
        for (int nf = 0; nf < 4; nf++) {
            int col = bn * 128 + g.wn + nf * 8 + (g.lane & 3) * 2;
            *(float2*)(C + (size_t)r0 * 1024 + col) = make_float2(g.acc[mf][nf][0], g.acc[mf][nf][1]);
            *(float2*)(C + (size_t)r1 * 1024 + col) = make_float2(g.acc[mf][nf][2], g.acc[mf][nf][3]);
        }
    }
}

// ---------------------------------------------------------------------------
// Flash attention (unchanged from R14): QK 2-term, PV 2-term.
// ---------------------------------------------------------------------------
#define KSTR 72
__global__ void __launch_bounds__(128, 3) attn3_k() {
    extern __shared__ __half ASM[];
    const int STG = 2 * 64 * KSTR;

    int tid = threadIdx.x, wid = tid >> 5, lane = tid & 31;
    int bph = blockIdx.y, h = bph & 15, bp = bph >> 4, hkv = h >> 2;
    int qt0 = blockIdx.x << 6;
    int qrow0 = bp * 512 + qt0;
    size_t vbase = (size_t)(bp * 4 + hkv) * 32768;

    {
        #pragma unroll
        for (int i = 0; i < 8; i++) {
            int half_ = i >> 2;
            int cc = (i & 3) * 128 + tid;
            int r = cc >> 3, kc = (cc & 7) * 8;
            uint32_t dst = smem_u32(ASM + half_ * 64 * KSTR + r * KSTR + kc);
            const __half* src = (half_ ? g_ql : g_qh) + (size_t)(qrow0 + r) * 1024 + h * 64 + kc;
            CP16(dst, src);
        }
        CP_COMMIT(); CP_WAIT0();
        __syncthreads();
    }
    uint32_t qh[4][4], ql[4][4];
    {
        __half* Qhi = ASM;
        __half* Qlo = ASM + 64 * KSTR;
        int row = wid * 16 + (lane & 15);
        #pragma unroll
        for (int ks = 0; ks < 4; ks++) {
            int koff = ks * 16 + ((lane >> 4) << 3);
            LDSM4(qh[ks][0], qh[ks][1], qh[ks][2], qh[ks][3], smem_u32(&Qhi[row * KSTR + koff]));
            LDSM4(ql[ks][0], ql[ks][1], ql[ks][2], ql[ks][3], smem_u32(&Qlo[row * KSTR + koff]));
        }
    }
    __syncthreads();

    auto issue = [&](int it, int s) {
        __half* stg = ASM + s * STG;
        int kt = it * 64;
        #pragma unroll
        for (int i = 0; i < 8; i++) {
            int arr = i >> 2;
            int cc = (i & 3) * 128 + tid;
            int r = cc >> 3, kc = (cc & 7) * 8;
            uint32_t dst = smem_u32(stg + arr * 64 * KSTR + r * KSTR + kc);
            const __half* src;
            if (arr == 0) src = g_kh + (size_t)(bp * 512 + kt + r) * 256 + hkv * 64 + kc;
            else          src = g_vth + vbase + (size_t)r * 512 + kt + kc;
            CP16(dst, src);
        }
    };

    float o[8][4];
    #pragma unroll
    for (int nf = 0; nf < 8; nf++)
        #pragma unroll
        for (int c = 0; c < 4; c++) o[nf][c] = 0.f;
    float m0 = -INFINITY, m1 = -INFINITY, l0 = 0.f, l1 = 0.f;

    issue(0, 0);
    CP_COMMIT();

    for (int it = 0; it < 8; it++) {
        CP_WAIT0();
        __syncthreads();
        if (it + 1 < 8) { issue(it + 1, (it + 1) & 1); CP_COMMIT(); }

        __half* stg = ASM + (it & 1) * STG;
        __half* Khi = stg;
        __half* Vth = stg + 64 * KSTR;

        float s[8][4];
        #pragma unroll
        for (int nf = 0; nf < 8; nf++)
            #pragma unroll
            for (int c = 0; c < 4; c++) s[nf][c] = 0.f;

        #pragma unroll
        for (int ks = 0; ks < 4; ks++) {
            int koff = ks * 16 + ((lane >> 4) << 3);
            #pragma unroll
            for (int jp = 0; jp < 8; jp += 2) {
                int brow = jp * 8 + (lane & 15);
                uint32_t r0, r1, r2, r3;
                LDSM4(r0, r1, r2, r3, smem_u32(&Khi[brow * KSTR + koff]));
                MMA16816(s[jp],     qh[ks][0], qh[ks][1], qh[ks][2], qh[ks][3], r0, r2);
                MMA16816(s[jp + 1], qh[ks][0], qh[ks][1], qh[ks][2], qh[ks][3], r1, r3);
                MMA16816(s[jp],     ql[ks][0], ql[ks][1], ql[ks][2], ql[ks][3], r0, r2);
                MMA16816(s[jp + 1], ql[ks][0], ql[ks][1], ql[ks][2], ql[ks][3], r1, r3);
            }
        }

        float rmax0 = -INFINITY, rmax1 = -INFINITY;
        #pragma unroll
        for (int nf = 0; nf < 8; nf++) {
            rmax0 = fmaxf(rmax0, fmaxf(s[nf][0], s[nf][1]));
            rmax1 = fmaxf(rmax1, fmaxf(s[nf][2], s[nf][3]));
        }
        rmax0 = fmaxf(rmax0, __shfl_xor_sync(0xffffffffu, rmax0, 1));
        rmax0 = fmaxf(rmax0, __shfl_xor_sync(0xffffffffu, rmax0, 2));
        rmax1 = fmaxf(rmax1, __shfl_xor_sync(0xffffffffu, rmax1, 1));
        rmax1 = fmaxf(rmax1, __shfl_xor_sync(0xffffffffu, rmax1, 2));
        float mn0 = fmaxf(m0, rmax0), mn1 = fmaxf(m1, rmax1);
        float al0 = exp2f(m0 - mn0), al1 = exp2f(m1 - mn1);
        float ps0 = 0.f, ps1 = 0.f;
        #pragma unroll
        for (int nf = 0; nf < 8; nf++) {
            s[nf][0] = exp2f(s[nf][0] - mn0); ps0 += s[nf][0];
            s[nf][1] = exp2f(s[nf][1] - mn0); ps0 += s[nf][1];
            s[nf][2] = exp2f(s[nf][2] - mn1); ps1 += s[nf][2];
            s[nf][3] = exp2f(s[nf][3] - mn1); ps1 += s[nf][3];
        }
        l0 = l0 * al0 + ps0; l1 = l1 * al1 + ps1;
        m0 = mn0; m1 = mn1;
        #pragma unroll
        for (int nf = 0; nf < 8; nf++) {
            o[nf][0] *= al0; o[nf][1] *= al0;
            o[nf][2] *= al1; o[nf][3] *= al1;
        }

        #pragma unroll
        for (int ks = 0; ks < 4; ks++) {
            float* pa = s[2 * ks];
            float* pb = s[2 * ks + 1];
            float ha0 = __half2float(__float2half_rn(pa[0]));
            float ha1 = __half2float(__float2half_rn(pa[1]));
            float ha2 = __half2float(__float2half_rn(pa[2]));
            float ha3 = __half2float(__float2half_rn(pa[3]));
            float hb0 = __half2float(__float2half_rn(pb[0]));
            float hb1 = __half2float(__float2half_rn(pb[1]));
            float hb2 = __half2float(__float2half_rn(pb[2]));
            float hb3 = __half2float(__float2half_rn(pb[3]));
            uint32_t ah0 = pk_h2(ha0, ha1), ah1 = pk_h2(ha2, ha3);
            uint32_t ah2 = pk_h2(hb0, hb1), ah3 = pk_h2(hb2, hb3);
            uint32_t pl0 = pk_h2(pa[0] - ha0, pa[1] - ha1);
            uint32_t pl1 = pk_h2(pa[2] - ha2, pa[3] - ha3);
            uint32_t pl2 = pk_h2(pb[0] - hb0, pb[1] - hb1);
            uint32_t pl3 = pk_h2(pb[2] - hb2, pb[3] - hb3);

            int koff = ks * 16 + ((lane >> 4) << 3);
            #pragma unroll
            for (int jp = 0; jp < 8; jp += 2) {
                int brow = jp * 8 + (lane & 15);
                uint32_t r0, r1, r2, r3;
                LDSM4(r0, r1, r2, r3, smem_u32(&Vth[brow * KSTR + koff]));
                MMA16816(o[jp],     ah0, ah1, ah2, ah3, r0, r2);
                MMA16816(o[jp + 1], ah0, ah1, ah2, ah3, r1, r3);
                MMA16816(o[jp],     pl0, pl1, pl2, pl3, r0, r2);
                MMA16816(o[jp + 1], pl0, pl1, pl2, pl3, r1, r3);
            }
        }
        __syncthreads();
    }

    l0 += __shfl_xor_sync(0xffffffffu, l0, 1);
    l0 += __shfl_xor_sync(0xffffffffu, l0, 2);
    l1 += __shfl_xor_sync(0xffffffffu, l1, 1);
    l1 += __shfl_xor_sync(0xffffffffu, l1, 2);
    float inv0 = 1.f / l0, inv1 = 1.f / l1;

    int row0 = qrow0 + wid * 16 + (lane >> 2);
    size_t b0 = (size_t)row0 * 1024 + h * 64 + (lane & 3) * 2;
    size_t b1 = b0 + 8 * 1024;
    #pragma unroll
    for (int nf = 0; nf < 8; nf++) {
        float x0 = o[nf][0] * inv0, y0 = o[nf][1] * inv0;
        float hx0 = __half2float(__float2half_rn(x0));
        float hy0 = __half2float(__float2half_rn(y0));
        *(uint32_t*)&g_ah[b0 + nf * 8] = pk_h2(hx0, hy0);
        *(uint32_t*)&g_al[b0 + nf * 8] = pk_h2(x0 - hx0, y0 - hy0);
        float x1 = o[nf][2] * inv1, y1 = o[nf][3] * inv1;
        float hx1 = __half2float(__float2half_rn(x1));
        float hy1 = __half2float(__float2half_rn(y1));
        *(uint32_t*)&g_ah[b1 + nf * 8] = pk_h2(hx1, hy1);
        *(uint32_t*)&g_al[b1 + nf * 8] = pk_h2(x1 - hx1, y1 - hy1);
    }
}

// ---------------------------------------------------------------------------
extern "C" void kernel_launch(void* const* d_in, const int* in_sizes, int n_in,
                              void* d_out, int out_size) {
    (void)in_sizes; (void)n_in; (void)out_size;
    const float* hidden = (const float*)d_in[0];
    const float* Wq = (const float*)d_in[1];
    const float* Wk = (const float*)d_in[2];
    const float* Wv = (const float*)d_in[3];
    const float* Wo = (const float*)d_in[4];
    float* out = (float*)d_out;

    const int gsm = 98304;                    // QKV: 3x32KB; gemmO: 2x48KB
    const int asm_ = 2 * 2 * 64 * KSTR * 2;   // 36864 B
    cudaFuncSetAttribute(bfgemmQKV_k, cudaFuncAttributeMaxDynamicSharedMemorySize, gsm);
    cudaFuncSetAttribute(bfgemmO_k, cudaFuncAttributeMaxDynamicSharedMemorySize, gsm);
    cudaFuncSetAttribute(attn3_k, cudaFuncAttributeMaxDynamicSharedMemorySize, asm_);

    // 0: Wo transpose (hi only)
    transWo_k<<<1024, 256>>>(Wo);
    // 1: convert hidden (remap) to fp16 (hi only)
    convAin_k<<<8192, 256>>>(hidden);
    // 2: Wq + Wk + Wv transpose (hi only)
    transWqkv_k<<<3072, 256>>>(Wq, Wk, Wv);
    // 3: fused QKV projection (1-term pure fp16, BK=64, 3-stage)  <- capture slot
    bfgemmQKV_k<<<dim3(12, 64), 256, gsm>>>();
    // 4: rope + split(Q)/hi(K) + V transpose
    prep2_k<<<22528, 256>>>();
    // 5: attention (QK 2-term, PV 2-term)
    attn3_k<<<dim3(8, 256), 128, asm_>>>();
    // 6: output projection (2-term, BK=64, 2-stage)
    bfgemmO_k<<<dim3(8, 64), 256, gsm>>>(out);
}

// round 16
// speedup vs baseline: 9.5614x; 1.2919x over previous
#include <cuda_runtime.h>
#include <cuda_fp16.h>
#include <cstdint>
#include <math.h>

#define NTOK 8192

// fp32 intermediates
__device__ float g_q[NTOK * 1024];
__device__ float g_k[NTOK * 256];
__device__ float g_v[NTOK * 256];
// fp16 operands
__device__ __half g_ah[NTOK * 1024];    // hidden (pre-QKV), then attention output (pre-Wo)
__device__ __half g_qh[NTOK * 1024];
__device__ __half g_kh[NTOK * 256];
__device__ __half g_vth[NTOK * 256];
__device__ __half g_wth[2560 * 1024];   // QKV rows 0-1535, Wo rows 1536-2559

__device__ __forceinline__ int remap_bpt(int r) {
    int b = r >> 12, p = (r >> 9) & 7, t = r & 511;
    return (b << 12) + (t << 3) + p;
}
__device__ __forceinline__ uint32_t smem_u32(const void* p) {
    uint32_t a;
    asm("{ .reg .u64 t; cvta.to.shared.u64 t, %1; cvt.u32.u64 %0, t; }" : "=r"(a) : "l"(p));
    return a;
}
#define LDSM4(r0, r1, r2, r3, a) \
    asm volatile("ldmatrix.sync.aligned.m8n8.x4.shared.b16 {%0,%1,%2,%3}, [%4];" \
        : "=r"(r0), "=r"(r1), "=r"(r2), "=r"(r3) : "r"(a))
#define MMA16816(c, a0, a1, a2, a3, b0, b1) \
    asm volatile("mma.sync.aligned.m16n8k16.row.col.f32.f16.f16.f32 " \
        "{%0,%1,%2,%3},{%4,%5,%6,%7},{%8,%9},{%0,%1,%2,%3};" \
        : "+f"((c)[0]), "+f"((c)[1]), "+f"((c)[2]), "+f"((c)[3]) \
        : "r"(a0), "r"(a1), "r"(a2), "r"(a3), "r"(b0), "r"(b1))
#define CP16(dst, src) \
    asm volatile("cp.async.cg.shared.global [%0], [%1], 16;" :: "r"(dst), "l"(src))
#define CP_COMMIT() asm volatile("cp.async.commit_group;" ::: "memory")
#define CP_WAIT1()  asm volatile("cp.async.wait_group 1;" ::: "memory")
#define CP_WAIT0()  asm volatile("cp.async.wait_group 0;" ::: "memory")

__device__ __forceinline__ uint32_t pk_h2(float x, float y) {
    __half2 h = __floats2half2_rn(x, y);
    return *(uint32_t*)&h;
}

// ---------------------------------------------------------------------------
// prep0 (fused): convA [0..8191] + Wqkv transpose [8192..11263] + Wo [11264..12287]
// ---------------------------------------------------------------------------
__device__ __forceinline__ void transhi_body(const float* __restrict__ in, int N,
                                             int rowoff, int bx, int by, int tid) {
    __shared__ float t[32][33];
    int n0 = bx * 32;
    if (n0 >= N) return;
    int k0 = by * 32, x = tid & 31, y = tid >> 5;
    for (int j = y; j < 32; j += 8)
        t[j][x] = in[(size_t)(k0 + j) * N + n0 + x];
    __syncthreads();
    for (int j = y; j < 32; j += 8)
        g_wth[(size_t)(rowoff + n0 + j) * 1024 + k0 + x] = __float2half_rn(t[x][j]);
}

__global__ void __launch_bounds__(256) prep0_k(const float* __restrict__ hidden,
                                               const float* __restrict__ Wq,
                                               const float* __restrict__ Wk,
                                               const float* __restrict__ Wv,
                                               const float* __restrict__ Wo) {
    int b = blockIdx.x, tid = threadIdx.x;
    if (b < 8192) {
        int idx = b * 256 + tid;
        int row = idx >> 8, c4 = (idx & 255) * 4;
        int srow = remap_bpt(row);
        float4 v = *(const float4*)(hidden + (size_t)srow * 1024 + c4);
        *(uint2*)&g_ah[(size_t)row * 1024 + c4] =
            make_uint2(pk_h2(v.x, v.y), pk_h2(v.z, v.w));
        return;
    }
    if (b < 11264) {
        int idx = b - 8192;
        int z = idx >> 10, r = idx & 1023;
        const float* in = (z == 0) ? Wq : (z == 1) ? Wk : Wv;
        int N = (z == 0) ? 1024 : 256;
        int rowoff = (z == 0) ? 0 : (z == 1) ? 1024 : 1280;
        transhi_body(in, N, rowoff, r & 31, r >> 5, tid);
        return;
    }
    int r = b - 11264;
    transhi_body(Wo, 1024, 1536, r & 31, r >> 5, tid);
}

// ---------------------------------------------------------------------------
// prep2: rope -> fp16 (Q and K both hi-only now) + V transpose
// ---------------------------------------------------------------------------
__global__ void __launch_bounds__(256) prep2_k() {
    __shared__ float t[32][33];
    int b = blockIdx.x, tid = threadIdx.x;
    if (b < 20480) {
        int idx = b * 256 + tid;
        const int QP = NTOK * 16 * 32;
        int i, tok;
        if (idx < QP) {
            i = idx & 31;
            int r = idx >> 5;
            tok = r >> 4;
            size_t off = (size_t)tok * 1024 + (r & 15) * 64;
            const float* base = g_q + off;
            int tt = tok & 511;
            float invf = expf(-(float)i * 0.28782313662425574f);
            float ang = (float)tt * invf, s, c;
            sincosf(ang, &s, &c);
            const float scale = 0.125f * 1.4426950408889634f;
            float x1 = base[i], x2 = base[i + 32];
            g_qh[off + i]      = __float2half_rn((x1 * c - x2 * s) * scale);
            g_qh[off + i + 32] = __float2half_rn((x1 * s + x2 * c) * scale);
        } else {
            int j = idx - QP;
            i = j & 31;
            int r = j >> 5;
            tok = r >> 2;
            size_t off = (size_t)tok * 256 + (r & 3) * 64;
            const float* base = g_k + off;
            int tt = tok & 511;
            float invf = expf(-(float)i * 0.28782313662425574f);
            float ang = (float)tt * invf, s, c;
            sincosf(ang, &s, &c);
            float x1 = base[i], x2 = base[i + 32];
            g_kh[off + i]      = __float2half_rn(x1 * c - x2 * s);
            g_kh[off + i + 32] = __float2half_rn(x1 * s + x2 * c);
        }
        return;
    }
    int idx = b - 20480;
    int bx = idx & 15, by = (idx >> 4) & 1, g = idx >> 5;
    int bp = g >> 2, hkv = g & 3;
    int k0 = bx * 32, d0 = by * 32, x = tid & 31, y = tid >> 5;
    for (int j = y; j < 32; j += 8)
        t[j][x] = g_v[(size_t)(bp * 512 + k0 + j) * 256 + hkv * 64 + d0 + x];
    __syncthreads();
    for (int j = y; j < 32; j += 8) {
        size_t o = (size_t)g * 32768 + (size_t)(d0 + j) * 512 + k0 + x;
        g_vth[o] = __float2half_rn(t[x][j]);
    }
}

// ---------------------------------------------------------------------------
// GEMM core: 1-term pure fp16, BK=64, 3-stage cp.async (stage = 32KB).
// ---------------------------------------------------------------------------
struct GemmCore {
    uint32_t smbase;
    int tid, wid, lane, wm, wn;
    float acc[4][4][4];

    __device__ __forceinline__ void init(const __half* sm, int t) {
        smbase = smem_u32(sm);
        tid = t; wid = t >> 5; lane = t & 31;
        wm = (wid >> 2) * 64; wn = (wid & 3) * 32;
        #pragma unroll
        for (int i = 0; i < 4; i++)
            #pragma unroll
            for (int j = 0; j < 4; j++)
                #pragma unroll
                for (int q = 0; q < 4; q++) acc[i][j][q] = 0.f;
    }
    __device__ __forceinline__ static uint32_t swz(int row, int chunk) {
        return (uint32_t)(row * 64 + ((chunk ^ (row & 7)) << 3));
    }
    __device__ __forceinline__ void issue(const __half* A, const __half* B,
                                          int am0, int bn0, int k0, int s) {
        uint32_t stg = smbase + (uint32_t)s * 16384 * 2;
        #pragma unroll
        for (int i = 0; i < 8; i++) {
            int arr = i >> 2;
            int cc = (i & 3) * 256 + tid;
            int r = cc >> 3, ch = cc & 7;
            uint32_t dst = stg + (arr * 8192 + swz(r, ch)) * 2;
            const __half* src = arr == 0
                ? A + (size_t)(am0 + r) * 1024 + k0 + ch * 8
                : B + (size_t)(bn0 + r) * 1024 + k0 + ch * 8;
            CP16(dst, src);
        }
    }
    __device__ __forceinline__ void compute(int s) {
        uint32_t stg = smbase + (uint32_t)s * 16384 * 2;
        #pragma unroll
        for (int ks = 0; ks < 4; ks++) {
            int koff = ks * 16 + ((lane >> 4) << 3);
            int chunk = koff >> 3;
            int arow = wm + (lane & 15);
            uint32_t ah[4][4];
            #pragma unroll
            for (int mf = 0; mf < 4; mf++) {
                uint32_t off = swz(arow + mf * 16, chunk) * 2;
                LDSM4(ah[mf][0], ah[mf][1], ah[mf][2], ah[mf][3], stg + off);
            }
            uint32_t bh[4][2];
            #pragma unroll
            for (int jp = 0; jp < 4; jp += 2) {
                int brow = wn + jp * 8 + (lane & 15);
                uint32_t off = swz(brow, chunk) * 2;
                uint32_t r0, r1, r2, r3;
                LDSM4(r0, r1, r2, r3, stg + 8192 * 2 + off);
                bh[jp][0] = r0; bh[jp + 1][0] = r1; bh[jp][1] = r2; bh[jp + 1][1] = r3;
            }
            #pragma unroll
            for (int mf = 0; mf < 4; mf++)
                #pragma unroll
                for (int nf = 0; nf < 4; nf++)
                    MMA16816(acc[mf][nf], ah[mf][0], ah[mf][1], ah[mf][2], ah[mf][3], bh[nf][0], bh[nf][1]);
        }
    }
    __device__ __forceinline__ void run(const __half* A, const __half* B, int am0, int bn0) {
        issue(A, B, am0, bn0, 0, 0);  CP_COMMIT();
        issue(A, B, am0, bn0, 64, 1); CP_COMMIT();
        for (int it = 0; it < 16; it++) {
            if (it < 15) { CP_WAIT1(); } else { CP_WAIT0(); }
            __syncthreads();
            if (it + 2 < 16) { issue(A, B, am0, bn0, (it + 2) * 64, (it + 2) % 3); CP_COMMIT(); }
            compute(it % 3);
        }
    }
};

__global__ void __launch_bounds__(256) bfgemmQKV_k() {
    extern __shared__ __half SM[];
    GemmCore g;
    g.init(SM, threadIdx.x);
    int bm = blockIdx.y, bn = blockIdx.x;
    g.run(g_ah, g_wth, bm * 128, bn * 128);

    float* C; int Ntot, colb;
    if (bn < 8)       { C = g_q; Ntot = 1024; colb = bn * 128; }
    else if (bn < 10) { C = g_k; Ntot = 256;  colb = (bn - 8) * 128; }
    else              { C = g_v; Ntot = 256;  colb = (bn - 10) * 128; }
    #pragma unroll
    for (int mf = 0; mf < 4; mf++) {
        int r0 = bm * 128 + g.wm + mf * 16 + (g.lane >> 2);
        int r1 = r0 + 8;
        #pragma unroll
        for (int nf = 0; nf < 4; nf++) {
            int col = colb + g.wn + nf * 8 + (g.lane & 3) * 2;
            *(float2*)(C + (size_t)r0 * Ntot + col) = make_float2(g.acc[mf][nf][0], g.acc[mf][nf][1]);
            *(float2*)(C + (size_t)r1 * Ntot + col) = make_float2(g.acc[mf][nf][2], g.acc[mf][nf][3]);
        }
    }
}

__global__ void __launch_bounds__(256) bfgemmO_k(float* __restrict__ C) {
    extern __shared__ __half SM[];
    GemmCore g;
    g.init(SM, threadIdx.x);
    int bm = blockIdx.y, bn = blockIdx.x;
    g.run(g_ah, g_wth + (size_t)1536 * 1024, bm * 128, bn * 128);
    #pragma unroll
    for (int mf = 0; mf < 4; mf++) {
        int r0 = remap_bpt(bm * 128 + g.wm + mf * 16 + (g.lane >> 2));
        int r1 = remap_bpt(bm * 128 + g.wm + mf * 16 + (g.lane >> 2) + 8);
        #pragma unroll
        for (int nf = 0; nf < 4; nf++) {
            int col = bn * 128 + g.wn + nf * 8 + (g.lane & 3) * 2;
            *(float2*)(C + (size_t)r0 * 1024 + col) = make_float2(g.acc[mf][nf][0], g.acc[mf][nf][1]);
            *(float2*)(C + (size_t)r1 * 1024 + col) = make_float2(g.acc[mf][nf][2], g.acc[mf][nf][3]);
        }
    }
}

// ---------------------------------------------------------------------------
// Flash attention: QK 1-term fp16, PV 2-term (P hi/lo). Output -> g_ah hi only.
// ---------------------------------------------------------------------------
#define KSTR 72
__global__ void __launch_bounds__(128, 3) attn3_k() {
    extern __shared__ __half ASM[];
    const int STG = 2 * 64 * KSTR;

    int tid = threadIdx.x, wid = tid >> 5, lane = tid & 31;
    int bph = blockIdx.y, h = bph & 15, bp = bph >> 4, hkv = h >> 2;
    int qt0 = blockIdx.x << 6;
    int qrow0 = bp * 512 + qt0;
    size_t vbase = (size_t)(bp * 4 + hkv) * 32768;

    // ---- Q tile (hi only) into stage0, then frags ----
    {
        #pragma unroll
        for (int i = 0; i < 4; i++) {
            int cc = i * 128 + tid;
            int r = cc >> 3, kc = (cc & 7) * 8;
            uint32_t dst = smem_u32(ASM + r * KSTR + kc);
            CP16(dst, g_qh + (size_t)(qrow0 + r) * 1024 + h * 64 + kc);
        }
        CP_COMMIT(); CP_WAIT0();
        __syncthreads();
    }
    uint32_t qh[4][4];
    {
        int row = wid * 16 + (lane & 15);
        #pragma unroll
        for (int ks = 0; ks < 4; ks++) {
            int koff = ks * 16 + ((lane >> 4) << 3);
            LDSM4(qh[ks][0], qh[ks][1], qh[ks][2], qh[ks][3], smem_u32(&ASM[row * KSTR + koff]));
        }
    }
    __syncthreads();

    auto issue = [&](int it, int s) {
        __half* stg = ASM + s * STG;
        int kt = it * 64;
        #pragma unroll
        for (int i = 0; i < 8; i++) {
            int arr = i >> 2;
            int cc = (i & 3) * 128 + tid;
            int r = cc >> 3, kc = (cc & 7) * 8;
            uint32_t dst = smem_u32(stg + arr * 64 * KSTR + r * KSTR + kc);
            const __half* src;
            if (arr == 0) src = g_kh + (size_t)(bp * 512 + kt + r) * 256 + hkv * 64 + kc;
            else          src = g_vth + vbase + (size_t)r * 512 + kt + kc;
            CP16(dst, src);
        }
    };

    float o[8][4];
    #pragma unroll
    for (int nf = 0; nf < 8; nf++)
        #pragma unroll
        for (int c = 0; c < 4; c++) o[nf][c] = 0.f;
    float m0 = -INFINITY, m1 = -INFINITY, l0 = 0.f, l1 = 0.f;

    issue(0, 0);
    CP_COMMIT();

    for (int it = 0; it < 8; it++) {
        CP_WAIT0();
        __syncthreads();
        if (it + 1 < 8) { issue(it + 1, (it + 1) & 1); CP_COMMIT(); }

        __half* stg = ASM + (it & 1) * STG;
        __half* Khi = stg;
        __half* Vth = stg + 64 * KSTR;

        float s[8][4];
        #pragma unroll
        for (int nf = 0; nf < 8; nf++)
            #pragma unroll
            for (int c = 0; c < 4; c++) s[nf][c] = 0.f;

        #pragma unroll
        for (int ks = 0; ks < 4; ks++) {
            int koff = ks * 16 + ((lane >> 4) << 3);
            #pragma unroll
            for (int jp = 0; jp < 8; jp += 2) {
                int brow = jp * 8 + (lane & 15);
                uint32_t r0, r1, r2, r3;
                LDSM4(r0, r1, r2, r3, smem_u32(&Khi[brow * KSTR + koff]));
                MMA16816(s[jp],     qh[ks][0], qh[ks][1], qh[ks][2], qh[ks][3], r0, r2);
                MMA16816(s[jp + 1], qh[ks][0], qh[ks][1], qh[ks][2], qh[ks][3], r1, r3);
            }
        }

        float rmax0 = -INFINITY, rmax1 = -INFINITY;
        #pragma unroll
        for (int nf = 0; nf < 8; nf++) {
            rmax0 = fmaxf(rmax0, fmaxf(s[nf][0], s[nf][1]));
            rmax1 = fmaxf(rmax1, fmaxf(s[nf][2], s[nf][3]));
        }
        rmax0 = fmaxf(rmax0, __shfl_xor_sync(0xffffffffu, rmax0, 1));
        rmax0 = fmaxf(rmax0, __shfl_xor_sync(0xffffffffu, rmax0, 2));
        rmax1 = fmaxf(rmax1, __shfl_xor_sync(0xffffffffu, rmax1, 1));
        rmax1 = fmaxf(rmax1, __shfl_xor_sync(0xffffffffu, rmax1, 2));
        float mn0 = fmaxf(m0, rmax0), mn1 = fmaxf(m1, rmax1);
        float al0 = exp2f(m0 - mn0), al1 = exp2f(m1 - mn1);
        float ps0 = 0.f, ps1 = 0.f;
        #pragma unroll
        for (int nf = 0; nf < 8; nf++) {
            s[nf][0] = exp2f(s[nf][0] - mn0); ps0 += s[nf][0];
            s[nf][1] = exp2f(s[nf][1] - mn0); ps0 += s[nf][1];
            s[nf][2] = exp2f(s[nf][2] - mn1); ps1 += s[nf][2];
            s[nf][3] = exp2f(s[nf][3] - mn1); ps1 += s[nf][3];
        }
        l0 = l0 * al0 + ps0; l1 = l1 * al1 + ps1;
        m0 = mn0; m1 = mn1;
        #pragma unroll
        for (int nf = 0; nf < 8; nf++) {
            o[nf][0] *= al0; o[nf][1] *= al0;
            o[nf][2] *= al1; o[nf][3] *= al1;
        }

        #pragma unroll
        for (int ks = 0; ks < 4; ks++) {
            float* pa = s[2 * ks];
            float* pb = s[2 * ks + 1];
            float ha0 = __half2float(__float2half_rn(pa[0]));
            float ha1 = __half2float(__float2half_rn(pa[1]));
            float ha2 = __half2float(__float2half_rn(pa[2]));
            float ha3 = __half2float(__float2half_rn(pa[3]));
            float hb0 = __half2float(__float2half_rn(pb[0]));
            float hb1 = __half2float(__float2half_rn(pb[1]));
            float hb2 = __half2float(__float2half_rn(pb[2]));
            float hb3 = __half2float(__float2half_rn(pb[3]));
            uint32_t ah0 = pk_h2(ha0, ha1), ah1 = pk_h2(ha2, ha3);
            uint32_t ah2 = pk_h2(hb0, hb1), ah3 = pk_h2(hb2, hb3);
            uint32_t pl0 = pk_h2(pa[0] - ha0, pa[1] - ha1);
            uint32_t pl1 = pk_h2(pa[2] - ha2, pa[3] - ha3);
            uint32_t pl2 = pk_h2(pb[0] - hb0, pb[1] - hb1);
            uint32_t pl3 = pk_h2(pb[2] - hb2, pb[3] - hb3);

            int koff = ks * 16 + ((lane >> 4) << 3);
            #pragma unroll
            for (int jp = 0; jp < 8; jp += 2) {
                int brow = jp * 8 + (lane & 15);
                uint32_t r0, r1, r2, r3;
                LDSM4(r0, r1, r2, r3, smem_u32(&Vth[brow * KSTR + koff]));
                MMA16816(o[jp],     ah0, ah1, ah2, ah3, r0, r2);
                MMA16816(o[jp + 1], ah0, ah1, ah2, ah3, r1, r3);
                MMA16816(o[jp],     pl0, pl1, pl2, pl3, r0, r2);
                MMA16816(o[jp + 1], pl0, pl1, pl2, pl3, r1, r3);
            }
        }
        __syncthreads();
    }

    l0 += __shfl_xor_sync(0xffffffffu, l0, 1);
    l0 += __shfl_xor_sync(0xffffffffu, l0, 2);
    l1 += __shfl_xor_sync(0xffffffffu, l1, 1);
    l1 += __shfl_xor_sync(0xffffffffu, l1, 2);
    float inv0 = 1.f / l0, inv1 = 1.f / l1;

    int row0 = qrow0 + wid * 16 + (lane >> 2);
    size_t b0 = (size_t)row0 * 1024 + h * 64 + (lane & 3) * 2;
    size_t b1 = b0 + 8 * 1024;
    #pragma unroll
    for (int nf = 0; nf < 8; nf++) {
        *(uint32_t*)&g_ah[b0 + nf * 8] = pk_h2(o[nf][0] * inv0, o[nf][1] * inv0);
        *(uint32_t*)&g_ah[b1 + nf * 8] = pk_h2(o[nf][2] * inv1, o[nf][3] * inv1);
    }
}

// ---------------------------------------------------------------------------
extern "C" void kernel_launch(void* const* d_in, const int* in_sizes, int n_in,
                              void* d_out, int out_size) {
    (void)in_sizes; (void)n_in; (void)out_size;
    const float* hidden = (const float*)d_in[0];
    const float* Wq = (const float*)d_in[1];
    const float* Wk = (const float*)d_in[2];
    const float* Wv = (const float*)d_in[3];
    const float* Wo = (const float*)d_in[4];
    float* out = (float*)d_out;

    const int gsm = 3 * 16384 * 2;            // 98304 B (3 stages x 32KB)
    const int asm_ = 2 * 2 * 64 * KSTR * 2;   // 36864 B
    cudaFuncSetAttribute(bfgemmQKV_k, cudaFuncAttributeMaxDynamicSharedMemorySize, gsm);
    cudaFuncSetAttribute(bfgemmO_k, cudaFuncAttributeMaxDynamicSharedMemorySize, gsm);
    cudaFuncSetAttribute(attn3_k, cudaFuncAttributeMaxDynamicSharedMemorySize, asm_);

    // 0: fused prep (convA + all weight transposes)
    prep0_k<<<12288, 256>>>(hidden, Wq, Wk, Wv, Wo);
    // 1: fused QKV projection (1-term fp16)
    bfgemmQKV_k<<<dim3(12, 64), 256, gsm>>>();
    // 2: rope (Q/K hi) + V transpose
    prep2_k<<<22528, 256>>>();
    // 3: attention (QK 1-term, PV 2-term)  <- capture slot
    attn3_k<<<dim3(8, 256), 128, asm_>>>();
    // 4: output projection (1-term)
    bfgemmO_k<<<dim3(8, 64), 256, gsm>>>(out);
}

// round 17
// speedup vs baseline: 10.2572x; 1.0728x over previous
#include <cuda_runtime.h>
#include <cuda_fp16.h>
#include <cstdint>
#include <math.h>

#define NTOK 8192

// fp32 intermediates
__device__ float g_q[NTOK * 1024];
__device__ float g_k[NTOK * 256];
__device__ float g_v[NTOK * 256];
// fp16 operands
__device__ __half g_ah[NTOK * 1024];    // hidden (pre-QKV), then attention output (pre-Wo)
__device__ __half g_qh[NTOK * 1024];
__device__ __half g_kh[NTOK * 256];
__device__ __half g_vth[NTOK * 256];
__device__ __half g_wth[2560 * 1024];   // QKV rows 0-1535, Wo rows 1536-2559

__device__ __forceinline__ int remap_bpt(int r) {
    int b = r >> 12, p = (r >> 9) & 7, t = r & 511;
    return (b << 12) + (t << 3) + p;
}
__device__ __forceinline__ uint32_t smem_u32(const void* p) {
    uint32_t a;
    asm("{ .reg .u64 t; cvta.to.shared.u64 t, %1; cvt.u32.u64 %0, t; }" : "=r"(a) : "l"(p));
    return a;
}
#define LDSM4(r0, r1, r2, r3, a) \
    asm volatile("ldmatrix.sync.aligned.m8n8.x4.shared.b16 {%0,%1,%2,%3}, [%4];" \
        : "=r"(r0), "=r"(r1), "=r"(r2), "=r"(r3) : "r"(a))
#define MMA16816(c, a0, a1, a2, a3, b0, b1) \
    asm volatile("mma.sync.aligned.m16n8k16.row.col.f32.f16.f16.f32 " \
        "{%0,%1,%2,%3},{%4,%5,%6,%7},{%8,%9},{%0,%1,%2,%3};" \
        : "+f"((c)[0]), "+f"((c)[1]), "+f"((c)[2]), "+f"((c)[3]) \
        : "r"(a0), "r"(a1), "r"(a2), "r"(a3), "r"(b0), "r"(b1))
#define CP16(dst, src) \
    asm volatile("cp.async.cg.shared.global [%0], [%1], 16;" :: "r"(dst), "l"(src))
#define CP_COMMIT() asm volatile("cp.async.commit_group;" ::: "memory")
#define CP_WAIT1()  asm volatile("cp.async.wait_group 1;" ::: "memory")
#define CP_WAIT0()  asm volatile("cp.async.wait_group 0;" ::: "memory")

__device__ __forceinline__ uint32_t pk_h2(float x, float y) {
    __half2 h = __floats2half2_rn(x, y);
    return *(uint32_t*)&h;
}

// ---------------------------------------------------------------------------
// prep0 (fused): convA [0..8191] + Wqkv transpose [8192..11263] + Wo [11264..12287]
// ---------------------------------------------------------------------------
__device__ __forceinline__ void transhi_body(const float* __restrict__ in, int N,
                                             int rowoff, int bx, int by, int tid) {
    __shared__ float t[32][33];
    int n0 = bx * 32;
    if (n0 >= N) return;
    int k0 = by * 32, x = tid & 31, y = tid >> 5;
    for (int j = y; j < 32; j += 8)
        t[j][x] = in[(size_t)(k0 + j) * N + n0 + x];
    __syncthreads();
    for (int j = y; j < 32; j += 8)
        g_wth[(size_t)(rowoff + n0 + j) * 1024 + k0 + x] = __float2half_rn(t[x][j]);
}

__global__ void __launch_bounds__(256) prep0_k(const float* __restrict__ hidden,
                                               const float* __restrict__ Wq,
                                               const float* __restrict__ Wk,
                                               const float* __restrict__ Wv,
                                               const float* __restrict__ Wo) {
    int b = blockIdx.x, tid = threadIdx.x;
    if (b < 8192) {
        int idx = b * 256 + tid;
        int row = idx >> 8, c4 = (idx & 255) * 4;
        int srow = remap_bpt(row);
        float4 v = *(const float4*)(hidden + (size_t)srow * 1024 + c4);
        *(uint2*)&g_ah[(size_t)row * 1024 + c4] =
            make_uint2(pk_h2(v.x, v.y), pk_h2(v.z, v.w));
        return;
    }
    if (b < 11264) {
        int idx = b - 8192;
        int z = idx >> 10, r = idx & 1023;
        const float* in = (z == 0) ? Wq : (z == 1) ? Wk : Wv;
        int N = (z == 0) ? 1024 : 256;
        int rowoff = (z == 0) ? 0 : (z == 1) ? 1024 : 1280;
        transhi_body(in, N, rowoff, r & 31, r >> 5, tid);
        return;
    }
    int r = b - 11264;
    transhi_body(Wo, 1024, 1536, r & 31, r >> 5, tid);
}

// ---------------------------------------------------------------------------
// prep2: rope -> fp16 + V transpose
// ---------------------------------------------------------------------------
__global__ void __launch_bounds__(256) prep2_k() {
    __shared__ float t[32][33];
    int b = blockIdx.x, tid = threadIdx.x;
    if (b < 20480) {
        int idx = b * 256 + tid;
        const int QP = NTOK * 16 * 32;
        int i, tok;
        if (idx < QP) {
            i = idx & 31;
            int r = idx >> 5;
            tok = r >> 4;
            size_t off = (size_t)tok * 1024 + (r & 15) * 64;
            const float* base = g_q + off;
            int tt = tok & 511;
            float invf = expf(-(float)i * 0.28782313662425574f);
            float ang = (float)tt * invf, s, c;
            sincosf(ang, &s, &c);
            const float scale = 0.125f * 1.4426950408889634f;
            float x1 = base[i], x2 = base[i + 32];
            g_qh[off + i]      = __float2half_rn((x1 * c - x2 * s) * scale);
            g_qh[off + i + 32] = __float2half_rn((x1 * s + x2 * c) * scale);
        } else {
            int j = idx - QP;
            i = j & 31;
            int r = j >> 5;
            tok = r >> 2;
            size_t off = (size_t)tok * 256 + (r & 3) * 64;
            const float* base = g_k + off;
            int tt = tok & 511;
            float invf = expf(-(float)i * 0.28782313662425574f);
            float ang = (float)tt * invf, s, c;
            sincosf(ang, &s, &c);
            float x1 = base[i], x2 = base[i + 32];
            g_kh[off + i]      = __float2half_rn(x1 * c - x2 * s);
            g_kh[off + i + 32] = __float2half_rn(x1 * s + x2 * c);
        }
        return;
    }
    int idx = b - 20480;
    int bx = idx & 15, by = (idx >> 4) & 1, g = idx >> 5;
    int bp = g >> 2, hkv = g & 3;
    int k0 = bx * 32, d0 = by * 32, x = tid & 31, y = tid >> 5;
    for (int j = y; j < 32; j += 8)
        t[j][x] = g_v[(size_t)(bp * 512 + k0 + j) * 256 + hkv * 64 + d0 + x];
    __syncthreads();
    for (int j = y; j < 32; j += 8) {
        size_t o = (size_t)g * 32768 + (size_t)(d0 + j) * 512 + k0 + x;
        g_vth[o] = __float2half_rn(t[x][j]);
    }
}

// ---------------------------------------------------------------------------
// GEMM core: 1-term pure fp16, BK=64, 3-stage cp.async (stage = 32KB).
// ---------------------------------------------------------------------------
struct GemmCore {
    uint32_t smbase;
    int tid, wid, lane, wm, wn;
    float acc[4][4][4];

    __device__ __forceinline__ void init(const __half* sm, int t) {
        smbase = smem_u32(sm);
        tid = t; wid = t >> 5; lane = t & 31;
        wm = (wid >> 2) * 64; wn = (wid & 3) * 32;
        #pragma unroll
        for (int i = 0; i < 4; i++)
            #pragma unroll
            for (int j = 0; j < 4; j++)
                #pragma unroll
                for (int q = 0; q < 4; q++) acc[i][j][q] = 0.f;
    }
    __device__ __forceinline__ static uint32_t swz(int row, int chunk) {
        return (uint32_t)(row * 64 + ((chunk ^ (row & 7)) << 3));
    }
    __device__ __forceinline__ void issue(const __half* A, const __half* B,
                                          int am0, int bn0, int k0, int s) {
        uint32_t stg = smbase + (uint32_t)s * 16384 * 2;
        #pragma unroll
        for (int i = 0; i < 8; i++) {
            int arr = i >> 2;
            int cc = (i & 3) * 256 + tid;
            int r = cc >> 3, ch = cc & 7;
            uint32_t dst = stg + (arr * 8192 + swz(r, ch)) * 2;
            const __half* src = arr == 0
                ? A + (size_t)(am0 + r) * 1024 + k0 + ch * 8
                : B + (size_t)(bn0 + r) * 1024 + k0 + ch * 8;
            CP16(dst, src);
        }
    }
    __device__ __forceinline__ void compute(int s) {
        uint32_t stg = smbase + (uint32_t)s * 16384 * 2;
        #pragma unroll
        for (int ks = 0; ks < 4; ks++) {
            int koff = ks * 16 + ((lane >> 4) << 3);
            int chunk = koff >> 3;
            int arow = wm + (lane & 15);
            uint32_t ah[4][4];
            #pragma unroll
            for (int mf = 0; mf < 4; mf++) {
                uint32_t off = swz(arow + mf * 16, chunk) * 2;
                LDSM4(ah[mf][0], ah[mf][1], ah[mf][2], ah[mf][3], stg + off);
            }
            uint32_t bh[4][2];
            #pragma unroll
            for (int jp = 0; jp < 4; jp += 2) {
                int brow = wn + jp * 8 + (lane & 15);
                uint32_t off = swz(brow, chunk) * 2;
                uint32_t r0, r1, r2, r3;
                LDSM4(r0, r1, r2, r3, stg + 8192 * 2 + off);
                bh[jp][0] = r0; bh[jp + 1][0] = r1; bh[jp][1] = r2; bh[jp + 1][1] = r3;
            }
            #pragma unroll
            for (int mf = 0; mf < 4; mf++)
                #pragma unroll
                for (int nf = 0; nf < 4; nf++)
                    MMA16816(acc[mf][nf], ah[mf][0], ah[mf][1], ah[mf][2], ah[mf][3], bh[nf][0], bh[nf][1]);
        }
    }
    __device__ __forceinline__ void run(const __half* A, const __half* B, int am0, int bn0) {
        issue(A, B, am0, bn0, 0, 0);  CP_COMMIT();
        issue(A, B, am0, bn0, 64, 1); CP_COMMIT();
        for (int it = 0; it < 16; it++) {
            if (it < 15) { CP_WAIT1(); } else { CP_WAIT0(); }
            __syncthreads();
            if (it + 2 < 16) { issue(A, B, am0, bn0, (it + 2) * 64, (it + 2) % 3); CP_COMMIT(); }
            compute(it % 3);
        }
    }
};

__global__ void __launch_bounds__(256) bfgemmQKV_k() {
    extern __shared__ __half SM[];
    GemmCore g;
    g.init(SM, threadIdx.x);
    int bm = blockIdx.y, bn = blockIdx.x;
    g.run(g_ah, g_wth, bm * 128, bn * 128);

    float* C; int Ntot, colb;
    if (bn < 8)       { C = g_q; Ntot = 1024; colb = bn * 128; }
    else if (bn < 10) { C = g_k; Ntot = 256;  colb = (bn - 8) * 128; }
    else              { C = g_v; Ntot = 256;  colb = (bn - 10) * 128; }
    #pragma unroll
    for (int mf = 0; mf < 4; mf++) {
        int r0 = bm * 128 + g.wm + mf * 16 + (g.lane >> 2);
        int r1 = r0 + 8;
        #pragma unroll
        for (int nf = 0; nf < 4; nf++) {
            int col = colb + g.wn + nf * 8 + (g.lane & 3) * 2;
            *(float2*)(C + (size_t)r0 * Ntot + col) = make_float2(g.acc[mf][nf][0], g.acc[mf][nf][1]);
            *(float2*)(C + (size_t)r1 * Ntot + col) = make_float2(g.acc[mf][nf][2], g.acc[mf][nf][3]);
        }
    }
}

__global__ void __launch_bounds__(256) bfgemmO_k(float* __restrict__ C) {
    extern __shared__ __half SM[];
    GemmCore g;
    g.init(SM, threadIdx.x);
    int bm = blockIdx.y, bn = blockIdx.x;
    g.run(g_ah, g_wth + (size_t)1536 * 1024, bm * 128, bn * 128);
    #pragma unroll
    for (int mf = 0; mf < 4; mf++) {
        int r0 = remap_bpt(bm * 128 + g.wm + mf * 16 + (g.lane >> 2));
        int r1 = remap_bpt(bm * 128 + g.wm + mf * 16 + (g.lane >> 2) + 8);
        #pragma unroll
        for (int nf = 0; nf < 4; nf++) {
            int col = bn * 128 + g.wn + nf * 8 + (g.lane & 3) * 2;
            *(float2*)(C + (size_t)r0 * 1024 + col) = make_float2(g.acc[mf][nf][0], g.acc[mf][nf][1]);
            *(float2*)(C + (size_t)r1 * 1024 + col) = make_float2(g.acc[mf][nf][2], g.acc[mf][nf][3]);
        }
    }
}

// ---------------------------------------------------------------------------
// Flash attention: QK 1-term fp16, PV 1-term (P rounded to fp16, lo dropped).
// ---------------------------------------------------------------------------
#define KSTR 72
__global__ void __launch_bounds__(128, 3) attn3_k() {
    extern __shared__ __half ASM[];
    const int STG = 2 * 64 * KSTR;

    int tid = threadIdx.x, wid = tid >> 5, lane = tid & 31;
    int bph = blockIdx.y, h = bph & 15, bp = bph >> 4, hkv = h >> 2;
    int qt0 = blockIdx.x << 6;
    int qrow0 = bp * 512 + qt0;
    size_t vbase = (size_t)(bp * 4 + hkv) * 32768;

    {
        #pragma unroll
        for (int i = 0; i < 4; i++) {
            int cc = i * 128 + tid;
            int r = cc >> 3, kc = (cc & 7) * 8;
            uint32_t dst = smem_u32(ASM + r * KSTR + kc);
            CP16(dst, g_qh + (size_t)(qrow0 + r) * 1024 + h * 64 + kc);
        }
        CP_COMMIT(); CP_WAIT0();
        __syncthreads();
    }
    uint32_t qh[4][4];
    {
        int row = wid * 16 + (lane & 15);
        #pragma unroll
        for (int ks = 0; ks < 4; ks++) {
            int koff = ks * 16 + ((lane >> 4) << 3);
            LDSM4(qh[ks][0], qh[ks][1], qh[ks][2], qh[ks][3], smem_u32(&ASM[row * KSTR + koff]));
        }
    }
    __syncthreads();

    auto issue = [&](int it, int s) {
        __half* stg = ASM + s * STG;
        int kt = it * 64;
        #pragma unroll
        for (int i = 0; i < 8; i++) {
            int arr = i >> 2;
            int cc = (i & 3) * 128 + tid;
            int r = cc >> 3, kc = (cc & 7) * 8;
            uint32_t dst = smem_u32(stg + arr * 64 * KSTR + r * KSTR + kc);
            const __half* src;
            if (arr == 0) src = g_kh + (size_t)(bp * 512 + kt + r) * 256 + hkv * 64 + kc;
            else          src = g_vth + vbase + (size_t)r * 512 + kt + kc;
            CP16(dst, src);
        }
    };

    float o[8][4];
    #pragma unroll
    for (int nf = 0; nf < 8; nf++)
        #pragma unroll
        for (int c = 0; c < 4; c++) o[nf][c] = 0.f;
    float m0 = -INFINITY, m1 = -INFINITY, l0 = 0.f, l1 = 0.f;

    issue(0, 0);
    CP_COMMIT();

    for (int it = 0; it < 8; it++) {
        CP_WAIT0();
        __syncthreads();
        if (it + 1 < 8) { issue(it + 1, (it + 1) & 1); CP_COMMIT(); }

        __half* stg = ASM + (it & 1) * STG;
        __half* Khi = stg;
        __half* Vth = stg + 64 * KSTR;

        float s[8][4];
        #pragma unroll
        for (int nf = 0; nf < 8; nf++)
            #pragma unroll
            for (int c = 0; c < 4; c++) s[nf][c] = 0.f;

        #pragma unroll
        for (int ks = 0; ks < 4; ks++) {
            int koff = ks * 16 + ((lane >> 4) << 3);
            #pragma unroll
            for (int jp = 0; jp < 8; jp += 2) {
                int brow = jp * 8 + (lane & 15);
                uint32_t r0, r1, r2, r3;
                LDSM4(r0, r1, r2, r3, smem_u32(&Khi[brow * KSTR + koff]));
                MMA16816(s[jp],     qh[ks][0], qh[ks][1], qh[ks][2], qh[ks][3], r0, r2);
                MMA16816(s[jp + 1], qh[ks][0], qh[ks][1], qh[ks][2], qh[ks][3], r1, r3);
            }
        }

        float rmax0 = -INFINITY, rmax1 = -INFINITY;
        #pragma unroll
        for (int nf = 0; nf < 8; nf++) {
            rmax0 = fmaxf(rmax0, fmaxf(s[nf][0], s[nf][1]));
            rmax1 = fmaxf(rmax1, fmaxf(s[nf][2], s[nf][3]));
        }
        rmax0 = fmaxf(rmax0, __shfl_xor_sync(0xffffffffu, rmax0, 1));
        rmax0 = fmaxf(rmax0, __shfl_xor_sync(0xffffffffu, rmax0, 2));
        rmax1 = fmaxf(rmax1, __shfl_xor_sync(0xffffffffu, rmax1, 1));
        rmax1 = fmaxf(rmax1, __shfl_xor_sync(0xffffffffu, rmax1, 2));
        float mn0 = fmaxf(m0, rmax0), mn1 = fmaxf(m1, rmax1);
        float al0 = exp2f(m0 - mn0), al1 = exp2f(m1 - mn1);
        float ps0 = 0.f, ps1 = 0.f;
        #pragma unroll
        for (int nf = 0; nf < 8; nf++) {
            s[nf][0] = exp2f(s[nf][0] - mn0); ps0 += s[nf][0];
            s[nf][1] = exp2f(s[nf][1] - mn0); ps0 += s[nf][1];
            s[nf][2] = exp2f(s[nf][2] - mn1); ps1 += s[nf][2];
            s[nf][3] = exp2f(s[nf][3] - mn1); ps1 += s[nf][3];
        }
        l0 = l0 * al0 + ps0; l1 = l1 * al1 + ps1;
        m0 = mn0; m1 = mn1;
        #pragma unroll
        for (int nf = 0; nf < 8; nf++) {
            o[nf][0] *= al0; o[nf][1] *= al0;
            o[nf][2] *= al1; o[nf][3] *= al1;
        }

        // PV: P rounded to fp16 (1-term)
        #pragma unroll
        for (int ks = 0; ks < 4; ks++) {
            float* pa = s[2 * ks];
            float* pb = s[2 * ks + 1];
            uint32_t p0 = pk_h2(pa[0], pa[1]), p1 = pk_h2(pa[2], pa[3]);
            uint32_t p2 = pk_h2(pb[0], pb[1]), p3 = pk_h2(pb[2], pb[3]);

            int koff = ks * 16 + ((lane >> 4) << 3);
            #pragma unroll
            for (int jp = 0; jp < 8; jp += 2) {
                int brow = jp * 8 + (lane & 15);
                uint32_t r0, r1, r2, r3;
                LDSM4(r0, r1, r2, r3, smem_u32(&Vth[brow * KSTR + koff]));
                MMA16816(o[jp],     p0, p1, p2, p3, r0, r2);
                MMA16816(o[jp + 1], p0, p1, p2, p3, r1, r3);
            }
        }
        __syncthreads();
    }

    l0 += __shfl_xor_sync(0xffffffffu, l0, 1);
    l0 += __shfl_xor_sync(0xffffffffu, l0, 2);
    l1 += __shfl_xor_sync(0xffffffffu, l1, 1);
    l1 += __shfl_xor_sync(0xffffffffu, l1, 2);
    float inv0 = 1.f / l0, inv1 = 1.f / l1;

    int row0 = qrow0 + wid * 16 + (lane >> 2);
    size_t b0 = (size_t)row0 * 1024 + h * 64 + (lane & 3) * 2;
    size_t b1 = b0 + 8 * 1024;
    #pragma unroll
    for (int nf = 0; nf < 8; nf++) {
        *(uint32_t*)&g_ah[b0 + nf * 8] = pk_h2(o[nf][0] * inv0, o[nf][1] * inv0);
        *(uint32_t*)&g_ah[b1 + nf * 8] = pk_h2(o[nf][2] * inv1, o[nf][3] * inv1);
    }
}

// ---------------------------------------------------------------------------
extern "C" void kernel_launch(void* const* d_in, const int* in_sizes, int n_in,
                              void* d_out, int out_size) {
    (void)in_sizes; (void)n_in; (void)out_size;
    const float* hidden = (const float*)d_in[0];
    const float* Wq = (const float*)d_in[1];
    const float* Wk = (const float*)d_in[2];
    const float* Wv = (const float*)d_in[3];
    const float* Wo = (const float*)d_in[4];
    float* out = (float*)d_out;

    const int gsm = 3 * 16384 * 2;            // 98304 B
    const int asm_ = 2 * 2 * 64 * KSTR * 2;   // 36864 B
    cudaFuncSetAttribute(bfgemmQKV_k, cudaFuncAttributeMaxDynamicSharedMemorySize, gsm);
    cudaFuncSetAttribute(bfgemmO_k, cudaFuncAttributeMaxDynamicSharedMemorySize, gsm);
    cudaFuncSetAttribute(attn3_k, cudaFuncAttributeMaxDynamicSharedMemorySize, asm_);

    // 0: fused prep (convA + all weight transposes)
    prep0_k<<<12288, 256>>>(hidden, Wq, Wk, Wv, Wo);
    // 1: fused QKV projection (1-term fp16)
    bfgemmQKV_k<<<dim3(12, 64), 256, gsm>>>();
    // 2: rope (Q/K hi) + V transpose
    prep2_k<<<22528, 256>>>();
    // 3: attention (QK 1-term, PV 1-term)  <- capture slot
    attn3_k<<<dim3(8, 256), 128, asm_>>>();
    // 4: output projection (1-term)
    bfgemmO_k<<<dim3(8, 64), 256, gsm>>>(out);
}